// round 7
// baseline (speedup 1.0000x reference)
#include <cuda_runtime.h>
#include <cuda_bf16.h>
#include <math.h>
#include <cstdint>

// ---------------- Problem constants ----------------
#define B_ 4
#define N_ 1025
#define C_ 768
#define H_ 12
#define D_ 64
#define TOPT 103
#define SCALEF 0.125f            // 64^-0.5

#define M_TOT (B_ * N_)          // 4100

// Output layout (float32, reference tuple flattened & concatenated):
#define OFF_OUT        0L
#define OFF_ENH_INDEX  3148800L
#define OFF_ENH_IDX    3465216L
#define OFF_FUSE_INDEX 3465628L
#define OFF_FUSE_IDX   3782044L
#define OFF_CLS        3782456L

// ---------------- Scratch (no allocation allowed) ----------------
__device__ float  g_q[B_*H_*N_*D_];     // [b,h,n,d]
__device__ float  g_k[B_*H_*N_*D_];
__device__ float  g_v[B_*H_*N_*D_];
__device__ float  g_ctx[B_*N_*C_];      // [b,n,h*64+d]
__device__ double g_clsd[B_*(N_-1)];
__device__ double g_cls_ph[B_*H_][N_-1];

// bf16 3-way splits
__device__ __nv_bfloat16 g_xs[3][M_TOT*C_];
__device__ __nv_bfloat16 g_ws[3][3*C_*C_];     // w_qkv [2304,768]
__device__ __nv_bfloat16 g_wo[3][C_*C_];       // w_out [768,768]
__device__ __nv_bfloat16 g_cs[3][M_TOT*C_];    // ctx splits

// ======================================================================
// Split kernel: fp32 -> 3 bf16 splits (error-free to ~2^-27)
// ======================================================================
__global__ void split3(const float* __restrict__ src,
                       __nv_bfloat16* __restrict__ d0,
                       __nv_bfloat16* __restrict__ d1,
                       __nv_bfloat16* __restrict__ d2, int n) {
    int i = blockIdx.x * blockDim.x + threadIdx.x;
    if (i < n) {
        float x = src[i];
        __nv_bfloat16 b0 = __float2bfloat16(x);
        float r = x - __bfloat162float(b0);
        __nv_bfloat16 b1 = __float2bfloat16(r);
        float r2 = r - __bfloat162float(b1);
        d0[i] = b0; d1[i] = b1; d2[i] = __float2bfloat16(r2);
    }
}

// ======================================================================
// mma.sync bf16 GEMM with 3-split/6-product fp32 emulation.
// D[m,n] = sum_k A[m,k]*B[n,k], K=768.  CTA tile 128x128, 8 warps,
// warp tile 64x32, K-block 32. mode 0: scatter g_q/g_k/g_v; mode 1: out+bias.
// ======================================================================
#define KB      32
#define LDA_P   40                      // padded row length in bf16 (80 B)
#define TILE_B  (128 * LDA_P * 2)       // 10240 B per tile
#define MMA_SMEM (6 * TILE_B)           // 61440 B

__device__ __forceinline__ void mma16816(float c[4], uint32_t a0, uint32_t a1,
                                         uint32_t a2, uint32_t a3,
                                         uint32_t b0, uint32_t b1) {
    asm volatile(
        "mma.sync.aligned.m16n8k16.row.col.f32.bf16.bf16.f32 "
        "{%0,%1,%2,%3}, {%4,%5,%6,%7}, {%8,%9}, {%0,%1,%2,%3};"
        : "+f"(c[0]), "+f"(c[1]), "+f"(c[2]), "+f"(c[3])
        : "r"(a0), "r"(a1), "r"(a2), "r"(a3), "r"(b0), "r"(b1));
}

__global__ void __launch_bounds__(256, 2)
mma_gemm(const __nv_bfloat16* __restrict__ A0, const __nv_bfloat16* __restrict__ A1,
         const __nv_bfloat16* __restrict__ A2,
         const __nv_bfloat16* __restrict__ B0, const __nv_bfloat16* __restrict__ B1,
         const __nv_bfloat16* __restrict__ B2,
         int mode, const float* __restrict__ bias, float* __restrict__ out) {
    extern __shared__ __align__(16) char smem[];
    const int tid = threadIdx.x;
    const int wid = tid >> 5, lane = tid & 31;
    const int gid = lane >> 2, tig = lane & 3;
    const int wr = wid >> 2, wc = wid & 3;        // warp grid 2 x 4
    const int m0 = blockIdx.y * 128;
    const int n0 = blockIdx.x * 128;

    const __nv_bfloat16* Asrc[3] = {A0, A1, A2};
    const __nv_bfloat16* Bsrc[3] = {B0, B1, B2};

    float acc[4][4][4];                           // [mtile][ntile][reg]
    #pragma unroll
    for (int i = 0; i < 4; i++)
        #pragma unroll
        for (int j = 0; j < 4; j++)
            #pragma unroll
            for (int r = 0; r < 4; r++) acc[i][j][r] = 0.f;

    // product schedule: b0b0, b0b1, b1b0, b0b2, b1b1, b2b0
    const int pa[6] = {0, 0, 1, 0, 1, 2};
    const int pb[6] = {0, 1, 0, 2, 1, 0};

    for (int kb = 0; kb < 24; kb++) {
        const int kcol = kb * KB;
        __syncthreads();
        // load 6 tiles (128 x 32 bf16 each) into padded SMEM
        #pragma unroll
        for (int s = 0; s < 3; s++) {
            const __nv_bfloat16* Ag = Asrc[s];
            const __nv_bfloat16* Bg = Bsrc[s];
            #pragma unroll
            for (int q = 0; q < 2; q++) {
                int idx = tid * 2 + q;                // 0..511
                int r = idx >> 2, c4 = idx & 3;
                int gm = m0 + r;
                uint4 va = (gm < M_TOT)
                    ? *(const uint4*)(Ag + (long)gm * C_ + kcol + c4 * 8)
                    : make_uint4(0, 0, 0, 0);
                *(uint4*)(smem + s * TILE_B + r * (LDA_P*2) + c4 * 16) = va;
                uint4 vb = *(const uint4*)(Bg + (long)(n0 + r) * C_ + kcol + c4 * 8);
                *(uint4*)(smem + (3 + s) * TILE_B + r * (LDA_P*2) + c4 * 16) = vb;
            }
        }
        __syncthreads();

        #pragma unroll
        for (int p = 0; p < 6; p++) {
            const char* Asm = smem + pa[p] * TILE_B;
            const char* Bsm = smem + (3 + pb[p]) * TILE_B;
            #pragma unroll
            for (int ks = 0; ks < 2; ks++) {
                const int kO = (ks * 16 + tig * 2) * 2;   // byte offset in row
                uint32_t af[4][4], bf[4][2];
                #pragma unroll
                for (int i = 0; i < 4; i++) {
                    int row = wr * 64 + i * 16 + gid;
                    const char* pr = Asm + row * (LDA_P*2) + kO;
                    af[i][0] = *(const uint32_t*)pr;
                    af[i][1] = *(const uint32_t*)(pr + 8 * (LDA_P*2));
                    af[i][2] = *(const uint32_t*)(pr + 16);
                    af[i][3] = *(const uint32_t*)(pr + 8 * (LDA_P*2) + 16);
                }
                #pragma unroll
                for (int j = 0; j < 4; j++) {
                    int nrow = wc * 32 + j * 8 + gid;
                    const char* pbp = Bsm + nrow * (LDA_P*2) + kO;
                    bf[j][0] = *(const uint32_t*)pbp;
                    bf[j][1] = *(const uint32_t*)(pbp + 16);
                }
                #pragma unroll
                for (int i = 0; i < 4; i++)
                    #pragma unroll
                    for (int j = 0; j < 4; j++)
                        mma16816(acc[i][j], af[i][0], af[i][1], af[i][2], af[i][3],
                                 bf[j][0], bf[j][1]);
            }
        }
    }

    // ---------------- epilogue ----------------
    #pragma unroll
    for (int i = 0; i < 4; i++) {
        #pragma unroll
        for (int half = 0; half < 2; half++) {
            int gm = m0 + wr * 64 + i * 16 + gid + half * 8;
            if (gm >= M_TOT) continue;
            int btok = gm / N_, nt = gm % N_;
            #pragma unroll
            for (int j = 0; j < 4; j++) {
                float v0 = acc[i][j][half * 2];
                float v1 = acc[i][j][half * 2 + 1];
                int jg = n0 + wc * 32 + j * 8 + tig * 2;
                if (mode == 0) {
                    int qkv_i = jg / C_;
                    int rem = jg % C_;
                    int h = rem >> 6, d0 = rem & 63;
                    float* dst = (qkv_i == 0) ? g_q : (qkv_i == 1 ? g_k : g_v);
                    long base = ((long)(btok * H_ + h) * N_ + nt) * 64 + d0;
                    *(float2*)&dst[base] = make_float2(v0, v1);
                } else {
                    long base = OFF_OUT + (long)gm * C_ + jg;
                    *(float2*)&out[base] = make_float2(v0 + bias[jg], v1 + bias[jg + 1]);
                }
            }
        }
    }
}

// ======================================================================
// Flash attention with CSA mask + masked-tile skipping (SIMT).
// ======================================================================
__global__ void attn_kernel() {
    extern __shared__ float sm[];
    float* Qs = sm;
    float* Ks = sm + 64*65;
    float* Vs = sm + 2*64*65;
    float* Ps = sm + 3*64*65;

    const int tid = threadIdx.x;
    const int ty = tid >> 4, tx = tid & 15;
    const int bh = blockIdx.y;
    const int q0g = blockIdx.x * 64;
    const float* Qg = g_q + (long)bh * N_ * 64;
    const float* Kg = g_k + (long)bh * N_ * 64;
    const float* Vg = g_v + (long)bh * N_ * 64;

    for (int idx = tid; idx < 64*64; idx += 256) {
        int r = idx >> 6, d = idx & 63;
        int qi = q0g + r;
        Qs[r*65 + d] = (qi < N_) ? Qg[(long)qi*64 + d] : 0.f;
    }

    bool q_uni = false; int qblk = -2;
    if (q0g >= 64) {
        int qhi = min(q0g + 63, N_ - 1);
        int blo = (q0g - 1) >> 8, bhi = (qhi - 1) >> 8;
        if (blo == bhi) { q_uni = true; qblk = blo; }
    }

    float acc[4][4] = {};
    float m_i[4], l_i[4];
    #pragma unroll
    for (int i = 0; i < 4; i++) { m_i[i] = -INFINITY; l_i[i] = 0.f; }

    const int r0 = ty*4, c0 = tx*4;

    for (int kt = 0; kt < 17; kt++) {
        const int k0g = kt * 64;
        if (q_uni && k0g >= 64) {
            int khi = min(k0g + 63, N_ - 1);
            int kbl = (k0g - 1) >> 8, kbh = (khi - 1) >> 8;
            if (kbl == kbh && kbl == qblk) continue;
        }
        __syncthreads();
        for (int idx = tid; idx < 64*64; idx += 256) {
            int r = idx >> 6, d = idx & 63;
            int kj = k0g + r;
            Ks[r*65 + d] = (kj < N_) ? Kg[(long)kj*64 + d] : 0.f;
            Vs[r*65 + d] = (kj < N_) ? Vg[(long)kj*64 + d] : 0.f;
        }
        __syncthreads();

        float sv[4][4] = {};
        #pragma unroll 8
        for (int kk = 0; kk < 64; kk++) {
            float a[4], b2[4];
            #pragma unroll
            for (int i = 0; i < 4; i++) a[i]  = Qs[(r0+i)*65 + kk];
            #pragma unroll
            for (int j = 0; j < 4; j++) b2[j] = Ks[(c0+j)*65 + kk];
            #pragma unroll
            for (int i = 0; i < 4; i++)
                #pragma unroll
                for (int j = 0; j < 4; j++)
                    sv[i][j] = fmaf(a[i], b2[j], sv[i][j]);
        }

        #pragma unroll
        for (int i = 0; i < 4; i++) {
            int qi = q0g + r0 + i;
            int qb = (qi >= 1) ? ((qi - 1) >> 8) : -1;
            #pragma unroll
            for (int j = 0; j < 4; j++) {
                int kj = k0g + c0 + j;
                float s = sv[i][j] * SCALEF;
                bool bad = (kj >= N_) ||
                           (qb >= 0 && kj >= 1 && (((kj - 1) >> 8) == qb));
                sv[i][j] = bad ? -INFINITY : s;
            }
        }

        #pragma unroll
        for (int i = 0; i < 4; i++) {
            float t = fmaxf(fmaxf(sv[i][0], sv[i][1]), fmaxf(sv[i][2], sv[i][3]));
            #pragma unroll
            for (int o = 8; o >= 1; o >>= 1)
                t = fmaxf(t, __shfl_xor_sync(0xffffffffu, t, o));
            float mnew = fmaxf(m_i[i], t);
            float corr = __expf(m_i[i] - mnew);
            m_i[i] = mnew;

            float p[4], rs = 0.f;
            #pragma unroll
            for (int j = 0; j < 4; j++) {
                p[j] = __expf(sv[i][j] - mnew);
                rs += p[j];
                Ps[(r0+i)*65 + c0 + j] = p[j];
            }
            #pragma unroll
            for (int o = 8; o >= 1; o >>= 1)
                rs += __shfl_xor_sync(0xffffffffu, rs, o);
            l_i[i] = l_i[i] * corr + rs;
            #pragma unroll
            for (int j = 0; j < 4; j++) acc[i][j] *= corr;
        }
        __syncthreads();

        #pragma unroll 8
        for (int jj = 0; jj < 64; jj++) {
            float p[4], v2[4];
            #pragma unroll
            for (int i = 0; i < 4; i++) p[i]  = Ps[(r0+i)*65 + jj];
            #pragma unroll
            for (int j = 0; j < 4; j++) v2[j] = Vs[jj*65 + c0 + j];
            #pragma unroll
            for (int i = 0; i < 4; i++)
                #pragma unroll
                for (int j = 0; j < 4; j++)
                    acc[i][j] = fmaf(p[i], v2[j], acc[i][j]);
        }
    }

    const int b = bh / H_, h = bh % H_;
    #pragma unroll
    for (int i = 0; i < 4; i++) {
        int qi = q0g + r0 + i;
        if (qi < N_) {
            float inv = 1.f / l_i[i];
            long base = ((long)b * N_ + qi) * C_ + h * 64 + c0;
            #pragma unroll
            for (int j = 0; j < 4; j++)
                g_ctx[base + j] = acc[i][j] * inv;
        }
    }
}

// ======================================================================
// cls per-head softmax row -- FULL fp64 from raw inputs (GEMM-independent):
//   q0 = W_q,h x_{b,0};  u = W_k,h^T q0;  s_j = 0.125 * u . x_{b,j}
// One CTA per (b,h), 1024 threads.
// ======================================================================
__global__ void __launch_bounds__(1024)
cls_head_kernel(const float* __restrict__ x, const float* __restrict__ w) {
    __shared__ double q0s[64];
    __shared__ double u[C_];
    __shared__ double s[N_];
    __shared__ double red[32];
    const int bh = blockIdx.x;
    const int b = bh / H_, h = bh % H_;
    const int tid = threadIdx.x;
    const int wid = tid >> 5, lane = tid & 31;

    const float* xb = x + (long)b * N_ * C_;           // x[b,0,:] at offset 0
    const float* wq = w + (long)(h * 64) * C_;         // W_q head h [64][768]
    const float* wk = w + (long)(C_ + h * 64) * C_;    // W_k head h [64][768]

    // phase 1: q0[d] (warp per d, 2 rounds)
    for (int d = wid; d < 64; d += 32) {
        double a = 0.0;
        for (int c = lane; c < C_; c += 32)
            a += (double)xb[c] * (double)wq[(long)d * C_ + c];
        #pragma unroll
        for (int o = 16; o >= 1; o >>= 1)
            a += __shfl_xor_sync(0xffffffffu, a, o);
        if (lane == 0) q0s[d] = a;
    }
    __syncthreads();

    // phase 2: u[c] = sum_d q0[d] * wk[d][c]  (coalesced across c)
    for (int c = tid; c < C_; c += 1024) {
        double a = 0.0;
        #pragma unroll 8
        for (int d = 0; d < 64; d++)
            a += q0s[d] * (double)wk[(long)d * C_ + c];
        u[c] = a;
    }
    __syncthreads();

    // phase 3: s[j] = 0.125 * u . x[b,j,:]
    for (int j = tid; j < N_; j += 1024) {
        const float* xr = xb + (long)j * C_;
        double a0 = 0, a1 = 0, a2 = 0, a3 = 0;
        for (int c = 0; c < C_; c += 4) {
            float4 xv = *(const float4*)&xr[c];
            a0 += u[c]     * (double)xv.x;
            a1 += u[c + 1] * (double)xv.y;
            a2 += u[c + 2] * (double)xv.z;
            a3 += u[c + 3] * (double)xv.w;
        }
        s[j] = ((a0 + a1) + (a2 + a3)) * 0.125;
    }
    __syncthreads();

    // softmax (fp64, deterministic tree reductions)
    double lm = -1e300;
    for (int j = tid; j < N_; j += 1024) lm = fmax(lm, s[j]);
    #pragma unroll
    for (int o = 16; o >= 1; o >>= 1)
        lm = fmax(lm, __shfl_xor_sync(0xffffffffu, lm, o));
    if (lane == 0) red[wid] = lm;
    __syncthreads();
    if (wid == 0) {
        double t = red[lane];
        #pragma unroll
        for (int o = 16; o >= 1; o >>= 1)
            t = fmax(t, __shfl_xor_sync(0xffffffffu, t, o));
        if (lane == 0) red[0] = t;
    }
    __syncthreads();
    const double m = red[0];
    __syncthreads();

    double ls = 0.0;
    for (int j = tid; j < N_; j += 1024) {
        double e = exp(s[j] - m);
        s[j] = e;
        ls += e;
    }
    #pragma unroll
    for (int o = 16; o >= 1; o >>= 1)
        ls += __shfl_xor_sync(0xffffffffu, ls, o);
    if (lane == 0) red[wid] = ls;
    __syncthreads();
    if (wid == 0) {
        double t = red[lane];
        #pragma unroll
        for (int o = 16; o >= 1; o >>= 1)
            t += __shfl_xor_sync(0xffffffffu, t, o);
        if (lane == 0) red[0] = t;
    }
    __syncthreads();
    const double inv = 1.0 / red[0];

    for (int j = tid; j < N_ - 1; j += 1024)
        g_cls_ph[bh][j] = s[j + 1] * inv;
}

// ======================================================================
// head-mean reduce (fp64, h-ascending). One CTA per batch.
// ======================================================================
__global__ void cls_reduce_kernel(float* __restrict__ out) {
    const int b = blockIdx.x, tid = threadIdx.x;
    for (int j = tid; j < N_ - 1; j += 256) {
        double a = 0.0;
        #pragma unroll
        for (int h = 0; h < H_; h++)
            a += g_cls_ph[b * H_ + h][j] * (1.0 / 12.0);
        g_clsd[b * (N_ - 1) + j] = a;
        out[OFF_CLS + (long)b * (N_ - 1) + j] = (float)a;
    }
}

// ======================================================================
// dual bitonic top-k (103 of 1024) on fp64 keys, jax tie-break.
// ======================================================================
__global__ void sort_kernel(float* __restrict__ out) {
    __shared__ double v[1024];
    __shared__ int ix[1024];
    const int b = blockIdx.x, tid = threadIdx.x;

    for (int pass = 0; pass < 2; pass++) {
        __syncthreads();
        for (int i = tid; i < 1024; i += 512) {
            v[i] = g_clsd[b * 1024 + i];
            ix[i] = i;
        }
        __syncthreads();
        const bool desc = (pass == 0);
        for (int k = 2; k <= 1024; k <<= 1) {
            for (int j = k >> 1; j > 0; j >>= 1) {
                for (int i = tid; i < 1024; i += 512) {
                    int p = i ^ j;
                    if (p > i) {
                        double va = v[i], vb = v[p];
                        int ia = ix[i], ib = ix[p];
                        bool ab = desc ? (va > vb || (va == vb && ia < ib))
                                       : (va < vb || (va == vb && ia < ib));
                        bool up = ((i & k) == 0);
                        if (up ? !ab : ab) {
                            v[i] = vb; v[p] = va;
                            ix[i] = ib; ix[p] = ia;
                        }
                    }
                }
                __syncthreads();
            }
        }
        const long offIdx = desc ? OFF_ENH_IDX : OFF_FUSE_IDX;
        const long offBrd = desc ? OFF_ENH_INDEX : OFF_FUSE_INDEX;
        for (int t = tid; t < TOPT; t += 512)
            out[offIdx + (long)b * TOPT + t] = (float)ix[t];
        for (int e = tid; e < TOPT * C_; e += 512) {
            int t = e / C_;
            out[offBrd + ((long)b * TOPT + t) * C_ + (e % C_)] = (float)ix[t];
        }
    }
}

// ======================================================================
// Launch
// ======================================================================
extern "C" void kernel_launch(void* const* d_in, const int* in_sizes, int n_in,
                              void* d_out, int out_size) {
    const float* x     = (const float*)d_in[0];
    const float* w_qkv = (const float*)d_in[1];
    const float* w_out = (const float*)d_in[2];
    const float* b_out = (const float*)d_in[3];
    float* out = (float*)d_out;

    const int ATTN_SMEM = 4 * 64 * 65 * (int)sizeof(float);   // 66560 B
    cudaFuncSetAttribute(attn_kernel, cudaFuncAttributeMaxDynamicSharedMemorySize,
                         ATTN_SMEM);
    cudaFuncSetAttribute(mma_gemm, cudaFuncAttributeMaxDynamicSharedMemorySize,
                         MMA_SMEM);

    __nv_bfloat16 *xs0, *xs1, *xs2, *ws0, *ws1, *ws2, *wo0, *wo1, *wo2,
                  *cs0, *cs1, *cs2;
    cudaGetSymbolAddress((void**)&xs0, g_xs); xs1 = xs0 + (long)M_TOT*C_; xs2 = xs1 + (long)M_TOT*C_;
    cudaGetSymbolAddress((void**)&ws0, g_ws); ws1 = ws0 + (long)3*C_*C_;  ws2 = ws1 + (long)3*C_*C_;
    cudaGetSymbolAddress((void**)&wo0, g_wo); wo1 = wo0 + (long)C_*C_;    wo2 = wo1 + (long)C_*C_;
    cudaGetSymbolAddress((void**)&cs0, g_cs); cs1 = cs0 + (long)M_TOT*C_; cs2 = cs1 + (long)M_TOT*C_;
    float* ctxp; cudaGetSymbolAddress((void**)&ctxp, g_ctx);

    split3<<<(M_TOT*C_ + 255)/256, 256>>>(x, xs0, xs1, xs2, M_TOT*C_);
    split3<<<(3*C_*C_ + 255)/256, 256>>>(w_qkv, ws0, ws1, ws2, 3*C_*C_);
    split3<<<(C_*C_ + 255)/256, 256>>>(w_out, wo0, wo1, wo2, C_*C_);

    // QKV: [4100,2304] = x @ w_qkv^T  (tensor cores, mma.sync)
    mma_gemm<<<dim3(3*C_/128, (M_TOT + 127)/128), 256, MMA_SMEM>>>(
        xs0, xs1, xs2, ws0, ws1, ws2, 0, b_out, out);

    attn_kernel<<<dim3(17, B_ * H_), 256, ATTN_SMEM>>>();

    split3<<<(M_TOT*C_ + 255)/256, 256>>>(ctxp, cs0, cs1, cs2, M_TOT*C_);

    // OUT: [4100,768] = ctx @ w_out^T + bias
    mma_gemm<<<dim3(C_/128, (M_TOT + 127)/128), 256, MMA_SMEM>>>(
        cs0, cs1, cs2, wo0, wo1, wo2, 1, b_out, out);

    // cls path: fp64 from raw inputs, independent of GEMM rounding
    cls_head_kernel<<<B_ * H_, 1024>>>(x, w_qkv);
    cls_reduce_kernel<<<B_, 256>>>(out);
    sort_kernel<<<B_, 512>>>(out);
}

// round 8
// speedup vs baseline: 1.3812x; 1.3812x over previous
#include <cuda_runtime.h>
#include <cuda_bf16.h>
#include <math.h>
#include <cstdint>

// ---------------- Problem constants ----------------
#define B_ 4
#define N_ 1025
#define C_ 768
#define H_ 12
#define D_ 64
#define TOPT 103
#define SCALEF 0.125f            // 64^-0.5

#define M_TOT (B_ * N_)          // 4100

// Output layout (float32, reference tuple flattened & concatenated):
#define OFF_OUT        0L
#define OFF_ENH_INDEX  3148800L
#define OFF_ENH_IDX    3465216L
#define OFF_FUSE_INDEX 3465628L
#define OFF_FUSE_IDX   3782044L
#define OFF_CLS        3782456L

// ---------------- Scratch (no allocation allowed) ----------------
__device__ float  g_q[B_*H_*N_*D_];     // [b,h,n,d]
__device__ float  g_k[B_*H_*N_*D_];
__device__ float  g_v[B_*H_*N_*D_];
__device__ float  g_ctx[B_*N_*C_];      // [b,n,h*64+d]
__device__ double g_clsd[B_*(N_-1)];
__device__ double g_cls_ph[B_*H_][N_-1];

// bf16 3-way splits
__device__ __nv_bfloat16 g_xs[3][M_TOT*C_];
__device__ __nv_bfloat16 g_ws[3][3*C_*C_];     // w_qkv [2304,768]
__device__ __nv_bfloat16 g_wo[3][C_*C_];       // w_out [768,768]
__device__ __nv_bfloat16 g_cs[3][M_TOT*C_];    // ctx splits

// ======================================================================
// Split kernel: fp32 -> 3 bf16 splits (error-free to ~2^-27)
// ======================================================================
__global__ void split3(const float* __restrict__ src,
                       __nv_bfloat16* __restrict__ d0,
                       __nv_bfloat16* __restrict__ d1,
                       __nv_bfloat16* __restrict__ d2, int n) {
    int i = blockIdx.x * blockDim.x + threadIdx.x;
    if (i < n) {
        float x = src[i];
        __nv_bfloat16 b0 = __float2bfloat16(x);
        float r = x - __bfloat162float(b0);
        __nv_bfloat16 b1 = __float2bfloat16(r);
        float r2 = r - __bfloat162float(b1);
        d0[i] = b0; d1[i] = b1; d2[i] = __float2bfloat16(r2);
    }
}

// ======================================================================
// mma.sync bf16 GEMM with 3-split/6-product fp32 emulation.
// Products grouped by A-split to cut fragment LDS (9 sets vs 12 per k-step).
// ======================================================================
#define KB      32
#define LDA_P   40                      // padded row length in bf16 (80 B)
#define TILE_B  (128 * LDA_P * 2)       // 10240 B per tile
#define MMA_SMEM (6 * TILE_B)           // 61440 B

__device__ __forceinline__ void mma16816(float c[4], uint32_t a0, uint32_t a1,
                                         uint32_t a2, uint32_t a3,
                                         uint32_t b0, uint32_t b1) {
    asm volatile(
        "mma.sync.aligned.m16n8k16.row.col.f32.bf16.bf16.f32 "
        "{%0,%1,%2,%3}, {%4,%5,%6,%7}, {%8,%9}, {%0,%1,%2,%3};"
        : "+f"(c[0]), "+f"(c[1]), "+f"(c[2]), "+f"(c[3])
        : "r"(a0), "r"(a1), "r"(a2), "r"(a3), "r"(b0), "r"(b1));
}

__global__ void __launch_bounds__(256, 2)
mma_gemm(const __nv_bfloat16* __restrict__ A0, const __nv_bfloat16* __restrict__ A1,
         const __nv_bfloat16* __restrict__ A2,
         const __nv_bfloat16* __restrict__ B0, const __nv_bfloat16* __restrict__ B1,
         const __nv_bfloat16* __restrict__ B2,
         int mode, const float* __restrict__ bias, float* __restrict__ out) {
    extern __shared__ __align__(16) char smem[];
    const int tid = threadIdx.x;
    const int wid = tid >> 5, lane = tid & 31;
    const int gid = lane >> 2, tig = lane & 3;
    const int wr = wid >> 2, wc = wid & 3;        // warp grid 2 x 4
    const int m0 = blockIdx.y * 128;
    const int n0 = blockIdx.x * 128;

    const __nv_bfloat16* Asrc[3] = {A0, A1, A2};
    const __nv_bfloat16* Bsrc[3] = {B0, B1, B2};

    float acc[4][4][4];
    #pragma unroll
    for (int i = 0; i < 4; i++)
        #pragma unroll
        for (int j = 0; j < 4; j++)
            #pragma unroll
            for (int r = 0; r < 4; r++) acc[i][j][r] = 0.f;

    for (int kb = 0; kb < 24; kb++) {
        const int kcol = kb * KB;
        __syncthreads();
        #pragma unroll
        for (int s = 0; s < 3; s++) {
            const __nv_bfloat16* Ag = Asrc[s];
            const __nv_bfloat16* Bg = Bsrc[s];
            #pragma unroll
            for (int q = 0; q < 2; q++) {
                int idx = tid * 2 + q;                // 0..511
                int r = idx >> 2, c4 = idx & 3;
                int gm = m0 + r;
                uint4 va = (gm < M_TOT)
                    ? *(const uint4*)(Ag + (long)gm * C_ + kcol + c4 * 8)
                    : make_uint4(0, 0, 0, 0);
                *(uint4*)(smem + s * TILE_B + r * (LDA_P*2) + c4 * 16) = va;
                uint4 vb = *(const uint4*)(Bg + (long)(n0 + r) * C_ + kcol + c4 * 8);
                *(uint4*)(smem + (3 + s) * TILE_B + r * (LDA_P*2) + c4 * 16) = vb;
            }
        }
        __syncthreads();

        #pragma unroll
        for (int ks = 0; ks < 2; ks++) {
            const int kO = (ks * 16 + tig * 2) * 2;   // byte offset in row
            #pragma unroll
            for (int sa = 0; sa < 3; sa++) {
                const char* Asm = smem + sa * TILE_B;
                uint32_t af[4][4];
                #pragma unroll
                for (int i = 0; i < 4; i++) {
                    int row = wr * 64 + i * 16 + gid;
                    const char* pr = Asm + row * (LDA_P*2) + kO;
                    af[i][0] = *(const uint32_t*)pr;
                    af[i][1] = *(const uint32_t*)(pr + 8 * (LDA_P*2));
                    af[i][2] = *(const uint32_t*)(pr + 16);
                    af[i][3] = *(const uint32_t*)(pr + 8 * (LDA_P*2) + 16);
                }
                #pragma unroll
                for (int sb = 0; sb < 3 - sa; sb++) {   // sa+sb <= 2
                    const char* Bsm = smem + (3 + sb) * TILE_B;
                    uint32_t bf[4][2];
                    #pragma unroll
                    for (int j = 0; j < 4; j++) {
                        int nrow = wc * 32 + j * 8 + gid;
                        const char* pbp = Bsm + nrow * (LDA_P*2) + kO;
                        bf[j][0] = *(const uint32_t*)pbp;
                        bf[j][1] = *(const uint32_t*)(pbp + 16);
                    }
                    #pragma unroll
                    for (int i = 0; i < 4; i++)
                        #pragma unroll
                        for (int j = 0; j < 4; j++)
                            mma16816(acc[i][j], af[i][0], af[i][1], af[i][2],
                                     af[i][3], bf[j][0], bf[j][1]);
                }
            }
        }
    }

    // ---------------- epilogue ----------------
    #pragma unroll
    for (int i = 0; i < 4; i++) {
        #pragma unroll
        for (int half = 0; half < 2; half++) {
            int gm = m0 + wr * 64 + i * 16 + gid + half * 8;
            if (gm >= M_TOT) continue;
            int btok = gm / N_, nt = gm % N_;
            #pragma unroll
            for (int j = 0; j < 4; j++) {
                float v0 = acc[i][j][half * 2];
                float v1 = acc[i][j][half * 2 + 1];
                int jg = n0 + wc * 32 + j * 8 + tig * 2;
                if (mode == 0) {
                    int qkv_i = jg / C_;
                    int rem = jg % C_;
                    int h = rem >> 6, d0 = rem & 63;
                    float* dst = (qkv_i == 0) ? g_q : (qkv_i == 1 ? g_k : g_v);
                    long base = ((long)(btok * H_ + h) * N_ + nt) * 64 + d0;
                    *(float2*)&dst[base] = make_float2(v0, v1);
                } else {
                    long base = OFF_OUT + (long)gm * C_ + jg;
                    *(float2*)&out[base] = make_float2(v0 + bias[jg], v1 + bias[jg + 1]);
                }
            }
        }
    }
}

// ======================================================================
// Flash attention with CSA mask + masked-tile skipping (SIMT).
// ======================================================================
__global__ void attn_kernel() {
    extern __shared__ float sm[];
    float* Qs = sm;
    float* Ks = sm + 64*65;
    float* Vs = sm + 2*64*65;
    float* Ps = sm + 3*64*65;

    const int tid = threadIdx.x;
    const int ty = tid >> 4, tx = tid & 15;
    const int bh = blockIdx.y;
    const int q0g = blockIdx.x * 64;
    const float* Qg = g_q + (long)bh * N_ * 64;
    const float* Kg = g_k + (long)bh * N_ * 64;
    const float* Vg = g_v + (long)bh * N_ * 64;

    for (int idx = tid; idx < 64*64; idx += 256) {
        int r = idx >> 6, d = idx & 63;
        int qi = q0g + r;
        Qs[r*65 + d] = (qi < N_) ? Qg[(long)qi*64 + d] : 0.f;
    }

    bool q_uni = false; int qblk = -2;
    if (q0g >= 64) {
        int qhi = min(q0g + 63, N_ - 1);
        int blo = (q0g - 1) >> 8, bhi = (qhi - 1) >> 8;
        if (blo == bhi) { q_uni = true; qblk = blo; }
    }

    float acc[4][4] = {};
    float m_i[4], l_i[4];
    #pragma unroll
    for (int i = 0; i < 4; i++) { m_i[i] = -INFINITY; l_i[i] = 0.f; }

    const int r0 = ty*4, c0 = tx*4;

    for (int kt = 0; kt < 17; kt++) {
        const int k0g = kt * 64;
        if (q_uni && k0g >= 64) {
            int khi = min(k0g + 63, N_ - 1);
            int kbl = (k0g - 1) >> 8, kbh = (khi - 1) >> 8;
            if (kbl == kbh && kbl == qblk) continue;
        }
        __syncthreads();
        for (int idx = tid; idx < 64*64; idx += 256) {
            int r = idx >> 6, d = idx & 63;
            int kj = k0g + r;
            Ks[r*65 + d] = (kj < N_) ? Kg[(long)kj*64 + d] : 0.f;
            Vs[r*65 + d] = (kj < N_) ? Vg[(long)kj*64 + d] : 0.f;
        }
        __syncthreads();

        float sv[4][4] = {};
        #pragma unroll 8
        for (int kk = 0; kk < 64; kk++) {
            float a[4], b2[4];
            #pragma unroll
            for (int i = 0; i < 4; i++) a[i]  = Qs[(r0+i)*65 + kk];
            #pragma unroll
            for (int j = 0; j < 4; j++) b2[j] = Ks[(c0+j)*65 + kk];
            #pragma unroll
            for (int i = 0; i < 4; i++)
                #pragma unroll
                for (int j = 0; j < 4; j++)
                    sv[i][j] = fmaf(a[i], b2[j], sv[i][j]);
        }

        #pragma unroll
        for (int i = 0; i < 4; i++) {
            int qi = q0g + r0 + i;
            int qb = (qi >= 1) ? ((qi - 1) >> 8) : -1;
            #pragma unroll
            for (int j = 0; j < 4; j++) {
                int kj = k0g + c0 + j;
                float s = sv[i][j] * SCALEF;
                bool bad = (kj >= N_) ||
                           (qb >= 0 && kj >= 1 && (((kj - 1) >> 8) == qb));
                sv[i][j] = bad ? -INFINITY : s;
            }
        }

        #pragma unroll
        for (int i = 0; i < 4; i++) {
            float t = fmaxf(fmaxf(sv[i][0], sv[i][1]), fmaxf(sv[i][2], sv[i][3]));
            #pragma unroll
            for (int o = 8; o >= 1; o >>= 1)
                t = fmaxf(t, __shfl_xor_sync(0xffffffffu, t, o));
            float mnew = fmaxf(m_i[i], t);
            float corr = __expf(m_i[i] - mnew);
            m_i[i] = mnew;

            float p[4], rs = 0.f;
            #pragma unroll
            for (int j = 0; j < 4; j++) {
                p[j] = __expf(sv[i][j] - mnew);
                rs += p[j];
                Ps[(r0+i)*65 + c0 + j] = p[j];
            }
            #pragma unroll
            for (int o = 8; o >= 1; o >>= 1)
                rs += __shfl_xor_sync(0xffffffffu, rs, o);
            l_i[i] = l_i[i] * corr + rs;
            #pragma unroll
            for (int j = 0; j < 4; j++) acc[i][j] *= corr;
        }
        __syncthreads();

        #pragma unroll 8
        for (int jj = 0; jj < 64; jj++) {
            float p[4], v2[4];
            #pragma unroll
            for (int i = 0; i < 4; i++) p[i]  = Ps[(r0+i)*65 + jj];
            #pragma unroll
            for (int j = 0; j < 4; j++) v2[j] = Vs[jj*65 + c0 + j];
            #pragma unroll
            for (int i = 0; i < 4; i++)
                #pragma unroll
                for (int j = 0; j < 4; j++)
                    acc[i][j] = fmaf(p[i], v2[j], acc[i][j]);
        }
    }

    const int b = bh / H_, h = bh % H_;
    #pragma unroll
    for (int i = 0; i < 4; i++) {
        int qi = q0g + r0 + i;
        if (qi < N_) {
            float inv = 1.f / l_i[i];
            long base = ((long)b * N_ + qi) * C_ + h * 64 + c0;
            #pragma unroll
            for (int j = 0; j < 4; j++)
                g_ctx[base + j] = acc[i][j] * inv;
        }
    }
}

// ======================================================================
// cls per-head softmax row v4 -- GEMM-independent, from raw inputs.
//   q0 = W_q,h x_{b,0} (fp64);  u = 0.125 * W_k,h^T q0 (fp64, stored hi/lo fp32)
//   s_j = u . x_{b,j}   via warp-per-j compensated fp32 (Kahan, ~1e-13 rel)
// One CTA per (b,h), 1024 threads.
// ======================================================================
__global__ void __launch_bounds__(1024)
cls_head_kernel(const float* __restrict__ x, const float* __restrict__ w) {
    __shared__ double q0s[64];
    __shared__ float uhi[C_], ulo[C_];
    __shared__ double s[N_];
    __shared__ double red[32];
    const int bh = blockIdx.x;
    const int b = bh / H_, h = bh % H_;
    const int tid = threadIdx.x;
    const int wid = tid >> 5, lane = tid & 31;

    const float* xb = x + (long)b * N_ * C_;           // x[b,0,:] at offset 0
    const float* wq = w + (long)(h * 64) * C_;         // W_q head h [64][768]
    const float* wk = w + (long)(C_ + h * 64) * C_;    // W_k head h [64][768]

    // phase 1: q0[d] (fp64, warp per d, 2 rounds, coalesced)
    for (int d = wid; d < 64; d += 32) {
        double a = 0.0;
        for (int c = lane; c < C_; c += 32)
            a += (double)xb[c] * (double)wq[(long)d * C_ + c];
        #pragma unroll
        for (int o = 16; o >= 1; o >>= 1)
            a += __shfl_xor_sync(0xffffffffu, a, o);
        if (lane == 0) q0s[d] = a;
    }
    __syncthreads();

    // phase 2: u[c] = 0.125 * sum_d q0[d]*wk[d][c] (fp64, coalesced over c)
    for (int c = tid; c < C_; c += 1024) {
        double a = 0.0;
        #pragma unroll 8
        for (int d = 0; d < 64; d++)
            a += q0s[d] * (double)wk[(long)d * C_ + c];
        a *= 0.125;
        float hi = (float)a;
        uhi[c] = hi;
        ulo[c] = (float)(a - (double)hi);
    }
    __syncthreads();

    // phase 3: s[j] = u . x[b,j,:]  -- warp per j, compensated fp32
    for (int j = wid; j < N_; j += 32) {
        const float* xr = xb + (long)j * C_;
        float sum = 0.f, comp = 0.f, err = 0.f;
        #pragma unroll 2
        for (int c = lane * 4; c < C_; c += 128) {
            float4 xv = *(const float4*)&xr[c];
            float4 uh = *(const float4*)&uhi[c];
            float4 ul = *(const float4*)&ulo[c];
            #pragma unroll
            for (int e4 = 0; e4 < 4; e4++) {
                float xe = (&xv.x)[e4], he = (&uh.x)[e4], le = (&ul.x)[e4];
                float p = he * xe;
                err = fmaf(he, xe, -p) + err;   // exact product residual
                err = fmaf(le, xe, err);        // lo-part contribution
                // Kahan add of p into (sum, comp)
                float y = p - comp;
                float t = sum + y;
                comp = (t - sum) - y;
                sum = t;
            }
        }
        double tot = ((double)sum - (double)comp) + (double)err;
        #pragma unroll
        for (int o = 16; o >= 1; o >>= 1)
            tot += __shfl_xor_sync(0xffffffffu, tot, o);
        if (lane == 0) s[j] = tot;
    }
    __syncthreads();

    // softmax (fp64, deterministic tree reductions)
    double lm = -1e300;
    for (int j = tid; j < N_; j += 1024) lm = fmax(lm, s[j]);
    #pragma unroll
    for (int o = 16; o >= 1; o >>= 1)
        lm = fmax(lm, __shfl_xor_sync(0xffffffffu, lm, o));
    if (lane == 0) red[wid] = lm;
    __syncthreads();
    if (wid == 0) {
        double t = red[lane];
        #pragma unroll
        for (int o = 16; o >= 1; o >>= 1)
            t = fmax(t, __shfl_xor_sync(0xffffffffu, t, o));
        if (lane == 0) red[0] = t;
    }
    __syncthreads();
    const double m = red[0];
    __syncthreads();

    double ls = 0.0;
    for (int j = tid; j < N_; j += 1024) {
        double e = exp(s[j] - m);
        s[j] = e;
        ls += e;
    }
    #pragma unroll
    for (int o = 16; o >= 1; o >>= 1)
        ls += __shfl_xor_sync(0xffffffffu, ls, o);
    if (lane == 0) red[wid] = ls;
    __syncthreads();
    if (wid == 0) {
        double t = red[lane];
        #pragma unroll
        for (int o = 16; o >= 1; o >>= 1)
            t += __shfl_xor_sync(0xffffffffu, t, o);
        if (lane == 0) red[0] = t;
    }
    __syncthreads();
    const double inv = 1.0 / red[0];

    for (int j = tid; j < N_ - 1; j += 1024)
        g_cls_ph[bh][j] = s[j + 1] * inv;
}

// ======================================================================
// head-mean reduce (fp64, h-ascending). One CTA per batch.
// ======================================================================
__global__ void cls_reduce_kernel(float* __restrict__ out) {
    const int b = blockIdx.x, tid = threadIdx.x;
    for (int j = tid; j < N_ - 1; j += 256) {
        double a = 0.0;
        #pragma unroll
        for (int h = 0; h < H_; h++)
            a += g_cls_ph[b * H_ + h][j] * (1.0 / 12.0);
        g_clsd[b * (N_ - 1) + j] = a;
        out[OFF_CLS + (long)b * (N_ - 1) + j] = (float)a;
    }
}

// ======================================================================
// dual bitonic top-k (103 of 1024) on fp64 keys, jax tie-break.
// ======================================================================
__global__ void sort_kernel(float* __restrict__ out) {
    __shared__ double v[1024];
    __shared__ int ix[1024];
    const int b = blockIdx.x, tid = threadIdx.x;

    for (int pass = 0; pass < 2; pass++) {
        __syncthreads();
        for (int i = tid; i < 1024; i += 512) {
            v[i] = g_clsd[b * 1024 + i];
            ix[i] = i;
        }
        __syncthreads();
        const bool desc = (pass == 0);
        for (int k = 2; k <= 1024; k <<= 1) {
            for (int j = k >> 1; j > 0; j >>= 1) {
                for (int i = tid; i < 1024; i += 512) {
                    int p = i ^ j;
                    if (p > i) {
                        double va = v[i], vb = v[p];
                        int ia = ix[i], ib = ix[p];
                        bool ab = desc ? (va > vb || (va == vb && ia < ib))
                                       : (va < vb || (va == vb && ia < ib));
                        bool up = ((i & k) == 0);
                        if (up ? !ab : ab) {
                            v[i] = vb; v[p] = va;
                            ix[i] = ib; ix[p] = ia;
                        }
                    }
                }
                __syncthreads();
            }
        }
        const long offIdx = desc ? OFF_ENH_IDX : OFF_FUSE_IDX;
        const long offBrd = desc ? OFF_ENH_INDEX : OFF_FUSE_INDEX;
        for (int t = tid; t < TOPT; t += 512)
            out[offIdx + (long)b * TOPT + t] = (float)ix[t];
        for (int e = tid; e < TOPT * C_; e += 512) {
            int t = e / C_;
            out[offBrd + ((long)b * TOPT + t) * C_ + (e % C_)] = (float)ix[t];
        }
    }
}

// ======================================================================
// Launch
// ======================================================================
extern "C" void kernel_launch(void* const* d_in, const int* in_sizes, int n_in,
                              void* d_out, int out_size) {
    const float* x     = (const float*)d_in[0];
    const float* w_qkv = (const float*)d_in[1];
    const float* w_out = (const float*)d_in[2];
    const float* b_out = (const float*)d_in[3];
    float* out = (float*)d_out;

    const int ATTN_SMEM = 4 * 64 * 65 * (int)sizeof(float);   // 66560 B
    cudaFuncSetAttribute(attn_kernel, cudaFuncAttributeMaxDynamicSharedMemorySize,
                         ATTN_SMEM);
    cudaFuncSetAttribute(mma_gemm, cudaFuncAttributeMaxDynamicSharedMemorySize,
                         MMA_SMEM);

    __nv_bfloat16 *xs0, *xs1, *xs2, *ws0, *ws1, *ws2, *wo0, *wo1, *wo2,
                  *cs0, *cs1, *cs2;
    cudaGetSymbolAddress((void**)&xs0, g_xs); xs1 = xs0 + (long)M_TOT*C_; xs2 = xs1 + (long)M_TOT*C_;
    cudaGetSymbolAddress((void**)&ws0, g_ws); ws1 = ws0 + (long)3*C_*C_;  ws2 = ws1 + (long)3*C_*C_;
    cudaGetSymbolAddress((void**)&wo0, g_wo); wo1 = wo0 + (long)C_*C_;    wo2 = wo1 + (long)C_*C_;
    cudaGetSymbolAddress((void**)&cs0, g_cs); cs1 = cs0 + (long)M_TOT*C_; cs2 = cs1 + (long)M_TOT*C_;
    float* ctxp; cudaGetSymbolAddress((void**)&ctxp, g_ctx);

    split3<<<(M_TOT*C_ + 255)/256, 256>>>(x, xs0, xs1, xs2, M_TOT*C_);
    split3<<<(3*C_*C_ + 255)/256, 256>>>(w_qkv, ws0, ws1, ws2, 3*C_*C_);
    split3<<<(C_*C_ + 255)/256, 256>>>(w_out, wo0, wo1, wo2, C_*C_);

    // QKV: [4100,2304] = x @ w_qkv^T  (tensor cores, mma.sync)
    mma_gemm<<<dim3(3*C_/128, (M_TOT + 127)/128), 256, MMA_SMEM>>>(
        xs0, xs1, xs2, ws0, ws1, ws2, 0, b_out, out);

    attn_kernel<<<dim3(17, B_ * H_), 256, ATTN_SMEM>>>();

    split3<<<(M_TOT*C_ + 255)/256, 256>>>(ctxp, cs0, cs1, cs2, M_TOT*C_);

    // OUT: [4100,768] = ctx @ w_out^T + bias
    mma_gemm<<<dim3(C_/128, (M_TOT + 127)/128), 256, MMA_SMEM>>>(
        cs0, cs1, cs2, wo0, wo1, wo2, 1, b_out, out);

    // cls path: high-precision from raw inputs, independent of GEMM rounding
    cls_head_kernel<<<B_ * H_, 1024>>>(x, w_qkv);
    cls_reduce_kernel<<<B_, 256>>>(out);
    sort_kernel<<<B_, 512>>>(out);
}

// round 9
// speedup vs baseline: 2.0486x; 1.4832x over previous
#include <cuda_runtime.h>
#include <cuda_bf16.h>
#include <math.h>
#include <cstdint>

// ---------------- Problem constants ----------------
#define B_ 4
#define N_ 1025
#define C_ 768
#define H_ 12
#define D_ 64
#define TOPT 103
#define SCALEF 0.125f            // 64^-0.5

#define M_TOT (B_ * N_)          // 4100

// Output layout (float32, reference tuple flattened & concatenated):
#define OFF_OUT        0L
#define OFF_ENH_INDEX  3148800L
#define OFF_ENH_IDX    3465216L
#define OFF_FUSE_INDEX 3465628L
#define OFF_FUSE_IDX   3782044L
#define OFF_CLS        3782456L

// ---------------- Scratch (no allocation allowed) ----------------
__device__ float  g_q[B_*H_*N_*D_];     // [b,h,n,d]
__device__ float  g_k[B_*H_*N_*D_];
__device__ float  g_v[B_*H_*N_*D_];
__device__ float  g_ctx[B_*N_*C_];      // [b,n,h*64+d]
__device__ double g_clsd[B_*(N_-1)];
__device__ double g_cls_ph[B_*H_][N_-1];

// bf16 2-way splits
__device__ __nv_bfloat16 g_xs[2][M_TOT*C_];
__device__ __nv_bfloat16 g_ws[2][3*C_*C_];     // w_qkv [2304,768]
__device__ __nv_bfloat16 g_wo[2][C_*C_];       // w_out [768,768]
__device__ __nv_bfloat16 g_cs[2][M_TOT*C_];    // ctx splits

// ======================================================================
// Split kernel: fp32 -> 2 bf16 splits (residual ~2^-16)
// ======================================================================
__global__ void split2(const float* __restrict__ src,
                       __nv_bfloat16* __restrict__ d0,
                       __nv_bfloat16* __restrict__ d1, int n) {
    int i = blockIdx.x * blockDim.x + threadIdx.x;
    if (i < n) {
        float x = src[i];
        __nv_bfloat16 b0 = __float2bfloat16(x);
        d0[i] = b0;
        d1[i] = __float2bfloat16(x - __bfloat162float(b0));
    }
}

// ======================================================================
// mma.sync bf16 GEMM, 2-split / 3-product fp32-ish emulation (~1e-4 rel).
// D[m,n] = sum_k A[m,k]*B[n,k], K=768.  CTA 128x128, 8 warps, KB=32.
// mode 0: scatter g_q/g_k/g_v; mode 1: out + bias.
// ======================================================================
#define KB      32
#define LDA_P   40                      // padded row length in bf16 (80 B)
#define TILE_B  (128 * LDA_P * 2)       // 10240 B per tile
#define MMA_SMEM (4 * TILE_B)           // 40960 B

__device__ __forceinline__ void mma16816(float c[4], uint32_t a0, uint32_t a1,
                                         uint32_t a2, uint32_t a3,
                                         uint32_t b0, uint32_t b1) {
    asm volatile(
        "mma.sync.aligned.m16n8k16.row.col.f32.bf16.bf16.f32 "
        "{%0,%1,%2,%3}, {%4,%5,%6,%7}, {%8,%9}, {%0,%1,%2,%3};"
        : "+f"(c[0]), "+f"(c[1]), "+f"(c[2]), "+f"(c[3])
        : "r"(a0), "r"(a1), "r"(a2), "r"(a3), "r"(b0), "r"(b1));
}

__global__ void __launch_bounds__(256, 2)
mma_gemm(const __nv_bfloat16* __restrict__ A0, const __nv_bfloat16* __restrict__ A1,
         const __nv_bfloat16* __restrict__ B0, const __nv_bfloat16* __restrict__ B1,
         int mode, const float* __restrict__ bias, float* __restrict__ out) {
    extern __shared__ __align__(16) char smem[];
    const int tid = threadIdx.x;
    const int wid = tid >> 5, lane = tid & 31;
    const int gid = lane >> 2, tig = lane & 3;
    const int wr = wid >> 2, wc = wid & 3;        // warp grid 2 x 4
    const int m0 = blockIdx.y * 128;
    const int n0 = blockIdx.x * 128;

    const __nv_bfloat16* Asrc[2] = {A0, A1};
    const __nv_bfloat16* Bsrc[2] = {B0, B1};

    float acc[4][4][4];
    #pragma unroll
    for (int i = 0; i < 4; i++)
        #pragma unroll
        for (int j = 0; j < 4; j++)
            #pragma unroll
            for (int r = 0; r < 4; r++) acc[i][j][r] = 0.f;

    for (int kb = 0; kb < 24; kb++) {
        const int kcol = kb * KB;
        __syncthreads();
        #pragma unroll
        for (int s = 0; s < 2; s++) {
            const __nv_bfloat16* Ag = Asrc[s];
            const __nv_bfloat16* Bg = Bsrc[s];
            #pragma unroll
            for (int q = 0; q < 2; q++) {
                int idx = tid * 2 + q;                // 0..511
                int r = idx >> 2, c4 = idx & 3;
                int gm = m0 + r;
                uint4 va = (gm < M_TOT)
                    ? *(const uint4*)(Ag + (long)gm * C_ + kcol + c4 * 8)
                    : make_uint4(0, 0, 0, 0);
                *(uint4*)(smem + s * TILE_B + r * (LDA_P*2) + c4 * 16) = va;
                uint4 vb = *(const uint4*)(Bg + (long)(n0 + r) * C_ + kcol + c4 * 8);
                *(uint4*)(smem + (2 + s) * TILE_B + r * (LDA_P*2) + c4 * 16) = vb;
            }
        }
        __syncthreads();

        #pragma unroll
        for (int ks = 0; ks < 2; ks++) {
            const int kO = (ks * 16 + tig * 2) * 2;   // byte offset in row
            #pragma unroll
            for (int sa = 0; sa < 2; sa++) {
                const char* Asm = smem + sa * TILE_B;
                uint32_t af[4][4];
                #pragma unroll
                for (int i = 0; i < 4; i++) {
                    int row = wr * 64 + i * 16 + gid;
                    const char* pr = Asm + row * (LDA_P*2) + kO;
                    af[i][0] = *(const uint32_t*)pr;
                    af[i][1] = *(const uint32_t*)(pr + 8 * (LDA_P*2));
                    af[i][2] = *(const uint32_t*)(pr + 16);
                    af[i][3] = *(const uint32_t*)(pr + 8 * (LDA_P*2) + 16);
                }
                #pragma unroll
                for (int sb = 0; sb < 2 - sa; sb++) {   // (0,0),(0,1),(1,0)
                    const char* Bsm = smem + (2 + sb) * TILE_B;
                    uint32_t bf[4][2];
                    #pragma unroll
                    for (int j = 0; j < 4; j++) {
                        int nrow = wc * 32 + j * 8 + gid;
                        const char* pbp = Bsm + nrow * (LDA_P*2) + kO;
                        bf[j][0] = *(const uint32_t*)pbp;
                        bf[j][1] = *(const uint32_t*)(pbp + 16);
                    }
                    #pragma unroll
                    for (int i = 0; i < 4; i++)
                        #pragma unroll
                        for (int j = 0; j < 4; j++)
                            mma16816(acc[i][j], af[i][0], af[i][1], af[i][2],
                                     af[i][3], bf[j][0], bf[j][1]);
                }
            }
        }
    }

    // ---------------- epilogue ----------------
    #pragma unroll
    for (int i = 0; i < 4; i++) {
        #pragma unroll
        for (int half = 0; half < 2; half++) {
            int gm = m0 + wr * 64 + i * 16 + gid + half * 8;
            if (gm >= M_TOT) continue;
            int btok = gm / N_, nt = gm % N_;
            #pragma unroll
            for (int j = 0; j < 4; j++) {
                float v0 = acc[i][j][half * 2];
                float v1 = acc[i][j][half * 2 + 1];
                int jg = n0 + wc * 32 + j * 8 + tig * 2;
                if (mode == 0) {
                    int qkv_i = jg / C_;
                    int rem = jg % C_;
                    int h = rem >> 6, d0 = rem & 63;
                    float* dst = (qkv_i == 0) ? g_q : (qkv_i == 1 ? g_k : g_v);
                    long base = ((long)(btok * H_ + h) * N_ + nt) * 64 + d0;
                    *(float2*)&dst[base] = make_float2(v0, v1);
                } else {
                    long base = OFF_OUT + (long)gm * C_ + jg;
                    *(float2*)&out[base] = make_float2(v0 + bias[jg], v1 + bias[jg + 1]);
                }
            }
        }
    }
}

// ======================================================================
// mma.sync flash attention, bf16 2-split / 3-product, CSA mask,
// per-warp masked-tile skip. CTA = 128 q-rows x (b,h); 8 warps x 16 rows.
// SMEM: phase A = Q splits [128][72]x2; phase B = K splits + V^T splits.
// ======================================================================
#define AP 36                            // words per padded 64-col bf16 row
#define ATTN_SMEM2 (2 * 128 * AP * 4)    // 36864 B (both phases fit)

__device__ __forceinline__ void split_pack(float x, float y,
                                           uint32_t& hi, uint32_t& lo) {
    __nv_bfloat16 x0 = __float2bfloat16(x);
    __nv_bfloat16 y0 = __float2bfloat16(y);
    __nv_bfloat16 x1 = __float2bfloat16(x - __bfloat162float(x0));
    __nv_bfloat16 y1 = __float2bfloat16(y - __bfloat162float(y0));
    __nv_bfloat162 h; h.x = x0; h.y = y0;
    __nv_bfloat162 l; l.x = x1; l.y = y1;
    hi = *(uint32_t*)&h; lo = *(uint32_t*)&l;
}

__global__ void __launch_bounds__(256)
attn_mma() {
    extern __shared__ __align__(16) uint32_t asw[];
    const int tid = threadIdx.x;
    const int wid = tid >> 5, lane = tid & 31;
    const int gid = lane >> 2, tig = lane & 3;
    const int bh = blockIdx.y;
    const int q0g = blockIdx.x * 128;
    const float* Qg = g_q + (long)bh * N_ * 64;
    const float* Kg = g_k + (long)bh * N_ * 64;
    const float* Vg = g_v + (long)bh * N_ * 64;

    // ---- phase A: stage Q (fp32 -> 2 bf16 splits), extract fragments ----
    {
        __nv_bfloat16* Q0 = (__nv_bfloat16*)asw;
        __nv_bfloat16* Q1 = (__nv_bfloat16*)(asw + 128 * AP);
        for (int idx = tid; idx < 128 * 64; idx += 256) {
            int r = idx >> 6, d = idx & 63;
            int qi = q0g + r;
            float v = (qi < N_) ? Qg[(long)qi * 64 + d] : 0.f;
            __nv_bfloat16 h0 = __float2bfloat16(v);
            Q0[r * 72 + d] = h0;
            Q1[r * 72 + d] = __float2bfloat16(v - __bfloat162float(h0));
        }
    }
    __syncthreads();
    uint32_t qf[2][4][4];
    {
        int row = wid * 16 + gid;
        #pragma unroll
        for (int ks = 0; ks < 4; ks++) {
            int b0 = row * AP + ks * 8 + tig;
            int b1 = (row + 8) * AP + ks * 8 + tig;
            #pragma unroll
            for (int s = 0; s < 2; s++) {
                const uint32_t* Qp = asw + s * 128 * AP;
                qf[s][ks][0] = Qp[b0];
                qf[s][ks][1] = Qp[b1];
                qf[s][ks][2] = Qp[b0 + 4];
                qf[s][ks][3] = Qp[b1 + 4];
            }
        }
    }
    __syncthreads();

    uint32_t* Ks0 = asw;
    uint32_t* Ks1 = asw + 64 * AP;
    uint32_t* Vt0 = asw + 2 * 64 * AP;
    uint32_t* Vt1 = asw + 3 * 64 * AP;

    float accD[8][4];
    #pragma unroll
    for (int dt = 0; dt < 8; dt++)
        #pragma unroll
        for (int r = 0; r < 4; r++) accD[dt][r] = 0.f;
    float m2[2] = {-INFINITY, -INFINITY};
    float l2[2] = {0.f, 0.f};

    // per-warp q-block uniformity (rows wid*16 .. +15)
    const int rlo = q0g + wid * 16;
    bool w_dead = (rlo >= N_);
    bool wq_uni = false; int wqb = -2;
    if (!w_dead && rlo >= 1) {
        int rhi = min(rlo + 15, N_ - 1);
        int b0 = (rlo - 1) >> 8, b1 = (rhi - 1) >> 8;
        if (b0 == b1 && b0 < 4) { wq_uni = true; wqb = b0; }
    }

    for (int kt = 0; kt < 17; kt++) {
        const int k0g = kt * 64;
        __syncthreads();
        // stage K (split) and V (split, transposed)
        for (int idx = tid; idx < 64 * 64; idx += 256) {
            int r = idx >> 6, d = idx & 63;
            int kj = k0g + r;
            float kv = (kj < N_) ? Kg[(long)kj * 64 + d] : 0.f;
            __nv_bfloat16 k0 = __float2bfloat16(kv);
            ((__nv_bfloat16*)Ks0)[r * 72 + d] = k0;
            ((__nv_bfloat16*)Ks1)[r * 72 + d] =
                __float2bfloat16(kv - __bfloat162float(k0));
            float vv = (kj < N_) ? Vg[(long)kj * 64 + d] : 0.f;
            __nv_bfloat16 v0 = __float2bfloat16(vv);
            ((__nv_bfloat16*)Vt0)[d * 72 + r] = v0;
            ((__nv_bfloat16*)Vt1)[d * 72 + r] =
                __float2bfloat16(vv - __bfloat162float(v0));
        }
        __syncthreads();

        bool skip = w_dead;
        if (!skip && wq_uni && k0g >= 64) {
            int khi = min(k0g + 63, N_ - 1);
            int kb0 = (k0g - 1) >> 8, kb1 = (khi - 1) >> 8;
            if (kb0 == kb1 && kb0 == wqb) skip = true;
        }
        if (skip) continue;   // only compute is skipped; both barriers above done

        // ---- S = Q K^T (3 products) ----
        float sp[8][4];
        #pragma unroll
        for (int nt = 0; nt < 8; nt++)
            #pragma unroll
            for (int r = 0; r < 4; r++) sp[nt][r] = 0.f;

        #pragma unroll
        for (int ks = 0; ks < 4; ks++) {
            #pragma unroll
            for (int nt = 0; nt < 8; nt++) {
                int kw = (nt * 8 + gid) * AP + ks * 8 + tig;
                uint32_t k00 = Ks0[kw], k01 = Ks0[kw + 4];
                uint32_t k10 = Ks1[kw], k11 = Ks1[kw + 4];
                mma16816(sp[nt], qf[0][ks][0], qf[0][ks][1], qf[0][ks][2],
                         qf[0][ks][3], k00, k01);
                mma16816(sp[nt], qf[0][ks][0], qf[0][ks][1], qf[0][ks][2],
                         qf[0][ks][3], k10, k11);
                mma16816(sp[nt], qf[1][ks][0], qf[1][ks][1], qf[1][ks][2],
                         qf[1][ks][3], k00, k01);
            }
        }

        // ---- scale + CSA mask ----
        #pragma unroll
        for (int nt = 0; nt < 8; nt++) {
            #pragma unroll
            for (int c = 0; c < 4; c++) {
                int row = rlo + gid + ((c >= 2) ? 8 : 0);
                int key = k0g + nt * 8 + 2 * tig + (c & 1);
                float s = sp[nt][c] * SCALEF;
                int qb = (row >= 1 && row < N_) ? ((row - 1) >> 8) : -1;
                bool bad = (key >= N_) ||
                           (qb >= 0 && key >= 1 && ((key - 1) >> 8) == qb);
                sp[nt][c] = bad ? -INFINITY : s;
            }
        }

        // ---- online softmax (per half: rows gid, gid+8) ----
        #pragma unroll
        for (int half = 0; half < 2; half++) {
            float mx = -INFINITY;
            #pragma unroll
            for (int nt = 0; nt < 8; nt++)
                mx = fmaxf(mx, fmaxf(sp[nt][half*2], sp[nt][half*2+1]));
            mx = fmaxf(mx, __shfl_xor_sync(0xffffffffu, mx, 1));
            mx = fmaxf(mx, __shfl_xor_sync(0xffffffffu, mx, 2));
            float mnew = fmaxf(m2[half], mx);
            float corr = __expf(m2[half] - mnew);
            m2[half] = mnew;
            float rs = 0.f;
            #pragma unroll
            for (int nt = 0; nt < 8; nt++) {
                float p0 = __expf(sp[nt][half*2]   - mnew);
                float p1 = __expf(sp[nt][half*2+1] - mnew);
                sp[nt][half*2] = p0; sp[nt][half*2+1] = p1;
                rs += p0 + p1;
            }
            rs += __shfl_xor_sync(0xffffffffu, rs, 1);
            rs += __shfl_xor_sync(0xffffffffu, rs, 2);
            l2[half] = l2[half] * corr + rs;
            #pragma unroll
            for (int dt = 0; dt < 8; dt++) {
                accD[dt][half*2]   *= corr;
                accD[dt][half*2+1] *= corr;
            }
        }

        // ---- O += P V (3 products), P frags straight from S accumulators ----
        #pragma unroll
        for (int ks = 0; ks < 4; ks++) {
            uint32_t p0[4], p1[4];
            split_pack(sp[2*ks][0],   sp[2*ks][1],   p0[0], p1[0]);
            split_pack(sp[2*ks][2],   sp[2*ks][3],   p0[1], p1[1]);
            split_pack(sp[2*ks+1][0], sp[2*ks+1][1], p0[2], p1[2]);
            split_pack(sp[2*ks+1][2], sp[2*ks+1][3], p0[3], p1[3]);
            #pragma unroll
            for (int dt = 0; dt < 8; dt++) {
                int vw = (dt * 8 + gid) * AP + ks * 8 + tig;
                uint32_t v00 = Vt0[vw], v01 = Vt0[vw + 4];
                uint32_t v10 = Vt1[vw], v11 = Vt1[vw + 4];
                mma16816(accD[dt], p0[0], p0[1], p0[2], p0[3], v00, v01);
                mma16816(accD[dt], p0[0], p0[1], p0[2], p0[3], v10, v11);
                mma16816(accD[dt], p1[0], p1[1], p1[2], p1[3], v00, v01);
            }
        }
    }

    // ---- epilogue ----
    const int b = bh / H_, h = bh % H_;
    #pragma unroll
    for (int half = 0; half < 2; half++) {
        int row = rlo + gid + half * 8;
        if (row < N_) {
            float inv = 1.f / l2[half];
            #pragma unroll
            for (int dt = 0; dt < 8; dt++) {
                int d = dt * 8 + 2 * tig;
                long base = ((long)b * N_ + row) * C_ + h * 64 + d;
                g_ctx[base]     = accD[dt][half*2]   * inv;
                g_ctx[base + 1] = accD[dt][half*2+1] * inv;
            }
        }
    }
}

// ======================================================================
// cls per-head softmax row -- GEMM-independent (raw inputs), high precision.
// ======================================================================
__global__ void __launch_bounds__(1024)
cls_head_kernel(const float* __restrict__ x, const float* __restrict__ w) {
    __shared__ double q0s[64];
    __shared__ float uhi[C_], ulo[C_];
    __shared__ double s[N_];
    __shared__ double red[32];
    const int bh = blockIdx.x;
    const int b = bh / H_, h = bh % H_;
    const int tid = threadIdx.x;
    const int wid = tid >> 5, lane = tid & 31;

    const float* xb = x + (long)b * N_ * C_;
    const float* wq = w + (long)(h * 64) * C_;
    const float* wk = w + (long)(C_ + h * 64) * C_;

    for (int d = wid; d < 64; d += 32) {
        double a = 0.0;
        for (int c = lane; c < C_; c += 32)
            a += (double)xb[c] * (double)wq[(long)d * C_ + c];
        #pragma unroll
        for (int o = 16; o >= 1; o >>= 1)
            a += __shfl_xor_sync(0xffffffffu, a, o);
        if (lane == 0) q0s[d] = a;
    }
    __syncthreads();

    for (int c = tid; c < C_; c += 1024) {
        double a = 0.0;
        #pragma unroll 8
        for (int d = 0; d < 64; d++)
            a += q0s[d] * (double)wk[(long)d * C_ + c];
        a *= 0.125;
        float hi = (float)a;
        uhi[c] = hi;
        ulo[c] = (float)(a - (double)hi);
    }
    __syncthreads();

    for (int j = wid; j < N_; j += 32) {
        const float* xr = xb + (long)j * C_;
        float sum = 0.f, comp = 0.f, err = 0.f;
        #pragma unroll 2
        for (int c = lane * 4; c < C_; c += 128) {
            float4 xv = *(const float4*)&xr[c];
            float4 uh = *(const float4*)&uhi[c];
            float4 ul = *(const float4*)&ulo[c];
            #pragma unroll
            for (int e4 = 0; e4 < 4; e4++) {
                float xe = (&xv.x)[e4], he = (&uh.x)[e4], le = (&ul.x)[e4];
                float p = he * xe;
                err = fmaf(he, xe, -p) + err;
                err = fmaf(le, xe, err);
                float y = p - comp;
                float t = sum + y;
                comp = (t - sum) - y;
                sum = t;
            }
        }
        double tot = ((double)sum - (double)comp) + (double)err;
        #pragma unroll
        for (int o = 16; o >= 1; o >>= 1)
            tot += __shfl_xor_sync(0xffffffffu, tot, o);
        if (lane == 0) s[j] = tot;
    }
    __syncthreads();

    double lm = -1e300;
    for (int j = tid; j < N_; j += 1024) lm = fmax(lm, s[j]);
    #pragma unroll
    for (int o = 16; o >= 1; o >>= 1)
        lm = fmax(lm, __shfl_xor_sync(0xffffffffu, lm, o));
    if (lane == 0) red[wid] = lm;
    __syncthreads();
    if (wid == 0) {
        double t = red[lane];
        #pragma unroll
        for (int o = 16; o >= 1; o >>= 1)
            t = fmax(t, __shfl_xor_sync(0xffffffffu, t, o));
        if (lane == 0) red[0] = t;
    }
    __syncthreads();
    const double m = red[0];
    __syncthreads();

    double ls = 0.0;
    for (int j = tid; j < N_; j += 1024) {
        double e = exp(s[j] - m);
        s[j] = e;
        ls += e;
    }
    #pragma unroll
    for (int o = 16; o >= 1; o >>= 1)
        ls += __shfl_xor_sync(0xffffffffu, ls, o);
    if (lane == 0) red[wid] = ls;
    __syncthreads();
    if (wid == 0) {
        double t = red[lane];
        #pragma unroll
        for (int o = 16; o >= 1; o >>= 1)
            t += __shfl_xor_sync(0xffffffffu, t, o);
        if (lane == 0) red[0] = t;
    }
    __syncthreads();
    const double inv = 1.0 / red[0];

    for (int j = tid; j < N_ - 1; j += 1024)
        g_cls_ph[bh][j] = s[j + 1] * inv;
}

// ======================================================================
// head-mean reduce (fp64, h-ascending). One CTA per batch.
// ======================================================================
__global__ void cls_reduce_kernel(float* __restrict__ out) {
    const int b = blockIdx.x, tid = threadIdx.x;
    for (int j = tid; j < N_ - 1; j += 256) {
        double a = 0.0;
        #pragma unroll
        for (int h = 0; h < H_; h++)
            a += g_cls_ph[b * H_ + h][j] * (1.0 / 12.0);
        g_clsd[b * (N_ - 1) + j] = a;
        out[OFF_CLS + (long)b * (N_ - 1) + j] = (float)a;
    }
}

// ======================================================================
// dual bitonic top-k (103 of 1024) on fp64 keys, jax tie-break.
// ======================================================================
__global__ void sort_kernel(float* __restrict__ out) {
    __shared__ double v[1024];
    __shared__ int ix[1024];
    const int b = blockIdx.x, tid = threadIdx.x;

    for (int pass = 0; pass < 2; pass++) {
        __syncthreads();
        for (int i = tid; i < 1024; i += 512) {
            v[i] = g_clsd[b * 1024 + i];
            ix[i] = i;
        }
        __syncthreads();
        const bool desc = (pass == 0);
        for (int k = 2; k <= 1024; k <<= 1) {
            for (int j = k >> 1; j > 0; j >>= 1) {
                for (int i = tid; i < 1024; i += 512) {
                    int p = i ^ j;
                    if (p > i) {
                        double va = v[i], vb = v[p];
                        int ia = ix[i], ib = ix[p];
                        bool ab = desc ? (va > vb || (va == vb && ia < ib))
                                       : (va < vb || (va == vb && ia < ib));
                        bool up = ((i & k) == 0);
                        if (up ? !ab : ab) {
                            v[i] = vb; v[p] = va;
                            ix[i] = ib; ix[p] = ia;
                        }
                    }
                }
                __syncthreads();
            }
        }
        const long offIdx = desc ? OFF_ENH_IDX : OFF_FUSE_IDX;
        const long offBrd = desc ? OFF_ENH_INDEX : OFF_FUSE_INDEX;
        for (int t = tid; t < TOPT; t += 512)
            out[offIdx + (long)b * TOPT + t] = (float)ix[t];
        for (int e = tid; e < TOPT * C_; e += 512) {
            int t = e / C_;
            out[offBrd + ((long)b * TOPT + t) * C_ + (e % C_)] = (float)ix[t];
        }
    }
}

// ======================================================================
// Launch
// ======================================================================
extern "C" void kernel_launch(void* const* d_in, const int* in_sizes, int n_in,
                              void* d_out, int out_size) {
    const float* x     = (const float*)d_in[0];
    const float* w_qkv = (const float*)d_in[1];
    const float* w_out = (const float*)d_in[2];
    const float* b_out = (const float*)d_in[3];
    float* out = (float*)d_out;

    cudaFuncSetAttribute(mma_gemm, cudaFuncAttributeMaxDynamicSharedMemorySize,
                         MMA_SMEM);
    cudaFuncSetAttribute(attn_mma, cudaFuncAttributeMaxDynamicSharedMemorySize,
                         ATTN_SMEM2);

    __nv_bfloat16 *xs0, *xs1, *ws0, *ws1, *wo0, *wo1, *cs0, *cs1;
    cudaGetSymbolAddress((void**)&xs0, g_xs); xs1 = xs0 + (long)M_TOT*C_;
    cudaGetSymbolAddress((void**)&ws0, g_ws); ws1 = ws0 + (long)3*C_*C_;
    cudaGetSymbolAddress((void**)&wo0, g_wo); wo1 = wo0 + (long)C_*C_;
    cudaGetSymbolAddress((void**)&cs0, g_cs); cs1 = cs0 + (long)M_TOT*C_;
    float* ctxp; cudaGetSymbolAddress((void**)&ctxp, g_ctx);

    split2<<<(M_TOT*C_ + 255)/256, 256>>>(x, xs0, xs1, M_TOT*C_);
    split2<<<(3*C_*C_ + 255)/256, 256>>>(w_qkv, ws0, ws1, 3*C_*C_);
    split2<<<(C_*C_ + 255)/256, 256>>>(w_out, wo0, wo1, C_*C_);

    // QKV: [4100,2304] = x @ w_qkv^T
    mma_gemm<<<dim3(3*C_/128, (M_TOT + 127)/128), 256, MMA_SMEM>>>(
        xs0, xs1, ws0, ws1, 0, b_out, out);

    // attention (tensor cores)
    attn_mma<<<dim3((N_ + 127)/128, B_ * H_), 256, ATTN_SMEM2>>>();

    split2<<<(M_TOT*C_ + 255)/256, 256>>>(ctxp, cs0, cs1, M_TOT*C_);

    // OUT: [4100,768] = ctx @ w_out^T + bias
    mma_gemm<<<dim3(C_/128, (M_TOT + 127)/128), 256, MMA_SMEM>>>(
        cs0, cs1, wo0, wo1, 1, b_out, out);

    // cls path: high-precision from raw inputs (GEMM-independent)
    cls_head_kernel<<<B_ * H_, 1024>>>(x, w_qkv);
    cls_reduce_kernel<<<B_, 256>>>(out);
    sort_kernel<<<B_, 512>>>(out);
}

// round 10
// speedup vs baseline: 2.2238x; 1.0855x over previous
#include <cuda_runtime.h>
#include <cuda_bf16.h>
#include <math.h>
#include <cstdint>

// ---------------- Problem constants ----------------
#define B_ 4
#define N_ 1025
#define C_ 768
#define H_ 12
#define D_ 64
#define TOPT 103
#define SCALEF 0.125f            // 64^-0.5

#define M_TOT (B_ * N_)          // 4100

// Output layout (float32, reference tuple flattened & concatenated):
#define OFF_OUT        0L
#define OFF_ENH_INDEX  3148800L
#define OFF_ENH_IDX    3465216L
#define OFF_FUSE_INDEX 3465628L
#define OFF_FUSE_IDX   3782044L
#define OFF_CLS        3782456L

// ---------------- Scratch (no allocation allowed) ----------------
__device__ float  g_ctx[B_*N_*C_];      // [b,n,h*64+d]
__device__ double g_clsd[B_*(N_-1)];
__device__ double g_cls_ph[B_*H_][N_-1];

// bf16 2-way splits
__device__ __nv_bfloat16 g_xs[2][M_TOT*C_];
__device__ __nv_bfloat16 g_ws[2][3*C_*C_];     // w_qkv [2304,768]
__device__ __nv_bfloat16 g_wo[2][C_*C_];       // w_out [768,768]
__device__ __nv_bfloat16 g_cs[2][M_TOT*C_];    // ctx splits
// q/k/v as bf16 splits, [b,h,n,d] (written directly by QKV GEMM epilogue)
__device__ __nv_bfloat16 g_qs[2][B_*H_*N_*D_];
__device__ __nv_bfloat16 g_ks[2][B_*H_*N_*D_];
__device__ __nv_bfloat16 g_vs[2][B_*H_*N_*D_];

// ================= helpers =================
__device__ __forceinline__ void ldsm4(uint32_t* r, uint32_t addr) {
    asm volatile("ldmatrix.sync.aligned.m8n8.x4.shared.b16 {%0,%1,%2,%3}, [%4];"
        : "=r"(r[0]), "=r"(r[1]), "=r"(r[2]), "=r"(r[3]) : "r"(addr));
}
__device__ __forceinline__ void mma16816(float c[4], uint32_t a0, uint32_t a1,
                                         uint32_t a2, uint32_t a3,
                                         uint32_t b0, uint32_t b1) {
    asm volatile(
        "mma.sync.aligned.m16n8k16.row.col.f32.bf16.bf16.f32 "
        "{%0,%1,%2,%3}, {%4,%5,%6,%7}, {%8,%9}, {%0,%1,%2,%3};"
        : "+f"(c[0]), "+f"(c[1]), "+f"(c[2]), "+f"(c[3])
        : "r"(a0), "r"(a1), "r"(a2), "r"(a3), "r"(b0), "r"(b1));
}
__device__ __forceinline__ void split_pack(float x, float y,
                                           uint32_t& hi, uint32_t& lo) {
    __nv_bfloat16 x0 = __float2bfloat16(x);
    __nv_bfloat16 y0 = __float2bfloat16(y);
    __nv_bfloat16 x1 = __float2bfloat16(x - __bfloat162float(x0));
    __nv_bfloat16 y1 = __float2bfloat16(y - __bfloat162float(y0));
    __nv_bfloat162 h; h.x = x0; h.y = y0;
    __nv_bfloat162 l; l.x = x1; l.y = y1;
    hi = *(uint32_t*)&h; lo = *(uint32_t*)&l;
}

// ======================================================================
// Split kernel: fp32 -> 2 bf16 splits (residual ~2^-16)
// ======================================================================
__global__ void split2(const float* __restrict__ src,
                       __nv_bfloat16* __restrict__ d0,
                       __nv_bfloat16* __restrict__ d1, int n) {
    int i = blockIdx.x * blockDim.x + threadIdx.x;
    if (i < n) {
        float x = src[i];
        __nv_bfloat16 b0 = __float2bfloat16(x);
        d0[i] = b0;
        d1[i] = __float2bfloat16(x - __bfloat162float(b0));
    }
}

// ======================================================================
// mma.sync bf16 GEMM, 2-split / 3-product, ldmatrix fragments.
// mode 0: write q/k/v bf16 splits; mode 1: out + bias (fp32).
// ======================================================================
#define KB      32
#define LDA_P   40                      // padded row length in bf16 (80 B)
#define TILE_B  (128 * LDA_P * 2)       // 10240 B per tile
#define MMA_SMEM (4 * TILE_B)           // 40960 B

__global__ void __launch_bounds__(256, 2)
mma_gemm(const __nv_bfloat16* __restrict__ A0, const __nv_bfloat16* __restrict__ A1,
         const __nv_bfloat16* __restrict__ B0, const __nv_bfloat16* __restrict__ B1,
         int mode, const float* __restrict__ bias, float* __restrict__ out) {
    extern __shared__ __align__(16) char smem[];
    const uint32_t smb = (uint32_t)__cvta_generic_to_shared(smem);
    const int tid = threadIdx.x;
    const int wid = tid >> 5, lane = tid & 31;
    const int gid = lane >> 2, tig = lane & 3;
    const int wr = wid >> 2, wc = wid & 3;        // warp grid 2 x 4
    const int m0 = blockIdx.y * 128;
    const int n0 = blockIdx.x * 128;

    // ldmatrix per-lane row/col components
    const int lr = lane & 7;
    const int aro = lr + ((lane >> 3) & 1) * 8;   // a-frag row
    const int aco = (lane >> 4) * 16;             // a-frag byte col
    const int bro = lr + (lane >> 4) * 8;         // b-frag row
    const int bco = ((lane >> 3) & 1) * 16;       // b-frag byte col

    const __nv_bfloat16* Asrc[2] = {A0, A1};
    const __nv_bfloat16* Bsrc[2] = {B0, B1};

    float acc[4][4][4];
    #pragma unroll
    for (int i = 0; i < 4; i++)
        #pragma unroll
        for (int j = 0; j < 4; j++)
            #pragma unroll
            for (int r = 0; r < 4; r++) acc[i][j][r] = 0.f;

    for (int kb = 0; kb < 24; kb++) {
        const int kcol = kb * KB;
        __syncthreads();
        #pragma unroll
        for (int s = 0; s < 2; s++) {
            const __nv_bfloat16* Ag = Asrc[s];
            const __nv_bfloat16* Bg = Bsrc[s];
            #pragma unroll
            for (int q = 0; q < 2; q++) {
                int idx = tid * 2 + q;                // 0..511
                int r = idx >> 2, c4 = idx & 3;
                int gm = m0 + r;
                uint4 va = (gm < M_TOT)
                    ? *(const uint4*)(Ag + (long)gm * C_ + kcol + c4 * 8)
                    : make_uint4(0, 0, 0, 0);
                *(uint4*)(smem + s * TILE_B + r * 80 + c4 * 16) = va;
                uint4 vb = *(const uint4*)(Bg + (long)(n0 + r) * C_ + kcol + c4 * 8);
                *(uint4*)(smem + (2 + s) * TILE_B + r * 80 + c4 * 16) = vb;
            }
        }
        __syncthreads();

        #pragma unroll
        for (int ks = 0; ks < 2; ks++) {
            #pragma unroll
            for (int sa = 0; sa < 2; sa++) {
                uint32_t af[4][4];
                #pragma unroll
                for (int i = 0; i < 4; i++)
                    ldsm4(af[i], smb + sa * TILE_B +
                          (uint32_t)((wr * 64 + i * 16 + aro) * 80 + ks * 32 + aco));
                #pragma unroll
                for (int sb = 0; sb < 2 - sa; sb++) {   // (0,0),(0,1),(1,0)
                    uint32_t bf[4][2], r4[4];
                    ldsm4(r4, smb + (2 + sb) * TILE_B +
                          (uint32_t)((wc * 32 + bro) * 80 + ks * 32 + bco));
                    bf[0][0] = r4[0]; bf[0][1] = r4[1];
                    bf[1][0] = r4[2]; bf[1][1] = r4[3];
                    ldsm4(r4, smb + (2 + sb) * TILE_B +
                          (uint32_t)((wc * 32 + 16 + bro) * 80 + ks * 32 + bco));
                    bf[2][0] = r4[0]; bf[2][1] = r4[1];
                    bf[3][0] = r4[2]; bf[3][1] = r4[3];
                    #pragma unroll
                    for (int i = 0; i < 4; i++)
                        #pragma unroll
                        for (int j = 0; j < 4; j++)
                            mma16816(acc[i][j], af[i][0], af[i][1], af[i][2],
                                     af[i][3], bf[j][0], bf[j][1]);
                }
            }
        }
    }

    // ---------------- epilogue ----------------
    #pragma unroll
    for (int i = 0; i < 4; i++) {
        #pragma unroll
        for (int half = 0; half < 2; half++) {
            int gm = m0 + wr * 64 + i * 16 + gid + half * 8;
            if (gm >= M_TOT) continue;
            int btok = gm / N_, nt = gm % N_;
            #pragma unroll
            for (int j = 0; j < 4; j++) {
                float v0 = acc[i][j][half * 2];
                float v1 = acc[i][j][half * 2 + 1];
                int jg = n0 + wc * 32 + j * 8 + tig * 2;
                if (mode == 0) {
                    int qkv_i = jg / C_;
                    int rem = jg % C_;
                    int h = rem >> 6, d0 = rem & 63;
                    __nv_bfloat16* dh = (qkv_i == 0) ? g_qs[0]
                                        : (qkv_i == 1 ? g_ks[0] : g_vs[0]);
                    __nv_bfloat16* dl = (qkv_i == 0) ? g_qs[1]
                                        : (qkv_i == 1 ? g_ks[1] : g_vs[1]);
                    long base = ((long)(btok * H_ + h) * N_ + nt) * 64 + d0;
                    uint32_t hi, lo;
                    split_pack(v0, v1, hi, lo);
                    *(uint32_t*)&dh[base] = hi;
                    *(uint32_t*)&dl[base] = lo;
                } else {
                    long base = OFF_OUT + (long)gm * C_ + jg;
                    *(float2*)&out[base] = make_float2(v0 + bias[jg], v1 + bias[jg + 1]);
                }
            }
        }
    }
}

// ======================================================================
// mma.sync flash attention on pre-split bf16 q/k/v, ldmatrix fragments,
// CSA mask, per-warp masked-tile skip. CTA = 128 q-rows x (b,h).
// SMEM rows padded to 72 bf16 (144 B) -> conflict-free ldmatrix.
// ======================================================================
#define AP 36                            // words per padded 64-col bf16 row
#define ATTN_SMEM2 (2 * 128 * AP * 4)    // 36864 B (both phases fit)
#define K0B 0
#define K1B 9216
#define V0B 18432
#define V1B 27648

__global__ void __launch_bounds__(256)
attn_mma() {
    extern __shared__ __align__(16) uint32_t asw[];
    const uint32_t smb = (uint32_t)__cvta_generic_to_shared(asw);
    const int tid = threadIdx.x;
    const int wid = tid >> 5, lane = tid & 31;
    const int gid = lane >> 2, tig = lane & 3;
    const int bh = blockIdx.y;
    const int q0g = blockIdx.x * 128;

    const int lr = lane & 7;
    const int aro = lr + ((lane >> 3) & 1) * 8;
    const int aco = (lane >> 4) * 16;
    const int bro = lr + (lane >> 4) * 8;
    const int bco = ((lane >> 3) & 1) * 16;

    const __nv_bfloat16* Qh = g_qs[0] + (long)bh * N_ * 64;
    const __nv_bfloat16* Ql = g_qs[1] + (long)bh * N_ * 64;
    const __nv_bfloat16* Kh = g_ks[0] + (long)bh * N_ * 64;
    const __nv_bfloat16* Kl = g_ks[1] + (long)bh * N_ * 64;
    const __nv_bfloat16* Vh = g_vs[0] + (long)bh * N_ * 64;
    const __nv_bfloat16* Vl = g_vs[1] + (long)bh * N_ * 64;

    // ---- phase A: stage Q splits (bf16 copies), extract fragments ----
    {
        __nv_bfloat16* Q0 = (__nv_bfloat16*)asw;
        __nv_bfloat16* Q1 = (__nv_bfloat16*)((char*)asw + V0B);
        for (int idx = tid; idx < 128 * 8; idx += 256) {
            int r = idx >> 3, c = idx & 7;
            int qi = q0g + r;
            uint4 vh = make_uint4(0, 0, 0, 0), vl = vh;
            if (qi < N_) {
                vh = *(const uint4*)(Qh + (long)qi * 64 + c * 8);
                vl = *(const uint4*)(Ql + (long)qi * 64 + c * 8);
            }
            *(uint4*)(Q0 + r * 72 + c * 8) = vh;
            *(uint4*)(Q1 + r * 72 + c * 8) = vl;
        }
    }
    __syncthreads();
    uint32_t qf[2][4][4];
    #pragma unroll
    for (int ks = 0; ks < 4; ks++) {
        uint32_t off = (uint32_t)((wid * 16 + aro) * 144 + ks * 32 + aco);
        ldsm4(qf[0][ks], smb + off);
        ldsm4(qf[1][ks], smb + V0B + off);
    }
    __syncthreads();

    float accD[8][4];
    #pragma unroll
    for (int dt = 0; dt < 8; dt++)
        #pragma unroll
        for (int r = 0; r < 4; r++) accD[dt][r] = 0.f;
    float m2[2] = {-INFINITY, -INFINITY};
    float l2[2] = {0.f, 0.f};

    // per-warp q-block uniformity (rows wid*16 .. +15)
    const int rlo = q0g + wid * 16;
    bool w_dead = (rlo >= N_);
    bool wq_uni = false; int wqb = -2;
    if (!w_dead && rlo >= 1) {
        int rhi = min(rlo + 15, N_ - 1);
        int b0 = (rlo - 1) >> 8, b1 = (rhi - 1) >> 8;
        if (b0 == b1 && b0 < 4) { wq_uni = true; wqb = b0; }
    }

    for (int kt = 0; kt < 17; kt++) {
        const int k0g = kt * 64;
        __syncthreads();
        // stage K splits (row copy) and V splits (transposed)
        {
            __nv_bfloat16* Ks0 = (__nv_bfloat16*)((char*)asw + K0B);
            __nv_bfloat16* Ks1 = (__nv_bfloat16*)((char*)asw + K1B);
            __nv_bfloat16* Vt0 = (__nv_bfloat16*)((char*)asw + V0B);
            __nv_bfloat16* Vt1 = (__nv_bfloat16*)((char*)asw + V1B);
            for (int idx = tid; idx < 512; idx += 256) {
                int r = idx >> 3, c = idx & 7;
                int kj = k0g + r;
                uint4 z = make_uint4(0, 0, 0, 0);
                uint4 kh = z, kl = z, vh = z, vl = z;
                if (kj < N_) {
                    kh = *(const uint4*)(Kh + (long)kj * 64 + c * 8);
                    kl = *(const uint4*)(Kl + (long)kj * 64 + c * 8);
                    vh = *(const uint4*)(Vh + (long)kj * 64 + c * 8);
                    vl = *(const uint4*)(Vl + (long)kj * 64 + c * 8);
                }
                *(uint4*)(Ks0 + r * 72 + c * 8) = kh;
                *(uint4*)(Ks1 + r * 72 + c * 8) = kl;
                const __nv_bfloat16* ph = (const __nv_bfloat16*)&vh;
                const __nv_bfloat16* pl = (const __nv_bfloat16*)&vl;
                #pragma unroll
                for (int e = 0; e < 8; e++) {
                    Vt0[(c * 8 + e) * 72 + r] = ph[e];
                    Vt1[(c * 8 + e) * 72 + r] = pl[e];
                }
            }
        }
        __syncthreads();

        bool skip = w_dead;
        if (!skip && wq_uni && k0g >= 64) {
            int khi = min(k0g + 63, N_ - 1);
            int kb0 = (k0g - 1) >> 8, kb1 = (khi - 1) >> 8;
            if (kb0 == kb1 && kb0 == wqb) skip = true;
        }
        if (skip) continue;

        // ---- S = Q K^T (3 products), ldmatrix K fragments ----
        float sp[8][4];
        #pragma unroll
        for (int nt = 0; nt < 8; nt++)
            #pragma unroll
            for (int r = 0; r < 4; r++) sp[nt][r] = 0.f;

        #pragma unroll
        for (int ks = 0; ks < 4; ks++) {
            #pragma unroll
            for (int ntp = 0; ntp < 4; ntp++) {
                uint32_t rowb = (uint32_t)((ntp * 16 + bro) * 144 + ks * 32 + bco);
                uint32_t h4[4], l4[4];
                ldsm4(h4, smb + K0B + rowb);
                ldsm4(l4, smb + K1B + rowb);
                mma16816(sp[2*ntp], qf[0][ks][0], qf[0][ks][1], qf[0][ks][2],
                         qf[0][ks][3], h4[0], h4[1]);
                mma16816(sp[2*ntp], qf[1][ks][0], qf[1][ks][1], qf[1][ks][2],
                         qf[1][ks][3], h4[0], h4[1]);
                mma16816(sp[2*ntp], qf[0][ks][0], qf[0][ks][1], qf[0][ks][2],
                         qf[0][ks][3], l4[0], l4[1]);
                mma16816(sp[2*ntp+1], qf[0][ks][0], qf[0][ks][1], qf[0][ks][2],
                         qf[0][ks][3], h4[2], h4[3]);
                mma16816(sp[2*ntp+1], qf[1][ks][0], qf[1][ks][1], qf[1][ks][2],
                         qf[1][ks][3], h4[2], h4[3]);
                mma16816(sp[2*ntp+1], qf[0][ks][0], qf[0][ks][1], qf[0][ks][2],
                         qf[0][ks][3], l4[2], l4[3]);
            }
        }

        // ---- scale + CSA mask ----
        #pragma unroll
        for (int nt = 0; nt < 8; nt++) {
            #pragma unroll
            for (int c = 0; c < 4; c++) {
                int row = rlo + gid + ((c >= 2) ? 8 : 0);
                int key = k0g + nt * 8 + 2 * tig + (c & 1);
                float s = sp[nt][c] * SCALEF;
                int qb = (row >= 1 && row < N_) ? ((row - 1) >> 8) : -1;
                bool bad = (key >= N_) ||
                           (qb >= 0 && key >= 1 && ((key - 1) >> 8) == qb);
                sp[nt][c] = bad ? -INFINITY : s;
            }
        }

        // ---- online softmax (per half: rows gid, gid+8) ----
        #pragma unroll
        for (int half = 0; half < 2; half++) {
            float mx = -INFINITY;
            #pragma unroll
            for (int nt = 0; nt < 8; nt++)
                mx = fmaxf(mx, fmaxf(sp[nt][half*2], sp[nt][half*2+1]));
            mx = fmaxf(mx, __shfl_xor_sync(0xffffffffu, mx, 1));
            mx = fmaxf(mx, __shfl_xor_sync(0xffffffffu, mx, 2));
            float mnew = fmaxf(m2[half], mx);
            float corr = __expf(m2[half] - mnew);
            m2[half] = mnew;
            float rs = 0.f;
            #pragma unroll
            for (int nt = 0; nt < 8; nt++) {
                float p0 = __expf(sp[nt][half*2]   - mnew);
                float p1 = __expf(sp[nt][half*2+1] - mnew);
                sp[nt][half*2] = p0; sp[nt][half*2+1] = p1;
                rs += p0 + p1;
            }
            rs += __shfl_xor_sync(0xffffffffu, rs, 1);
            rs += __shfl_xor_sync(0xffffffffu, rs, 2);
            l2[half] = l2[half] * corr + rs;
            #pragma unroll
            for (int dt = 0; dt < 8; dt++) {
                accD[dt][half*2]   *= corr;
                accD[dt][half*2+1] *= corr;
            }
        }

        // ---- O += P V (3 products), ldmatrix V fragments ----
        #pragma unroll
        for (int ks = 0; ks < 4; ks++) {
            uint32_t p0[4], p1[4];
            split_pack(sp[2*ks][0],   sp[2*ks][1],   p0[0], p1[0]);
            split_pack(sp[2*ks][2],   sp[2*ks][3],   p0[1], p1[1]);
            split_pack(sp[2*ks+1][0], sp[2*ks+1][1], p0[2], p1[2]);
            split_pack(sp[2*ks+1][2], sp[2*ks+1][3], p0[3], p1[3]);
            #pragma unroll
            for (int dtp = 0; dtp < 4; dtp++) {
                uint32_t rowb = (uint32_t)((dtp * 16 + bro) * 144 + ks * 32 + bco);
                uint32_t h4[4], l4[4];
                ldsm4(h4, smb + V0B + rowb);
                ldsm4(l4, smb + V1B + rowb);
                mma16816(accD[2*dtp], p0[0], p0[1], p0[2], p0[3], h4[0], h4[1]);
                mma16816(accD[2*dtp], p1[0], p1[1], p1[2], p1[3], h4[0], h4[1]);
                mma16816(accD[2*dtp], p0[0], p0[1], p0[2], p0[3], l4[0], l4[1]);
                mma16816(accD[2*dtp+1], p0[0], p0[1], p0[2], p0[3], h4[2], h4[3]);
                mma16816(accD[2*dtp+1], p1[0], p1[1], p1[2], p1[3], h4[2], h4[3]);
                mma16816(accD[2*dtp+1], p0[0], p0[1], p0[2], p0[3], l4[2], l4[3]);
            }
        }
    }

    // ---- epilogue ----
    const int b = bh / H_, h = bh % H_;
    #pragma unroll
    for (int half = 0; half < 2; half++) {
        int row = rlo + gid + half * 8;
        if (row < N_) {
            float inv = 1.f / l2[half];
            #pragma unroll
            for (int dt = 0; dt < 8; dt++) {
                int d = dt * 8 + 2 * tig;
                long base = ((long)b * N_ + row) * C_ + h * 64 + d;
                g_ctx[base]     = accD[dt][half*2]   * inv;
                g_ctx[base + 1] = accD[dt][half*2+1] * inv;
            }
        }
    }
}

// ======================================================================
// cls per-head softmax row -- GEMM-independent (raw inputs), high precision.
// ======================================================================
__global__ void __launch_bounds__(1024)
cls_head_kernel(const float* __restrict__ x, const float* __restrict__ w) {
    __shared__ double q0s[64];
    __shared__ float uhi[C_], ulo[C_];
    __shared__ double s[N_];
    __shared__ double red[32];
    const int bh = blockIdx.x;
    const int b = bh / H_, h = bh % H_;
    const int tid = threadIdx.x;
    const int wid = tid >> 5, lane = tid & 31;

    const float* xb = x + (long)b * N_ * C_;
    const float* wq = w + (long)(h * 64) * C_;
    const float* wk = w + (long)(C_ + h * 64) * C_;

    for (int d = wid; d < 64; d += 32) {
        double a = 0.0;
        for (int c = lane; c < C_; c += 32)
            a += (double)xb[c] * (double)wq[(long)d * C_ + c];
        #pragma unroll
        for (int o = 16; o >= 1; o >>= 1)
            a += __shfl_xor_sync(0xffffffffu, a, o);
        if (lane == 0) q0s[d] = a;
    }
    __syncthreads();

    for (int c = tid; c < C_; c += 1024) {
        double a = 0.0;
        #pragma unroll 8
        for (int d = 0; d < 64; d++)
            a += q0s[d] * (double)wk[(long)d * C_ + c];
        a *= 0.125;
        float hi = (float)a;
        uhi[c] = hi;
        ulo[c] = (float)(a - (double)hi);
    }
    __syncthreads();

    for (int j = wid; j < N_; j += 32) {
        const float* xr = xb + (long)j * C_;
        float sum = 0.f, comp = 0.f, err = 0.f;
        #pragma unroll 2
        for (int c = lane * 4; c < C_; c += 128) {
            float4 xv = *(const float4*)&xr[c];
            float4 uh = *(const float4*)&uhi[c];
            float4 ul = *(const float4*)&ulo[c];
            #pragma unroll
            for (int e4 = 0; e4 < 4; e4++) {
                float xe = (&xv.x)[e4], he = (&uh.x)[e4], le = (&ul.x)[e4];
                float p = he * xe;
                err = fmaf(he, xe, -p) + err;
                err = fmaf(le, xe, err);
                float y = p - comp;
                float t = sum + y;
                comp = (t - sum) - y;
                sum = t;
            }
        }
        double tot = ((double)sum - (double)comp) + (double)err;
        #pragma unroll
        for (int o = 16; o >= 1; o >>= 1)
            tot += __shfl_xor_sync(0xffffffffu, tot, o);
        if (lane == 0) s[j] = tot;
    }
    __syncthreads();

    double lm = -1e300;
    for (int j = tid; j < N_; j += 1024) lm = fmax(lm, s[j]);
    #pragma unroll
    for (int o = 16; o >= 1; o >>= 1)
        lm = fmax(lm, __shfl_xor_sync(0xffffffffu, lm, o));
    if (lane == 0) red[wid] = lm;
    __syncthreads();
    if (wid == 0) {
        double t = red[lane];
        #pragma unroll
        for (int o = 16; o >= 1; o >>= 1)
            t = fmax(t, __shfl_xor_sync(0xffffffffu, t, o));
        if (lane == 0) red[0] = t;
    }
    __syncthreads();
    const double m = red[0];
    __syncthreads();

    double ls = 0.0;
    for (int j = tid; j < N_; j += 1024) {
        double e = exp(s[j] - m);
        s[j] = e;
        ls += e;
    }
    #pragma unroll
    for (int o = 16; o >= 1; o >>= 1)
        ls += __shfl_xor_sync(0xffffffffu, ls, o);
    if (lane == 0) red[wid] = ls;
    __syncthreads();
    if (wid == 0) {
        double t = red[lane];
        #pragma unroll
        for (int o = 16; o >= 1; o >>= 1)
            t += __shfl_xor_sync(0xffffffffu, t, o);
        if (lane == 0) red[0] = t;
    }
    __syncthreads();
    const double inv = 1.0 / red[0];

    for (int j = tid; j < N_ - 1; j += 1024)
        g_cls_ph[bh][j] = s[j + 1] * inv;
}

// ======================================================================
// head-mean reduce (fp64, h-ascending). One CTA per batch.
// ======================================================================
__global__ void cls_reduce_kernel(float* __restrict__ out) {
    const int b = blockIdx.x, tid = threadIdx.x;
    for (int j = tid; j < N_ - 1; j += 256) {
        double a = 0.0;
        #pragma unroll
        for (int h = 0; h < H_; h++)
            a += g_cls_ph[b * H_ + h][j] * (1.0 / 12.0);
        g_clsd[b * (N_ - 1) + j] = a;
        out[OFF_CLS + (long)b * (N_ - 1) + j] = (float)a;
    }
}

// ======================================================================
// dual bitonic top-k (103 of 1024) on fp64 keys, jax tie-break.
// ======================================================================
__global__ void sort_kernel(float* __restrict__ out) {
    __shared__ double v[1024];
    __shared__ int ix[1024];
    const int b = blockIdx.x, tid = threadIdx.x;

    for (int pass = 0; pass < 2; pass++) {
        __syncthreads();
        for (int i = tid; i < 1024; i += 512) {
            v[i] = g_clsd[b * 1024 + i];
            ix[i] = i;
        }
        __syncthreads();
        const bool desc = (pass == 0);
        for (int k = 2; k <= 1024; k <<= 1) {
            for (int j = k >> 1; j > 0; j >>= 1) {
                for (int i = tid; i < 1024; i += 512) {
                    int p = i ^ j;
                    if (p > i) {
                        double va = v[i], vb = v[p];
                        int ia = ix[i], ib = ix[p];
                        bool ab = desc ? (va > vb || (va == vb && ia < ib))
                                       : (va < vb || (va == vb && ia < ib));
                        bool up = ((i & k) == 0);
                        if (up ? !ab : ab) {
                            v[i] = vb; v[p] = va;
                            ix[i] = ib; ix[p] = ia;
                        }
                    }
                }
                __syncthreads();
            }
        }
        const long offIdx = desc ? OFF_ENH_IDX : OFF_FUSE_IDX;
        const long offBrd = desc ? OFF_ENH_INDEX : OFF_FUSE_INDEX;
        for (int t = tid; t < TOPT; t += 512)
            out[offIdx + (long)b * TOPT + t] = (float)ix[t];
        for (int e = tid; e < TOPT * C_; e += 512) {
            int t = e / C_;
            out[offBrd + ((long)b * TOPT + t) * C_ + (e % C_)] = (float)ix[t];
        }
    }
}

// ======================================================================
// Launch
// ======================================================================
extern "C" void kernel_launch(void* const* d_in, const int* in_sizes, int n_in,
                              void* d_out, int out_size) {
    const float* x     = (const float*)d_in[0];
    const float* w_qkv = (const float*)d_in[1];
    const float* w_out = (const float*)d_in[2];
    const float* b_out = (const float*)d_in[3];
    float* out = (float*)d_out;

    cudaFuncSetAttribute(mma_gemm, cudaFuncAttributeMaxDynamicSharedMemorySize,
                         MMA_SMEM);
    cudaFuncSetAttribute(attn_mma, cudaFuncAttributeMaxDynamicSharedMemorySize,
                         ATTN_SMEM2);

    __nv_bfloat16 *xs0, *xs1, *ws0, *ws1, *wo0, *wo1, *cs0, *cs1;
    cudaGetSymbolAddress((void**)&xs0, g_xs); xs1 = xs0 + (long)M_TOT*C_;
    cudaGetSymbolAddress((void**)&ws0, g_ws); ws1 = ws0 + (long)3*C_*C_;
    cudaGetSymbolAddress((void**)&wo0, g_wo); wo1 = wo0 + (long)C_*C_;
    cudaGetSymbolAddress((void**)&cs0, g_cs); cs1 = cs0 + (long)M_TOT*C_;
    float* ctxp; cudaGetSymbolAddress((void**)&ctxp, g_ctx);

    split2<<<(M_TOT*C_ + 255)/256, 256>>>(x, xs0, xs1, M_TOT*C_);
    split2<<<(3*C_*C_ + 255)/256, 256>>>(w_qkv, ws0, ws1, 3*C_*C_);
    split2<<<(C_*C_ + 255)/256, 256>>>(w_out, wo0, wo1, C_*C_);

    // QKV: [4100,2304] = x @ w_qkv^T, writes bf16 q/k/v splits directly
    mma_gemm<<<dim3(3*C_/128, (M_TOT + 127)/128), 256, MMA_SMEM>>>(
        xs0, xs1, ws0, ws1, 0, b_out, out);

    // attention (tensor cores, ldmatrix, pre-split operands)
    attn_mma<<<dim3((N_ + 127)/128, B_ * H_), 256, ATTN_SMEM2>>>();

    split2<<<(M_TOT*C_ + 255)/256, 256>>>(ctxp, cs0, cs1, M_TOT*C_);

    // OUT: [4100,768] = ctx @ w_out^T + bias
    mma_gemm<<<dim3(C_/128, (M_TOT + 127)/128), 256, MMA_SMEM>>>(
        cs0, cs1, wo0, wo1, 1, b_out, out);

    // cls path: high-precision from raw inputs (GEMM-independent)
    cls_head_kernel<<<B_ * H_, 1024>>>(x, w_qkv);
    cls_reduce_kernel<<<B_, 256>>>(out);
    sort_kernel<<<B_, 512>>>(out);
}

// round 11
// speedup vs baseline: 2.4098x; 1.0837x over previous
#include <cuda_runtime.h>
#include <cuda_bf16.h>
#include <math.h>
#include <cstdint>

// ---------------- Problem constants ----------------
#define B_ 4
#define N_ 1025
#define C_ 768
#define H_ 12
#define D_ 64
#define TOPT 103
#define SCALEF 0.125f            // 64^-0.5

#define M_TOT (B_ * N_)          // 4100

// Output layout (float32, reference tuple flattened & concatenated):
#define OFF_OUT        0L
#define OFF_ENH_INDEX  3148800L
#define OFF_ENH_IDX    3465216L
#define OFF_FUSE_INDEX 3465628L
#define OFF_FUSE_IDX   3782044L
#define OFF_CLS        3782456L

// ---------------- Scratch (no allocation allowed) ----------------
__device__ float  g_ctx[B_*N_*C_];      // [b,n,h*64+d]
__device__ double g_clsd[B_*(N_-1)];
__device__ double g_cls_ph[B_*H_][N_-1];

// bf16 2-way splits
__device__ __nv_bfloat16 g_xs[2][M_TOT*C_];
__device__ __nv_bfloat16 g_ws[2][3*C_*C_];     // w_qkv [2304,768]
__device__ __nv_bfloat16 g_wo[2][C_*C_];       // w_out [768,768]
__device__ __nv_bfloat16 g_cs[2][M_TOT*C_];    // ctx splits
// q/k/v as bf16 splits, [b,h,n,d] (written directly by QKV GEMM epilogue)
__device__ __nv_bfloat16 g_qs[2][B_*H_*N_*D_];
__device__ __nv_bfloat16 g_ks[2][B_*H_*N_*D_];
__device__ __nv_bfloat16 g_vs[2][B_*H_*N_*D_];

// ================= helpers =================
__device__ __forceinline__ void ldsm4(uint32_t* r, uint32_t addr) {
    asm volatile("ldmatrix.sync.aligned.m8n8.x4.shared.b16 {%0,%1,%2,%3}, [%4];"
        : "=r"(r[0]), "=r"(r[1]), "=r"(r[2]), "=r"(r[3]) : "r"(addr));
}
__device__ __forceinline__ void ldsm4t(uint32_t* r, uint32_t addr) {
    asm volatile("ldmatrix.sync.aligned.m8n8.x4.trans.shared.b16 {%0,%1,%2,%3}, [%4];"
        : "=r"(r[0]), "=r"(r[1]), "=r"(r[2]), "=r"(r[3]) : "r"(addr));
}
__device__ __forceinline__ void mma16816(float c[4], uint32_t a0, uint32_t a1,
                                         uint32_t a2, uint32_t a3,
                                         uint32_t b0, uint32_t b1) {
    asm volatile(
        "mma.sync.aligned.m16n8k16.row.col.f32.bf16.bf16.f32 "
        "{%0,%1,%2,%3}, {%4,%5,%6,%7}, {%8,%9}, {%0,%1,%2,%3};"
        : "+f"(c[0]), "+f"(c[1]), "+f"(c[2]), "+f"(c[3])
        : "r"(a0), "r"(a1), "r"(a2), "r"(a3), "r"(b0), "r"(b1));
}
__device__ __forceinline__ void cpa16(uint32_t dst, const void* src, int sz) {
    asm volatile("cp.async.cg.shared.global [%0], [%1], 16, %2;"
        :: "r"(dst), "l"(src), "r"(sz));
}
#define CP_COMMIT() asm volatile("cp.async.commit_group;" ::: "memory")
#define CP_WAIT1()  asm volatile("cp.async.wait_group 1;" ::: "memory")
__device__ __forceinline__ void split_pack(float x, float y,
                                           uint32_t& hi, uint32_t& lo) {
    __nv_bfloat16 x0 = __float2bfloat16(x);
    __nv_bfloat16 y0 = __float2bfloat16(y);
    __nv_bfloat16 x1 = __float2bfloat16(x - __bfloat162float(x0));
    __nv_bfloat16 y1 = __float2bfloat16(y - __bfloat162float(y0));
    __nv_bfloat162 h; h.x = x0; h.y = y0;
    __nv_bfloat162 l; l.x = x1; l.y = y1;
    hi = *(uint32_t*)&h; lo = *(uint32_t*)&l;
}

// ======================================================================
// Split kernel: fp32 -> 2 bf16 splits (residual ~2^-16)
// ======================================================================
__global__ void split2(const float* __restrict__ src,
                       __nv_bfloat16* __restrict__ d0,
                       __nv_bfloat16* __restrict__ d1, int n) {
    int i = blockIdx.x * blockDim.x + threadIdx.x;
    if (i < n) {
        float x = src[i];
        __nv_bfloat16 b0 = __float2bfloat16(x);
        d0[i] = b0;
        d1[i] = __float2bfloat16(x - __bfloat162float(b0));
    }
}

// ======================================================================
// mma.sync bf16 GEMM, 2-split / 3-product, ldmatrix + cp.async double buffer.
// mode 0: write q/k/v bf16 splits; mode 1: out + bias (fp32).
// ======================================================================
#define TILE_B  (128 * 80)               // 10240 B per split tile (80B rows)
#define STAGE_G (4 * TILE_B)             // 40960 B per stage
#define MMA_SMEM (2 * STAGE_G)           // 81920 B

__global__ void __launch_bounds__(256, 2)
mma_gemm(const __nv_bfloat16* __restrict__ A0, const __nv_bfloat16* __restrict__ A1,
         const __nv_bfloat16* __restrict__ B0, const __nv_bfloat16* __restrict__ B1,
         int mode, const float* __restrict__ bias, float* __restrict__ out) {
    extern __shared__ __align__(16) char smem[];
    const uint32_t smb = (uint32_t)__cvta_generic_to_shared(smem);
    const int tid = threadIdx.x;
    const int wid = tid >> 5, lane = tid & 31;
    const int gid = lane >> 2, tig = lane & 3;
    const int wr = wid >> 2, wc = wid & 3;        // warp grid 2 x 4
    const int m0 = blockIdx.y * 128;
    const int n0 = blockIdx.x * 128;

    const int lr = lane & 7;
    const int aro = lr + ((lane >> 3) & 1) * 8;
    const int aco = (lane >> 4) * 16;
    const int bro = lr + (lane >> 4) * 8;
    const int bco = ((lane >> 3) & 1) * 16;

    const __nv_bfloat16* Asrc[2] = {A0, A1};
    const __nv_bfloat16* Bsrc[2] = {B0, B1};

    float acc[4][4][4];
    #pragma unroll
    for (int i = 0; i < 4; i++)
        #pragma unroll
        for (int j = 0; j < 4; j++)
            #pragma unroll
            for (int r = 0; r < 4; r++) acc[i][j][r] = 0.f;

    // stage kb into buffer bufi (cp.async)
    auto stageg = [&](int kb_, int bufi) {
        const int kcol = kb_ * 32;
        const uint32_t sb = smb + bufi * STAGE_G;
        #pragma unroll
        for (int t = 0; t < 8; t++) {
            int idx = tid + t * 256;                 // 0..2047
            int a = idx >> 9;                        // 0:A0 1:A1 2:B0 3:B1
            int r = (idx >> 2) & 127, c = idx & 3;
            const __nv_bfloat16* src;
            int sz = 16;
            if (a < 2) {
                src = Asrc[a] + (long)(m0 + r) * C_ + kcol + c * 8;
                if (m0 + r >= M_TOT) sz = 0;
            } else {
                src = Bsrc[a - 2] + (long)(n0 + r) * C_ + kcol + c * 8;
            }
            cpa16(sb + a * TILE_B + r * 80 + c * 16, src, sz);
        }
    };

    stageg(0, 0);
    CP_COMMIT();

    for (int kb = 0; kb < 24; kb++) {
        __syncthreads();                 // prior compute done (buffer reuse)
        if (kb + 1 < 24) stageg(kb + 1, (kb + 1) & 1);
        CP_COMMIT();
        CP_WAIT1();                      // tile kb resident
        __syncthreads();

        const uint32_t sb = smb + (kb & 1) * STAGE_G;
        #pragma unroll
        for (int ks = 0; ks < 2; ks++) {
            #pragma unroll
            for (int sa = 0; sa < 2; sa++) {
                uint32_t af[4][4];
                #pragma unroll
                for (int i = 0; i < 4; i++)
                    ldsm4(af[i], sb + sa * TILE_B +
                          (uint32_t)((wr * 64 + i * 16 + aro) * 80 + ks * 32 + aco));
                #pragma unroll
                for (int sb2 = 0; sb2 < 2 - sa; sb2++) {   // (0,0),(0,1),(1,0)
                    uint32_t bf[4][2], r4[4];
                    ldsm4(r4, sb + (2 + sb2) * TILE_B +
                          (uint32_t)((wc * 32 + bro) * 80 + ks * 32 + bco));
                    bf[0][0] = r4[0]; bf[0][1] = r4[1];
                    bf[1][0] = r4[2]; bf[1][1] = r4[3];
                    ldsm4(r4, sb + (2 + sb2) * TILE_B +
                          (uint32_t)((wc * 32 + 16 + bro) * 80 + ks * 32 + bco));
                    bf[2][0] = r4[0]; bf[2][1] = r4[1];
                    bf[3][0] = r4[2]; bf[3][1] = r4[3];
                    #pragma unroll
                    for (int i = 0; i < 4; i++)
                        #pragma unroll
                        for (int j = 0; j < 4; j++)
                            mma16816(acc[i][j], af[i][0], af[i][1], af[i][2],
                                     af[i][3], bf[j][0], bf[j][1]);
                }
            }
        }
    }

    // ---------------- epilogue ----------------
    #pragma unroll
    for (int i = 0; i < 4; i++) {
        #pragma unroll
        for (int half = 0; half < 2; half++) {
            int gm = m0 + wr * 64 + i * 16 + gid + half * 8;
            if (gm >= M_TOT) continue;
            int btok = gm / N_, nt = gm % N_;
            #pragma unroll
            for (int j = 0; j < 4; j++) {
                float v0 = acc[i][j][half * 2];
                float v1 = acc[i][j][half * 2 + 1];
                int jg = n0 + wc * 32 + j * 8 + tig * 2;
                if (mode == 0) {
                    int qkv_i = jg / C_;
                    int rem = jg % C_;
                    int h = rem >> 6, d0 = rem & 63;
                    __nv_bfloat16* dh = (qkv_i == 0) ? g_qs[0]
                                        : (qkv_i == 1 ? g_ks[0] : g_vs[0]);
                    __nv_bfloat16* dl = (qkv_i == 0) ? g_qs[1]
                                        : (qkv_i == 1 ? g_ks[1] : g_vs[1]);
                    long base = ((long)(btok * H_ + h) * N_ + nt) * 64 + d0;
                    uint32_t hi, lo;
                    split_pack(v0, v1, hi, lo);
                    *(uint32_t*)&dh[base] = hi;
                    *(uint32_t*)&dl[base] = lo;
                } else {
                    long base = OFF_OUT + (long)gm * C_ + jg;
                    *(float2*)&out[base] = make_float2(v0 + bias[jg], v1 + bias[jg + 1]);
                }
            }
        }
    }
}

// ======================================================================
// mma.sync flash attention, pre-split bf16 q/k/v, ldmatrix (+trans for V),
// cp.async double-buffered K/V staging, CSA mask, per-warp tile skip.
// CTA = 128 q-rows x (b,h). SMEM rows padded to 144 B (conflict-free LDSM).
// Stage layout: K0 @0, K1 @9216, V0 @18432, V1 @27648 (each 64x144B).
// ======================================================================
#define TILE_A  9216
#define STAGE_A (4 * TILE_A)             // 36864 B per stage
#define ATTN_SMEM2 (2 * STAGE_A)         // 73728 B

__global__ void __launch_bounds__(256)
attn_mma() {
    extern __shared__ __align__(16) uint32_t asw[];
    const uint32_t smb = (uint32_t)__cvta_generic_to_shared(asw);
    const int tid = threadIdx.x;
    const int wid = tid >> 5, lane = tid & 31;
    const int gid = lane >> 2, tig = lane & 3;
    const int bh = blockIdx.y;
    const int q0g = blockIdx.x * 128;

    const int lr = lane & 7;
    const int aro = lr + ((lane >> 3) & 1) * 8;
    const int aco = (lane >> 4) * 16;
    const int bro = lr + (lane >> 4) * 8;
    const int bco = ((lane >> 3) & 1) * 16;
    const int vro = lr + ((lane >> 3) & 1) * 8;   // trans: k-row component
    const int vco = (lane >> 4) * 16;             // trans: d byte component

    const __nv_bfloat16* Qh = g_qs[0] + (long)bh * N_ * 64;
    const __nv_bfloat16* Ql = g_qs[1] + (long)bh * N_ * 64;
    const __nv_bfloat16* Kh = g_ks[0] + (long)bh * N_ * 64;
    const __nv_bfloat16* Kl = g_ks[1] + (long)bh * N_ * 64;
    const __nv_bfloat16* Vh = g_vs[0] + (long)bh * N_ * 64;
    const __nv_bfloat16* Vl = g_vs[1] + (long)bh * N_ * 64;

    // ---- phase A: stage Q splits into stage 0, extract fragments ----
    {
        __nv_bfloat16* Q0 = (__nv_bfloat16*)asw;
        __nv_bfloat16* Q1 = (__nv_bfloat16*)((char*)asw + STAGE_A);
        for (int idx = tid; idx < 128 * 8; idx += 256) {
            int r = idx >> 3, c = idx & 7;
            int qi = q0g + r;
            uint4 vh = make_uint4(0, 0, 0, 0), vl = vh;
            if (qi < N_) {
                vh = *(const uint4*)(Qh + (long)qi * 64 + c * 8);
                vl = *(const uint4*)(Ql + (long)qi * 64 + c * 8);
            }
            *(uint4*)(Q0 + r * 72 + c * 8) = vh;
            *(uint4*)(Q1 + r * 72 + c * 8) = vl;
        }
    }
    __syncthreads();
    uint32_t qf[2][4][4];
    #pragma unroll
    for (int ks = 0; ks < 4; ks++) {
        uint32_t off = (uint32_t)((wid * 16 + aro) * 144 + ks * 32 + aco);
        ldsm4(qf[0][ks], smb + off);
        ldsm4(qf[1][ks], smb + STAGE_A + off);
    }
    __syncthreads();

    float accD[8][4];
    #pragma unroll
    for (int dt = 0; dt < 8; dt++)
        #pragma unroll
        for (int r = 0; r < 4; r++) accD[dt][r] = 0.f;
    float m2[2] = {-INFINITY, -INFINITY};
    float l2[2] = {0.f, 0.f};

    // per-warp q-block uniformity (rows wid*16 .. +15)
    const int rlo = q0g + wid * 16;
    bool w_dead = (rlo >= N_);
    bool wq_uni = false; int wqb = -2;
    if (!w_dead && rlo >= 1) {
        int rhi = min(rlo + 15, N_ - 1);
        int b0 = (rlo - 1) >> 8, b1 = (rhi - 1) >> 8;
        if (b0 == b1 && b0 < 4) { wq_uni = true; wqb = b0; }
    }

    // cp.async stage of K/V splits (row-major, no transpose)
    auto stagea = [&](int kt_, int bufi) {
        const int k0 = kt_ * 64;
        const uint32_t sb = smb + bufi * STAGE_A;
        const __nv_bfloat16* srcs[4] = {Kh, Kl, Vh, Vl};
        #pragma unroll
        for (int t = 0; t < 8; t++) {
            int idx = tid + t * 256;                 // 0..2047
            int a = idx >> 9, r = (idx >> 3) & 63, c = idx & 7;
            int kj = k0 + r;
            const __nv_bfloat16* src = srcs[a] + (long)kj * 64 + c * 8;
            cpa16(sb + a * TILE_A + r * 144 + c * 16, src, (kj < N_) ? 16 : 0);
        }
    };

    stagea(0, 0);
    CP_COMMIT();

    for (int kt = 0; kt < 17; kt++) {
        const int k0g = kt * 64;
        __syncthreads();                 // prior compute done
        if (kt + 1 < 17) stagea(kt + 1, (kt + 1) & 1);
        CP_COMMIT();
        CP_WAIT1();
        __syncthreads();

        bool skip = w_dead;
        if (!skip && wq_uni && k0g >= 64) {
            int khi = min(k0g + 63, N_ - 1);
            int kb0 = (k0g - 1) >> 8, kb1 = (khi - 1) >> 8;
            if (kb0 == kb1 && kb0 == wqb) skip = true;
        }
        if (skip) continue;

        const uint32_t sb = smb + (kt & 1) * STAGE_A;

        // ---- S = Q K^T (3 products), ldmatrix K fragments ----
        float sp[8][4];
        #pragma unroll
        for (int nt = 0; nt < 8; nt++)
            #pragma unroll
            for (int r = 0; r < 4; r++) sp[nt][r] = 0.f;

        #pragma unroll
        for (int ks = 0; ks < 4; ks++) {
            #pragma unroll
            for (int ntp = 0; ntp < 4; ntp++) {
                uint32_t rowb = (uint32_t)((ntp * 16 + bro) * 144 + ks * 32 + bco);
                uint32_t h4[4], l4[4];
                ldsm4(h4, sb + rowb);                 // K0
                ldsm4(l4, sb + TILE_A + rowb);        // K1
                mma16816(sp[2*ntp], qf[0][ks][0], qf[0][ks][1], qf[0][ks][2],
                         qf[0][ks][3], h4[0], h4[1]);
                mma16816(sp[2*ntp], qf[1][ks][0], qf[1][ks][1], qf[1][ks][2],
                         qf[1][ks][3], h4[0], h4[1]);
                mma16816(sp[2*ntp], qf[0][ks][0], qf[0][ks][1], qf[0][ks][2],
                         qf[0][ks][3], l4[0], l4[1]);
                mma16816(sp[2*ntp+1], qf[0][ks][0], qf[0][ks][1], qf[0][ks][2],
                         qf[0][ks][3], h4[2], h4[3]);
                mma16816(sp[2*ntp+1], qf[1][ks][0], qf[1][ks][1], qf[1][ks][2],
                         qf[1][ks][3], h4[2], h4[3]);
                mma16816(sp[2*ntp+1], qf[0][ks][0], qf[0][ks][1], qf[0][ks][2],
                         qf[0][ks][3], l4[2], l4[3]);
            }
        }

        // ---- scale + CSA mask ----
        #pragma unroll
        for (int nt = 0; nt < 8; nt++) {
            #pragma unroll
            for (int c = 0; c < 4; c++) {
                int row = rlo + gid + ((c >= 2) ? 8 : 0);
                int key = k0g + nt * 8 + 2 * tig + (c & 1);
                float s = sp[nt][c] * SCALEF;
                int qb = (row >= 1 && row < N_) ? ((row - 1) >> 8) : -1;
                bool bad = (key >= N_) ||
                           (qb >= 0 && key >= 1 && ((key - 1) >> 8) == qb);
                sp[nt][c] = bad ? -INFINITY : s;
            }
        }

        // ---- online softmax (per half: rows gid, gid+8) ----
        #pragma unroll
        for (int half = 0; half < 2; half++) {
            float mx = -INFINITY;
            #pragma unroll
            for (int nt = 0; nt < 8; nt++)
                mx = fmaxf(mx, fmaxf(sp[nt][half*2], sp[nt][half*2+1]));
            mx = fmaxf(mx, __shfl_xor_sync(0xffffffffu, mx, 1));
            mx = fmaxf(mx, __shfl_xor_sync(0xffffffffu, mx, 2));
            float mnew = fmaxf(m2[half], mx);
            float corr = __expf(m2[half] - mnew);
            m2[half] = mnew;
            float rs = 0.f;
            #pragma unroll
            for (int nt = 0; nt < 8; nt++) {
                float p0 = __expf(sp[nt][half*2]   - mnew);
                float p1 = __expf(sp[nt][half*2+1] - mnew);
                sp[nt][half*2] = p0; sp[nt][half*2+1] = p1;
                rs += p0 + p1;
            }
            rs += __shfl_xor_sync(0xffffffffu, rs, 1);
            rs += __shfl_xor_sync(0xffffffffu, rs, 2);
            l2[half] = l2[half] * corr + rs;
            #pragma unroll
            for (int dt = 0; dt < 8; dt++) {
                accD[dt][half*2]   *= corr;
                accD[dt][half*2+1] *= corr;
            }
        }

        // ---- O += P V (3 products), ldmatrix.trans V fragments ----
        #pragma unroll
        for (int ks = 0; ks < 4; ks++) {
            uint32_t p0[4], p1[4];
            split_pack(sp[2*ks][0],   sp[2*ks][1],   p0[0], p1[0]);
            split_pack(sp[2*ks][2],   sp[2*ks][3],   p0[1], p1[1]);
            split_pack(sp[2*ks+1][0], sp[2*ks+1][1], p0[2], p1[2]);
            split_pack(sp[2*ks+1][2], sp[2*ks+1][3], p0[3], p1[3]);
            #pragma unroll
            for (int dtp = 0; dtp < 4; dtp++) {
                uint32_t rowb = (uint32_t)((ks * 16 + vro) * 144 + dtp * 32 + vco);
                uint32_t h4[4], l4[4];
                ldsm4t(h4, sb + 2 * TILE_A + rowb);   // V0 (row-major + trans)
                ldsm4t(l4, sb + 3 * TILE_A + rowb);   // V1
                mma16816(accD[2*dtp], p0[0], p0[1], p0[2], p0[3], h4[0], h4[1]);
                mma16816(accD[2*dtp], p1[0], p1[1], p1[2], p1[3], h4[0], h4[1]);
                mma16816(accD[2*dtp], p0[0], p0[1], p0[2], p0[3], l4[0], l4[1]);
                mma16816(accD[2*dtp+1], p0[0], p0[1], p0[2], p0[3], h4[2], h4[3]);
                mma16816(accD[2*dtp+1], p1[0], p1[1], p1[2], p1[3], h4[2], h4[3]);
                mma16816(accD[2*dtp+1], p0[0], p0[1], p0[2], p0[3], l4[2], l4[3]);
            }
        }
    }

    // ---- epilogue ----
    const int b = bh / H_, h = bh % H_;
    #pragma unroll
    for (int half = 0; half < 2; half++) {
        int row = rlo + gid + half * 8;
        if (row < N_) {
            float inv = 1.f / l2[half];
            #pragma unroll
            for (int dt = 0; dt < 8; dt++) {
                int d = dt * 8 + 2 * tig;
                long base = ((long)b * N_ + row) * C_ + h * 64 + d;
                g_ctx[base]     = accD[dt][half*2]   * inv;
                g_ctx[base + 1] = accD[dt][half*2+1] * inv;
            }
        }
    }
}

// ======================================================================
// cls per-head softmax row -- GEMM-independent (raw inputs), high precision.
// ======================================================================
__global__ void __launch_bounds__(1024)
cls_head_kernel(const float* __restrict__ x, const float* __restrict__ w) {
    __shared__ double q0s[64];
    __shared__ float uhi[C_], ulo[C_];
    __shared__ double s[N_];
    __shared__ double red[32];
    const int bh = blockIdx.x;
    const int b = bh / H_, h = bh % H_;
    const int tid = threadIdx.x;
    const int wid = tid >> 5, lane = tid & 31;

    const float* xb = x + (long)b * N_ * C_;
    const float* wq = w + (long)(h * 64) * C_;
    const float* wk = w + (long)(C_ + h * 64) * C_;

    for (int d = wid; d < 64; d += 32) {
        double a = 0.0;
        for (int c = lane; c < C_; c += 32)
            a += (double)xb[c] * (double)wq[(long)d * C_ + c];
        #pragma unroll
        for (int o = 16; o >= 1; o >>= 1)
            a += __shfl_xor_sync(0xffffffffu, a, o);
        if (lane == 0) q0s[d] = a;
    }
    __syncthreads();

    for (int c = tid; c < C_; c += 1024) {
        double a = 0.0;
        #pragma unroll 8
        for (int d = 0; d < 64; d++)
            a += q0s[d] * (double)wk[(long)d * C_ + c];
        a *= 0.125;
        float hi = (float)a;
        uhi[c] = hi;
        ulo[c] = (float)(a - (double)hi);
    }
    __syncthreads();

    for (int j = wid; j < N_; j += 32) {
        const float* xr = xb + (long)j * C_;
        float sum = 0.f, comp = 0.f, err = 0.f;
        #pragma unroll 2
        for (int c = lane * 4; c < C_; c += 128) {
            float4 xv = *(const float4*)&xr[c];
            float4 uh = *(const float4*)&uhi[c];
            float4 ul = *(const float4*)&ulo[c];
            #pragma unroll
            for (int e4 = 0; e4 < 4; e4++) {
                float xe = (&xv.x)[e4], he = (&uh.x)[e4], le = (&ul.x)[e4];
                float p = he * xe;
                err = fmaf(he, xe, -p) + err;
                err = fmaf(le, xe, err);
                float y = p - comp;
                float t = sum + y;
                comp = (t - sum) - y;
                sum = t;
            }
        }
        double tot = ((double)sum - (double)comp) + (double)err;
        #pragma unroll
        for (int o = 16; o >= 1; o >>= 1)
            tot += __shfl_xor_sync(0xffffffffu, tot, o);
        if (lane == 0) s[j] = tot;
    }
    __syncthreads();

    double lm = -1e300;
    for (int j = tid; j < N_; j += 1024) lm = fmax(lm, s[j]);
    #pragma unroll
    for (int o = 16; o >= 1; o >>= 1)
        lm = fmax(lm, __shfl_xor_sync(0xffffffffu, lm, o));
    if (lane == 0) red[wid] = lm;
    __syncthreads();
    if (wid == 0) {
        double t = red[lane];
        #pragma unroll
        for (int o = 16; o >= 1; o >>= 1)
            t = fmax(t, __shfl_xor_sync(0xffffffffu, t, o));
        if (lane == 0) red[0] = t;
    }
    __syncthreads();
    const double m = red[0];
    __syncthreads();

    double ls = 0.0;
    for (int j = tid; j < N_; j += 1024) {
        double e = exp(s[j] - m);
        s[j] = e;
        ls += e;
    }
    #pragma unroll
    for (int o = 16; o >= 1; o >>= 1)
        ls += __shfl_xor_sync(0xffffffffu, ls, o);
    if (lane == 0) red[wid] = ls;
    __syncthreads();
    if (wid == 0) {
        double t = red[lane];
        #pragma unroll
        for (int o = 16; o >= 1; o >>= 1)
            t += __shfl_xor_sync(0xffffffffu, t, o);
        if (lane == 0) red[0] = t;
    }
    __syncthreads();
    const double inv = 1.0 / red[0];

    for (int j = tid; j < N_ - 1; j += 1024)
        g_cls_ph[bh][j] = s[j + 1] * inv;
}

// ======================================================================
// head-mean reduce (fp64, h-ascending). One CTA per batch.
// ======================================================================
__global__ void cls_reduce_kernel(float* __restrict__ out) {
    const int b = blockIdx.x, tid = threadIdx.x;
    for (int j = tid; j < N_ - 1; j += 256) {
        double a = 0.0;
        #pragma unroll
        for (int h = 0; h < H_; h++)
            a += g_cls_ph[b * H_ + h][j] * (1.0 / 12.0);
        g_clsd[b * (N_ - 1) + j] = a;
        out[OFF_CLS + (long)b * (N_ - 1) + j] = (float)a;
    }
}

// ======================================================================
// dual bitonic top-k (103 of 1024) on fp64 keys, jax tie-break.
// ======================================================================
__global__ void sort_kernel(float* __restrict__ out) {
    __shared__ double v[1024];
    __shared__ int ix[1024];
    const int b = blockIdx.x, tid = threadIdx.x;

    for (int pass = 0; pass < 2; pass++) {
        __syncthreads();
        for (int i = tid; i < 1024; i += 512) {
            v[i] = g_clsd[b * 1024 + i];
            ix[i] = i;
        }
        __syncthreads();
        const bool desc = (pass == 0);
        for (int k = 2; k <= 1024; k <<= 1) {
            for (int j = k >> 1; j > 0; j >>= 1) {
                for (int i = tid; i < 1024; i += 512) {
                    int p = i ^ j;
                    if (p > i) {
                        double va = v[i], vb = v[p];
                        int ia = ix[i], ib = ix[p];
                        bool ab = desc ? (va > vb || (va == vb && ia < ib))
                                       : (va < vb || (va == vb && ia < ib));
                        bool up = ((i & k) == 0);
                        if (up ? !ab : ab) {
                            v[i] = vb; v[p] = va;
                            ix[i] = ib; ix[p] = ia;
                        }
                    }
                }
                __syncthreads();
            }
        }
        const long offIdx = desc ? OFF_ENH_IDX : OFF_FUSE_IDX;
        const long offBrd = desc ? OFF_ENH_INDEX : OFF_FUSE_INDEX;
        for (int t = tid; t < TOPT; t += 512)
            out[offIdx + (long)b * TOPT + t] = (float)ix[t];
        for (int e = tid; e < TOPT * C_; e += 512) {
            int t = e / C_;
            out[offBrd + ((long)b * TOPT + t) * C_ + (e % C_)] = (float)ix[t];
        }
    }
}

// ======================================================================
// Launch
// ======================================================================
extern "C" void kernel_launch(void* const* d_in, const int* in_sizes, int n_in,
                              void* d_out, int out_size) {
    const float* x     = (const float*)d_in[0];
    const float* w_qkv = (const float*)d_in[1];
    const float* w_out = (const float*)d_in[2];
    const float* b_out = (const float*)d_in[3];
    float* out = (float*)d_out;

    cudaFuncSetAttribute(mma_gemm, cudaFuncAttributeMaxDynamicSharedMemorySize,
                         MMA_SMEM);
    cudaFuncSetAttribute(attn_mma, cudaFuncAttributeMaxDynamicSharedMemorySize,
                         ATTN_SMEM2);

    __nv_bfloat16 *xs0, *xs1, *ws0, *ws1, *wo0, *wo1, *cs0, *cs1;
    cudaGetSymbolAddress((void**)&xs0, g_xs); xs1 = xs0 + (long)M_TOT*C_;
    cudaGetSymbolAddress((void**)&ws0, g_ws); ws1 = ws0 + (long)3*C_*C_;
    cudaGetSymbolAddress((void**)&wo0, g_wo); wo1 = wo0 + (long)C_*C_;
    cudaGetSymbolAddress((void**)&cs0, g_cs); cs1 = cs0 + (long)M_TOT*C_;
    float* ctxp; cudaGetSymbolAddress((void**)&ctxp, g_ctx);

    split2<<<(M_TOT*C_ + 255)/256, 256>>>(x, xs0, xs1, M_TOT*C_);
    split2<<<(3*C_*C_ + 255)/256, 256>>>(w_qkv, ws0, ws1, 3*C_*C_);
    split2<<<(C_*C_ + 255)/256, 256>>>(w_out, wo0, wo1, C_*C_);

    // QKV: [4100,2304] = x @ w_qkv^T, writes bf16 q/k/v splits directly
    mma_gemm<<<dim3(3*C_/128, (M_TOT + 127)/128), 256, MMA_SMEM>>>(
        xs0, xs1, ws0, ws1, 0, b_out, out);

    // attention (tensor cores, ldmatrix(.trans), cp.async double buffer)
    attn_mma<<<dim3((N_ + 127)/128, B_ * H_), 256, ATTN_SMEM2>>>();

    split2<<<(M_TOT*C_ + 255)/256, 256>>>(ctxp, cs0, cs1, M_TOT*C_);

    // OUT: [4100,768] = ctx @ w_out^T + bias
    mma_gemm<<<dim3(C_/128, (M_TOT + 127)/128), 256, MMA_SMEM>>>(
        cs0, cs1, wo0, wo1, 1, b_out, out);

    // cls path: high-precision from raw inputs (GEMM-independent)
    cls_head_kernel<<<B_ * H_, 1024>>>(x, w_qkv);
    cls_reduce_kernel<<<B_, 256>>>(out);
    sort_kernel<<<B_, 512>>>(out);
}

// round 12
// speedup vs baseline: 2.5125x; 1.0426x over previous
#include <cuda_runtime.h>
#include <cuda_bf16.h>
#include <math.h>
#include <cstdint>

// ---------------- Problem constants ----------------
#define B_ 4
#define N_ 1025
#define C_ 768
#define H_ 12
#define D_ 64
#define TOPT 103
#define SCALEF 0.125f            // 64^-0.5
#define SCLOG2E (0.125f * 1.4426950408889634f)   // fold scale * log2(e) into Q

#define M_TOT (B_ * N_)          // 4100

// Output layout (float32, reference tuple flattened & concatenated):
#define OFF_OUT        0L
#define OFF_ENH_INDEX  3148800L
#define OFF_ENH_IDX    3465216L
#define OFF_FUSE_INDEX 3465628L
#define OFF_FUSE_IDX   3782044L
#define OFF_CLS        3782456L

// ---------------- Scratch (no allocation allowed) ----------------
__device__ double g_clsd[B_*(N_-1)];
__device__ double g_cls_ph[B_*H_][N_-1];

// bf16 2-way splits
__device__ __nv_bfloat16 g_xs[2][M_TOT*C_];
__device__ __nv_bfloat16 g_ws[2][3*C_*C_];     // w_qkv [2304,768]
__device__ __nv_bfloat16 g_wo[2][C_*C_];       // w_out [768,768]
__device__ __nv_bfloat16 g_cs[2][M_TOT*C_];    // ctx splits (written by attn)
// q/k/v as bf16 splits, [b,h,n,d]; q pre-scaled by SCALE*log2e
__device__ __nv_bfloat16 g_qs[2][B_*H_*N_*D_];
__device__ __nv_bfloat16 g_ks[2][B_*H_*N_*D_];
__device__ __nv_bfloat16 g_vs[2][B_*H_*N_*D_];

// ================= helpers =================
__device__ __forceinline__ void ldsm4(uint32_t* r, uint32_t addr) {
    asm volatile("ldmatrix.sync.aligned.m8n8.x4.shared.b16 {%0,%1,%2,%3}, [%4];"
        : "=r"(r[0]), "=r"(r[1]), "=r"(r[2]), "=r"(r[3]) : "r"(addr));
}
__device__ __forceinline__ void ldsm4t(uint32_t* r, uint32_t addr) {
    asm volatile("ldmatrix.sync.aligned.m8n8.x4.trans.shared.b16 {%0,%1,%2,%3}, [%4];"
        : "=r"(r[0]), "=r"(r[1]), "=r"(r[2]), "=r"(r[3]) : "r"(addr));
}
__device__ __forceinline__ void mma16816(float c[4], uint32_t a0, uint32_t a1,
                                         uint32_t a2, uint32_t a3,
                                         uint32_t b0, uint32_t b1) {
    asm volatile(
        "mma.sync.aligned.m16n8k16.row.col.f32.bf16.bf16.f32 "
        "{%0,%1,%2,%3}, {%4,%5,%6,%7}, {%8,%9}, {%0,%1,%2,%3};"
        : "+f"(c[0]), "+f"(c[1]), "+f"(c[2]), "+f"(c[3])
        : "r"(a0), "r"(a1), "r"(a2), "r"(a3), "r"(b0), "r"(b1));
}
__device__ __forceinline__ void cpa16(uint32_t dst, const void* src, int sz) {
    asm volatile("cp.async.cg.shared.global [%0], [%1], 16, %2;"
        :: "r"(dst), "l"(src), "r"(sz));
}
#define CP_COMMIT() asm volatile("cp.async.commit_group;" ::: "memory")
#define CP_WAIT1()  asm volatile("cp.async.wait_group 1;" ::: "memory")
__device__ __forceinline__ void split_pack(float x, float y,
                                           uint32_t& hi, uint32_t& lo) {
    __nv_bfloat16 x0 = __float2bfloat16(x);
    __nv_bfloat16 y0 = __float2bfloat16(y);
    __nv_bfloat16 x1 = __float2bfloat16(x - __bfloat162float(x0));
    __nv_bfloat16 y1 = __float2bfloat16(y - __bfloat162float(y0));
    __nv_bfloat162 h; h.x = x0; h.y = y0;
    __nv_bfloat162 l; l.x = x1; l.y = y1;
    hi = *(uint32_t*)&h; lo = *(uint32_t*)&l;
}

// ======================================================================
// Split kernel: fp32 -> 2 bf16 splits (residual ~2^-16)
// ======================================================================
__global__ void split2(const float* __restrict__ src,
                       __nv_bfloat16* __restrict__ d0,
                       __nv_bfloat16* __restrict__ d1, int n) {
    int i = blockIdx.x * blockDim.x + threadIdx.x;
    if (i < n) {
        float x = src[i];
        __nv_bfloat16 b0 = __float2bfloat16(x);
        d0[i] = b0;
        d1[i] = __float2bfloat16(x - __bfloat162float(b0));
    }
}

// ======================================================================
// mma.sync bf16 GEMM, 2-split / 3-product, ldmatrix + cp.async double buffer.
// mode 0: write q/k/v bf16 splits (q pre-scaled); mode 1: out + bias (fp32).
// ======================================================================
#define TILE_B  (128 * 80)               // 10240 B per split tile (80B rows)
#define STAGE_G (4 * TILE_B)             // 40960 B per stage
#define MMA_SMEM (2 * STAGE_G)           // 81920 B

__global__ void __launch_bounds__(256, 2)
mma_gemm(const __nv_bfloat16* __restrict__ A0, const __nv_bfloat16* __restrict__ A1,
         const __nv_bfloat16* __restrict__ B0, const __nv_bfloat16* __restrict__ B1,
         int mode, const float* __restrict__ bias, float* __restrict__ out) {
    extern __shared__ __align__(16) char smem[];
    const uint32_t smb = (uint32_t)__cvta_generic_to_shared(smem);
    const int tid = threadIdx.x;
    const int wid = tid >> 5, lane = tid & 31;
    const int gid = lane >> 2, tig = lane & 3;
    const int wr = wid >> 2, wc = wid & 3;        // warp grid 2 x 4
    const int m0 = blockIdx.y * 128;
    const int n0 = blockIdx.x * 128;

    const int lr = lane & 7;
    const int aro = lr + ((lane >> 3) & 1) * 8;
    const int aco = (lane >> 4) * 16;
    const int bro = lr + (lane >> 4) * 8;
    const int bco = ((lane >> 3) & 1) * 16;

    const __nv_bfloat16* Asrc[2] = {A0, A1};
    const __nv_bfloat16* Bsrc[2] = {B0, B1};

    float acc[4][4][4];
    #pragma unroll
    for (int i = 0; i < 4; i++)
        #pragma unroll
        for (int j = 0; j < 4; j++)
            #pragma unroll
            for (int r = 0; r < 4; r++) acc[i][j][r] = 0.f;

    auto stageg = [&](int kb_, int bufi) {
        const int kcol = kb_ * 32;
        const uint32_t sb = smb + bufi * STAGE_G;
        #pragma unroll
        for (int t = 0; t < 8; t++) {
            int idx = tid + t * 256;                 // 0..2047
            int a = idx >> 9;                        // 0:A0 1:A1 2:B0 3:B1
            int r = (idx >> 2) & 127, c = idx & 3;
            const __nv_bfloat16* src;
            int sz = 16;
            if (a < 2) {
                src = Asrc[a] + (long)(m0 + r) * C_ + kcol + c * 8;
                if (m0 + r >= M_TOT) sz = 0;
            } else {
                src = Bsrc[a - 2] + (long)(n0 + r) * C_ + kcol + c * 8;
            }
            cpa16(sb + a * TILE_B + r * 80 + c * 16, src, sz);
        }
    };

    stageg(0, 0);
    CP_COMMIT();

    for (int kb = 0; kb < 24; kb++) {
        __syncthreads();
        if (kb + 1 < 24) stageg(kb + 1, (kb + 1) & 1);
        CP_COMMIT();
        CP_WAIT1();
        __syncthreads();

        const uint32_t sb = smb + (kb & 1) * STAGE_G;
        #pragma unroll
        for (int ks = 0; ks < 2; ks++) {
            #pragma unroll
            for (int sa = 0; sa < 2; sa++) {
                uint32_t af[4][4];
                #pragma unroll
                for (int i = 0; i < 4; i++)
                    ldsm4(af[i], sb + sa * TILE_B +
                          (uint32_t)((wr * 64 + i * 16 + aro) * 80 + ks * 32 + aco));
                #pragma unroll
                for (int sb2 = 0; sb2 < 2 - sa; sb2++) {
                    uint32_t bf[4][2], r4[4];
                    ldsm4(r4, sb + (2 + sb2) * TILE_B +
                          (uint32_t)((wc * 32 + bro) * 80 + ks * 32 + bco));
                    bf[0][0] = r4[0]; bf[0][1] = r4[1];
                    bf[1][0] = r4[2]; bf[1][1] = r4[3];
                    ldsm4(r4, sb + (2 + sb2) * TILE_B +
                          (uint32_t)((wc * 32 + 16 + bro) * 80 + ks * 32 + bco));
                    bf[2][0] = r4[0]; bf[2][1] = r4[1];
                    bf[3][0] = r4[2]; bf[3][1] = r4[3];
                    #pragma unroll
                    for (int i = 0; i < 4; i++)
                        #pragma unroll
                        for (int j = 0; j < 4; j++)
                            mma16816(acc[i][j], af[i][0], af[i][1], af[i][2],
                                     af[i][3], bf[j][0], bf[j][1]);
                }
            }
        }
    }

    // ---------------- epilogue ----------------
    #pragma unroll
    for (int i = 0; i < 4; i++) {
        #pragma unroll
        for (int half = 0; half < 2; half++) {
            int gm = m0 + wr * 64 + i * 16 + gid + half * 8;
            if (gm >= M_TOT) continue;
            int btok = gm / N_, nt = gm % N_;
            #pragma unroll
            for (int j = 0; j < 4; j++) {
                float v0 = acc[i][j][half * 2];
                float v1 = acc[i][j][half * 2 + 1];
                int jg = n0 + wc * 32 + j * 8 + tig * 2;
                if (mode == 0) {
                    int qkv_i = jg / C_;
                    int rem = jg % C_;
                    int h = rem >> 6, d0 = rem & 63;
                    if (qkv_i == 0) { v0 *= SCLOG2E; v1 *= SCLOG2E; }
                    __nv_bfloat16* dh = (qkv_i == 0) ? g_qs[0]
                                        : (qkv_i == 1 ? g_ks[0] : g_vs[0]);
                    __nv_bfloat16* dl = (qkv_i == 0) ? g_qs[1]
                                        : (qkv_i == 1 ? g_ks[1] : g_vs[1]);
                    long base = ((long)(btok * H_ + h) * N_ + nt) * 64 + d0;
                    uint32_t hi, lo;
                    split_pack(v0, v1, hi, lo);
                    *(uint32_t*)&dh[base] = hi;
                    *(uint32_t*)&dl[base] = lo;
                } else {
                    long base = OFF_OUT + (long)gm * C_ + jg;
                    *(float2*)&out[base] = make_float2(v0 + bias[jg], v1 + bias[jg + 1]);
                }
            }
        }
    }
}

// ======================================================================
// mma.sync flash attention, pre-split bf16 q/k/v (q pre-scaled by
// SCALE*log2e -> exp2f softmax), ldmatrix (+trans for V), cp.async double
// buffer, hoisted CSA mask classification, per-warp tile skip.
// Writes ctx directly as bf16 2-splits (g_cs).
// ======================================================================
#define TILE_A  9216
#define STAGE_A (4 * TILE_A)             // 36864 B per stage
#define ATTN_SMEM2 (2 * STAGE_A)         // 73728 B

__global__ void __launch_bounds__(256)
attn_mma() {
    extern __shared__ __align__(16) uint32_t asw[];
    const uint32_t smb = (uint32_t)__cvta_generic_to_shared(asw);
    const int tid = threadIdx.x;
    const int wid = tid >> 5, lane = tid & 31;
    const int gid = lane >> 2, tig = lane & 3;
    const int bh = blockIdx.y;
    const int q0g = blockIdx.x * 128;

    const int lr = lane & 7;
    const int aro = lr + ((lane >> 3) & 1) * 8;
    const int aco = (lane >> 4) * 16;
    const int bro = lr + (lane >> 4) * 8;
    const int bco = ((lane >> 3) & 1) * 16;
    const int vro = lr + ((lane >> 3) & 1) * 8;
    const int vco = (lane >> 4) * 16;

    const __nv_bfloat16* Qh = g_qs[0] + (long)bh * N_ * 64;
    const __nv_bfloat16* Ql = g_qs[1] + (long)bh * N_ * 64;
    const __nv_bfloat16* Kh = g_ks[0] + (long)bh * N_ * 64;
    const __nv_bfloat16* Kl = g_ks[1] + (long)bh * N_ * 64;
    const __nv_bfloat16* Vh = g_vs[0] + (long)bh * N_ * 64;
    const __nv_bfloat16* Vl = g_vs[1] + (long)bh * N_ * 64;

    // ---- phase A: stage Q splits into stage 0, extract fragments ----
    {
        __nv_bfloat16* Q0 = (__nv_bfloat16*)asw;
        __nv_bfloat16* Q1 = (__nv_bfloat16*)((char*)asw + STAGE_A);
        for (int idx = tid; idx < 128 * 8; idx += 256) {
            int r = idx >> 3, c = idx & 7;
            int qi = q0g + r;
            uint4 vh = make_uint4(0, 0, 0, 0), vl = vh;
            if (qi < N_) {
                vh = *(const uint4*)(Qh + (long)qi * 64 + c * 8);
                vl = *(const uint4*)(Ql + (long)qi * 64 + c * 8);
            }
            *(uint4*)(Q0 + r * 72 + c * 8) = vh;
            *(uint4*)(Q1 + r * 72 + c * 8) = vl;
        }
    }
    __syncthreads();
    uint32_t qf[2][4][4];
    #pragma unroll
    for (int ks = 0; ks < 4; ks++) {
        uint32_t off = (uint32_t)((wid * 16 + aro) * 144 + ks * 32 + aco);
        ldsm4(qf[0][ks], smb + off);
        ldsm4(qf[1][ks], smb + STAGE_A + off);
    }
    __syncthreads();

    float accD[8][4];
    #pragma unroll
    for (int dt = 0; dt < 8; dt++)
        #pragma unroll
        for (int r = 0; r < 4; r++) accD[dt][r] = 0.f;
    float m2[2] = {-INFINITY, -INFINITY};
    float l2[2] = {0.f, 0.f};

    // per-warp row-block data (hoisted out of the kt loop)
    const int rlo = q0g + wid * 16;
    const bool w_dead = (rlo >= N_);
    bool wq_uni = false; int wqb = -2;
    int wblk_lo = 5, wblk_hi = -5;
    if (!w_dead) {
        int rhi = min(rlo + 15, N_ - 1);
        int blo = (max(rlo, 1) - 1) >> 8;
        int bhi = (rhi >= 1) ? ((rhi - 1) >> 8) : -1;
        wblk_lo = blo; wblk_hi = bhi;
        if (rlo >= 1 && blo == bhi) { wq_uni = true; wqb = blo; }
    }
    // per-thread row blocks (hoisted)
    const int row0g = rlo + gid, row1g = rlo + gid + 8;
    const int qb0 = (row0g >= 1 && row0g < N_) ? ((row0g - 1) >> 8) : -1;
    const int qb1 = (row1g >= 1 && row1g < N_) ? ((row1g - 1) >> 8) : -1;

    auto stagea = [&](int kt_, int bufi) {
        const int k0 = kt_ * 64;
        const uint32_t sb = smb + bufi * STAGE_A;
        const __nv_bfloat16* srcs[4] = {Kh, Kl, Vh, Vl};
        #pragma unroll
        for (int t = 0; t < 8; t++) {
            int idx = tid + t * 256;
            int a = idx >> 9, r = (idx >> 3) & 63, c = idx & 7;
            int kj = k0 + r;
            const __nv_bfloat16* src = srcs[a] + (long)kj * 64 + c * 8;
            cpa16(sb + a * TILE_A + r * 144 + c * 16, src, (kj < N_) ? 16 : 0);
        }
    };

    stagea(0, 0);
    CP_COMMIT();

    for (int kt = 0; kt < 17; kt++) {
        const int k0g = kt * 64;
        __syncthreads();
        if (kt + 1 < 17) stagea(kt + 1, (kt + 1) & 1);
        CP_COMMIT();
        CP_WAIT1();
        __syncthreads();

        // tile classification (warp-uniform)
        bool skip = w_dead;
        bool need_mask = false;
        if (!skip) {
            int klo = max(k0g, 1), khi = min(k0g + 63, N_ - 1);
            int kbl = (klo - 1) >> 8, kbh = (khi - 1) >> 8;
            if (wq_uni && k0g >= 1 && kbl == kbh && kbl == wqb) skip = true;
            else need_mask = (k0g + 63 >= N_) ||
                             (kbl <= wblk_hi && kbh >= wblk_lo);
        }
        if (skip) continue;

        const uint32_t sb = smb + (kt & 1) * STAGE_A;

        // ---- S = Q K^T (3 products), ldmatrix K fragments ----
        float sp[8][4];
        #pragma unroll
        for (int nt = 0; nt < 8; nt++)
            #pragma unroll
            for (int r = 0; r < 4; r++) sp[nt][r] = 0.f;

        #pragma unroll
        for (int ks = 0; ks < 4; ks++) {
            #pragma unroll
            for (int ntp = 0; ntp < 4; ntp++) {
                uint32_t rowb = (uint32_t)((ntp * 16 + bro) * 144 + ks * 32 + bco);
                uint32_t h4[4], l4[4];
                ldsm4(h4, sb + rowb);
                ldsm4(l4, sb + TILE_A + rowb);
                mma16816(sp[2*ntp], qf[0][ks][0], qf[0][ks][1], qf[0][ks][2],
                         qf[0][ks][3], h4[0], h4[1]);
                mma16816(sp[2*ntp], qf[1][ks][0], qf[1][ks][1], qf[1][ks][2],
                         qf[1][ks][3], h4[0], h4[1]);
                mma16816(sp[2*ntp], qf[0][ks][0], qf[0][ks][1], qf[0][ks][2],
                         qf[0][ks][3], l4[0], l4[1]);
                mma16816(sp[2*ntp+1], qf[0][ks][0], qf[0][ks][1], qf[0][ks][2],
                         qf[0][ks][3], h4[2], h4[3]);
                mma16816(sp[2*ntp+1], qf[1][ks][0], qf[1][ks][1], qf[1][ks][2],
                         qf[1][ks][3], h4[2], h4[3]);
                mma16816(sp[2*ntp+1], qf[0][ks][0], qf[0][ks][1], qf[0][ks][2],
                         qf[0][ks][3], l4[2], l4[3]);
            }
        }

        // ---- CSA mask (only on flagged tiles; scale folded into Q) ----
        if (need_mask) {
            #pragma unroll
            for (int nt = 0; nt < 8; nt++) {
                #pragma unroll
                for (int c = 0; c < 4; c++) {
                    int qb = (c >= 2) ? qb1 : qb0;
                    int key = k0g + nt * 8 + 2 * tig + (c & 1);
                    bool bad = (key >= N_) ||
                               (qb >= 0 && key >= 1 && ((key - 1) >> 8) == qb);
                    if (bad) sp[nt][c] = -INFINITY;
                }
            }
        }

        // ---- online softmax in log2 domain (per half: rows gid, gid+8) ----
        #pragma unroll
        for (int half = 0; half < 2; half++) {
            float mx = -INFINITY;
            #pragma unroll
            for (int nt = 0; nt < 8; nt++)
                mx = fmaxf(mx, fmaxf(sp[nt][half*2], sp[nt][half*2+1]));
            mx = fmaxf(mx, __shfl_xor_sync(0xffffffffu, mx, 1));
            mx = fmaxf(mx, __shfl_xor_sync(0xffffffffu, mx, 2));
            float mnew = fmaxf(m2[half], mx);
            float corr = exp2f(m2[half] - mnew);
            m2[half] = mnew;
            float rs = 0.f;
            #pragma unroll
            for (int nt = 0; nt < 8; nt++) {
                float p0 = exp2f(sp[nt][half*2]   - mnew);
                float p1 = exp2f(sp[nt][half*2+1] - mnew);
                sp[nt][half*2] = p0; sp[nt][half*2+1] = p1;
                rs += p0 + p1;
            }
            rs += __shfl_xor_sync(0xffffffffu, rs, 1);
            rs += __shfl_xor_sync(0xffffffffu, rs, 2);
            l2[half] = l2[half] * corr + rs;
            #pragma unroll
            for (int dt = 0; dt < 8; dt++) {
                accD[dt][half*2]   *= corr;
                accD[dt][half*2+1] *= corr;
            }
        }

        // ---- O += P V (3 products), ldmatrix.trans V fragments ----
        #pragma unroll
        for (int ks = 0; ks < 4; ks++) {
            uint32_t p0[4], p1[4];
            split_pack(sp[2*ks][0],   sp[2*ks][1],   p0[0], p1[0]);
            split_pack(sp[2*ks][2],   sp[2*ks][3],   p0[1], p1[1]);
            split_pack(sp[2*ks+1][0], sp[2*ks+1][1], p0[2], p1[2]);
            split_pack(sp[2*ks+1][2], sp[2*ks+1][3], p0[3], p1[3]);
            #pragma unroll
            for (int dtp = 0; dtp < 4; dtp++) {
                uint32_t rowb = (uint32_t)((ks * 16 + vro) * 144 + dtp * 32 + vco);
                uint32_t h4[4], l4[4];
                ldsm4t(h4, sb + 2 * TILE_A + rowb);
                ldsm4t(l4, sb + 3 * TILE_A + rowb);
                mma16816(accD[2*dtp], p0[0], p0[1], p0[2], p0[3], h4[0], h4[1]);
                mma16816(accD[2*dtp], p1[0], p1[1], p1[2], p1[3], h4[0], h4[1]);
                mma16816(accD[2*dtp], p0[0], p0[1], p0[2], p0[3], l4[0], l4[1]);
                mma16816(accD[2*dtp+1], p0[0], p0[1], p0[2], p0[3], h4[2], h4[3]);
                mma16816(accD[2*dtp+1], p1[0], p1[1], p1[2], p1[3], h4[2], h4[3]);
                mma16816(accD[2*dtp+1], p0[0], p0[1], p0[2], p0[3], l4[2], l4[3]);
            }
        }
    }

    // ---- epilogue: write ctx directly as bf16 2-splits ----
    const int b = bh / H_, h = bh % H_;
    #pragma unroll
    for (int half = 0; half < 2; half++) {
        int row = rlo + gid + half * 8;
        if (row < N_) {
            float inv = 1.f / l2[half];
            #pragma unroll
            for (int dt = 0; dt < 8; dt++) {
                int d = dt * 8 + 2 * tig;
                long base = ((long)b * N_ + row) * C_ + h * 64 + d;
                uint32_t hi, lo;
                split_pack(accD[dt][half*2] * inv, accD[dt][half*2+1] * inv, hi, lo);
                *(uint32_t*)&g_cs[0][base] = hi;
                *(uint32_t*)&g_cs[1][base] = lo;
            }
        }
    }
}

// ======================================================================
// cls per-head softmax row -- GEMM-independent (raw inputs), high precision.
// ======================================================================
__global__ void __launch_bounds__(1024)
cls_head_kernel(const float* __restrict__ x, const float* __restrict__ w) {
    __shared__ double q0s[64];
    __shared__ float uhi[C_], ulo[C_];
    __shared__ double s[N_];
    __shared__ double red[32];
    const int bh = blockIdx.x;
    const int b = bh / H_, h = bh % H_;
    const int tid = threadIdx.x;
    const int wid = tid >> 5, lane = tid & 31;

    const float* xb = x + (long)b * N_ * C_;
    const float* wq = w + (long)(h * 64) * C_;
    const float* wk = w + (long)(C_ + h * 64) * C_;

    for (int d = wid; d < 64; d += 32) {
        double a = 0.0;
        for (int c = lane; c < C_; c += 32)
            a += (double)xb[c] * (double)wq[(long)d * C_ + c];
        #pragma unroll
        for (int o = 16; o >= 1; o >>= 1)
            a += __shfl_xor_sync(0xffffffffu, a, o);
        if (lane == 0) q0s[d] = a;
    }
    __syncthreads();

    for (int c = tid; c < C_; c += 1024) {
        double a = 0.0;
        #pragma unroll 8
        for (int d = 0; d < 64; d++)
            a += q0s[d] * (double)wk[(long)d * C_ + c];
        a *= 0.125;
        float hi = (float)a;
        uhi[c] = hi;
        ulo[c] = (float)(a - (double)hi);
    }
    __syncthreads();

    for (int j = wid; j < N_; j += 32) {
        const float* xr = xb + (long)j * C_;
        float sum = 0.f, comp = 0.f, err = 0.f;
        #pragma unroll 2
        for (int c = lane * 4; c < C_; c += 128) {
            float4 xv = *(const float4*)&xr[c];
            float4 uh = *(const float4*)&uhi[c];
            float4 ul = *(const float4*)&ulo[c];
            #pragma unroll
            for (int e4 = 0; e4 < 4; e4++) {
                float xe = (&xv.x)[e4], he = (&uh.x)[e4], le = (&ul.x)[e4];
                float p = he * xe;
                err = fmaf(he, xe, -p) + err;
                err = fmaf(le, xe, err);
                float y = p - comp;
                float t = sum + y;
                comp = (t - sum) - y;
                sum = t;
            }
        }
        double tot = ((double)sum - (double)comp) + (double)err;
        #pragma unroll
        for (int o = 16; o >= 1; o >>= 1)
            tot += __shfl_xor_sync(0xffffffffu, tot, o);
        if (lane == 0) s[j] = tot;
    }
    __syncthreads();

    double lm = -1e300;
    for (int j = tid; j < N_; j += 1024) lm = fmax(lm, s[j]);
    #pragma unroll
    for (int o = 16; o >= 1; o >>= 1)
        lm = fmax(lm, __shfl_xor_sync(0xffffffffu, lm, o));
    if (lane == 0) red[wid] = lm;
    __syncthreads();
    if (wid == 0) {
        double t = red[lane];
        #pragma unroll
        for (int o = 16; o >= 1; o >>= 1)
            t = fmax(t, __shfl_xor_sync(0xffffffffu, t, o));
        if (lane == 0) red[0] = t;
    }
    __syncthreads();
    const double m = red[0];
    __syncthreads();

    double ls = 0.0;
    for (int j = tid; j < N_; j += 1024) {
        double e = exp(s[j] - m);
        s[j] = e;
        ls += e;
    }
    #pragma unroll
    for (int o = 16; o >= 1; o >>= 1)
        ls += __shfl_xor_sync(0xffffffffu, ls, o);
    if (lane == 0) red[wid] = ls;
    __syncthreads();
    if (wid == 0) {
        double t = red[lane];
        #pragma unroll
        for (int o = 16; o >= 1; o >>= 1)
            t += __shfl_xor_sync(0xffffffffu, t, o);
        if (lane == 0) red[0] = t;
    }
    __syncthreads();
    const double inv = 1.0 / red[0];

    for (int j = tid; j < N_ - 1; j += 1024)
        g_cls_ph[bh][j] = s[j + 1] * inv;
}

// ======================================================================
// head-mean reduce (fp64, h-ascending). One CTA per batch.
// ======================================================================
__global__ void cls_reduce_kernel(float* __restrict__ out) {
    const int b = blockIdx.x, tid = threadIdx.x;
    for (int j = tid; j < N_ - 1; j += 256) {
        double a = 0.0;
        #pragma unroll
        for (int h = 0; h < H_; h++)
            a += g_cls_ph[b * H_ + h][j] * (1.0 / 12.0);
        g_clsd[b * (N_ - 1) + j] = a;
        out[OFF_CLS + (long)b * (N_ - 1) + j] = (float)a;
    }
}

// ======================================================================
// dual bitonic top-k (103 of 1024) on fp64 keys, jax tie-break.
// ======================================================================
__global__ void sort_kernel(float* __restrict__ out) {
    __shared__ double v[1024];
    __shared__ int ix[1024];
    const int b = blockIdx.x, tid = threadIdx.x;

    for (int pass = 0; pass < 2; pass++) {
        __syncthreads();
        for (int i = tid; i < 1024; i += 512) {
            v[i] = g_clsd[b * 1024 + i];
            ix[i] = i;
        }
        __syncthreads();
        const bool desc = (pass == 0);
        for (int k = 2; k <= 1024; k <<= 1) {
            for (int j = k >> 1; j > 0; j >>= 1) {
                for (int i = tid; i < 1024; i += 512) {
                    int p = i ^ j;
                    if (p > i) {
                        double va = v[i], vb = v[p];
                        int ia = ix[i], ib = ix[p];
                        bool ab = desc ? (va > vb || (va == vb && ia < ib))
                                       : (va < vb || (va == vb && ia < ib));
                        bool up = ((i & k) == 0);
                        if (up ? !ab : ab) {
                            v[i] = vb; v[p] = va;
                            ix[i] = ib; ix[p] = ia;
                        }
                    }
                }
                __syncthreads();
            }
        }
        const long offIdx = desc ? OFF_ENH_IDX : OFF_FUSE_IDX;
        const long offBrd = desc ? OFF_ENH_INDEX : OFF_FUSE_INDEX;
        for (int t = tid; t < TOPT; t += 512)
            out[offIdx + (long)b * TOPT + t] = (float)ix[t];
        for (int e = tid; e < TOPT * C_; e += 512) {
            int t = e / C_;
            out[offBrd + ((long)b * TOPT + t) * C_ + (e % C_)] = (float)ix[t];
        }
    }
}

// ======================================================================
// Launch
// ======================================================================
extern "C" void kernel_launch(void* const* d_in, const int* in_sizes, int n_in,
                              void* d_out, int out_size) {
    const float* x     = (const float*)d_in[0];
    const float* w_qkv = (const float*)d_in[1];
    const float* w_out = (const float*)d_in[2];
    const float* b_out = (const float*)d_in[3];
    float* out = (float*)d_out;

    cudaFuncSetAttribute(mma_gemm, cudaFuncAttributeMaxDynamicSharedMemorySize,
                         MMA_SMEM);
    cudaFuncSetAttribute(attn_mma, cudaFuncAttributeMaxDynamicSharedMemorySize,
                         ATTN_SMEM2);

    __nv_bfloat16 *xs0, *xs1, *ws0, *ws1, *wo0, *wo1, *cs0, *cs1;
    cudaGetSymbolAddress((void**)&xs0, g_xs); xs1 = xs0 + (long)M_TOT*C_;
    cudaGetSymbolAddress((void**)&ws0, g_ws); ws1 = ws0 + (long)3*C_*C_;
    cudaGetSymbolAddress((void**)&wo0, g_wo); wo1 = wo0 + (long)C_*C_;
    cudaGetSymbolAddress((void**)&cs0, g_cs); cs1 = cs0 + (long)M_TOT*C_;

    split2<<<(M_TOT*C_ + 255)/256, 256>>>(x, xs0, xs1, M_TOT*C_);
    split2<<<(3*C_*C_ + 255)/256, 256>>>(w_qkv, ws0, ws1, 3*C_*C_);
    split2<<<(C_*C_ + 255)/256, 256>>>(w_out, wo0, wo1, C_*C_);

    // QKV: [4100,2304] = x @ w_qkv^T, writes bf16 q/k/v splits (q pre-scaled)
    mma_gemm<<<dim3(3*C_/128, (M_TOT + 127)/128), 256, MMA_SMEM>>>(
        xs0, xs1, ws0, ws1, 0, b_out, out);

    // attention -> ctx bf16 splits directly
    attn_mma<<<dim3((N_ + 127)/128, B_ * H_), 256, ATTN_SMEM2>>>();

    // OUT: [4100,768] = ctx @ w_out^T + bias
    mma_gemm<<<dim3(C_/128, (M_TOT + 127)/128), 256, MMA_SMEM>>>(
        cs0, cs1, wo0, wo1, 1, b_out, out);

    // cls path: high-precision from raw inputs (GEMM-independent)
    cls_head_kernel<<<B_ * H_, 1024>>>(x, w_qkv);
    cls_reduce_kernel<<<B_, 256>>>(out);
    sort_kernel<<<B_, 512>>>(out);
}

// round 13
// speedup vs baseline: 2.5948x; 1.0328x over previous
#include <cuda_runtime.h>
#include <cuda_bf16.h>
#include <math.h>
#include <cstdint>

// ---------------- Problem constants ----------------
#define B_ 4
#define N_ 1025
#define C_ 768
#define H_ 12
#define D_ 64
#define TOPT 103
#define SCALEF 0.125f            // 64^-0.5
#define SCLOG2E (0.125f * 1.4426950408889634f)   // fold scale * log2(e) into Q

#define M_TOT (B_ * N_)          // 4100

// Output layout (float32, reference tuple flattened & concatenated):
#define OFF_OUT        0L
#define OFF_ENH_INDEX  3148800L
#define OFF_ENH_IDX    3465216L
#define OFF_FUSE_INDEX 3465628L
#define OFF_FUSE_IDX   3782044L
#define OFF_CLS        3782456L

// ---------------- Scratch (no allocation allowed) ----------------
__device__ double g_clsd[B_*(N_-1)];
__device__ double g_cls_ph[B_*H_][N_-1];

// bf16 2-way splits
__device__ __nv_bfloat16 g_xs[2][M_TOT*C_];
__device__ __nv_bfloat16 g_ws[2][3*C_*C_];     // w_qkv [2304,768]
__device__ __nv_bfloat16 g_wo[2][C_*C_];       // w_out [768,768]
__device__ __nv_bfloat16 g_cs[2][M_TOT*C_];    // ctx splits (written by attn)
// q/k/v as bf16 splits, [b,h,n,d]; q pre-scaled by SCALE*log2e
__device__ __nv_bfloat16 g_qs[2][B_*H_*N_*D_];
__device__ __nv_bfloat16 g_ks[2][B_*H_*N_*D_];
__device__ __nv_bfloat16 g_vs[2][B_*H_*N_*D_];

// ================= helpers =================
__device__ __forceinline__ void ldsm4(uint32_t* r, uint32_t addr) {
    asm volatile("ldmatrix.sync.aligned.m8n8.x4.shared.b16 {%0,%1,%2,%3}, [%4];"
        : "=r"(r[0]), "=r"(r[1]), "=r"(r[2]), "=r"(r[3]) : "r"(addr));
}
__device__ __forceinline__ void ldsm4t(uint32_t* r, uint32_t addr) {
    asm volatile("ldmatrix.sync.aligned.m8n8.x4.trans.shared.b16 {%0,%1,%2,%3}, [%4];"
        : "=r"(r[0]), "=r"(r[1]), "=r"(r[2]), "=r"(r[3]) : "r"(addr));
}
__device__ __forceinline__ void mma16816(float c[4], uint32_t a0, uint32_t a1,
                                         uint32_t a2, uint32_t a3,
                                         uint32_t b0, uint32_t b1) {
    asm volatile(
        "mma.sync.aligned.m16n8k16.row.col.f32.bf16.bf16.f32 "
        "{%0,%1,%2,%3}, {%4,%5,%6,%7}, {%8,%9}, {%0,%1,%2,%3};"
        : "+f"(c[0]), "+f"(c[1]), "+f"(c[2]), "+f"(c[3])
        : "r"(a0), "r"(a1), "r"(a2), "r"(a3), "r"(b0), "r"(b1));
}
__device__ __forceinline__ void cpa16(uint32_t dst, const void* src, int sz) {
    asm volatile("cp.async.cg.shared.global [%0], [%1], 16, %2;"
        :: "r"(dst), "l"(src), "r"(sz));
}
#define CP_COMMIT() asm volatile("cp.async.commit_group;" ::: "memory")
#define CP_WAIT1()  asm volatile("cp.async.wait_group 1;" ::: "memory")
__device__ __forceinline__ void split_pack(float x, float y,
                                           uint32_t& hi, uint32_t& lo) {
    __nv_bfloat16 x0 = __float2bfloat16(x);
    __nv_bfloat16 y0 = __float2bfloat16(y);
    __nv_bfloat16 x1 = __float2bfloat16(x - __bfloat162float(x0));
    __nv_bfloat16 y1 = __float2bfloat16(y - __bfloat162float(y0));
    __nv_bfloat162 h; h.x = x0; h.y = y0;
    __nv_bfloat162 l; l.x = x1; l.y = y1;
    hi = *(uint32_t*)&h; lo = *(uint32_t*)&l;
}

// ======================================================================
// Split kernel: fp32 -> 2 bf16 splits (residual ~2^-16)
// ======================================================================
__global__ void split2(const float* __restrict__ src,
                       __nv_bfloat16* __restrict__ d0,
                       __nv_bfloat16* __restrict__ d1, int n) {
    int i = blockIdx.x * blockDim.x + threadIdx.x;
    if (i < n) {
        float x = src[i];
        __nv_bfloat16 b0 = __float2bfloat16(x);
        d0[i] = b0;
        d1[i] = __float2bfloat16(x - __bfloat162float(b0));
    }
}

// ======================================================================
// mma.sync bf16 GEMM, 2-split / 3-product, ldmatrix + cp.async double buffer.
// mode 0: write q/k/v bf16 splits (q pre-scaled); mode 1: out + bias (fp32).
// ======================================================================
#define TILE_B  (128 * 80)               // 10240 B per split tile (80B rows)
#define STAGE_G (4 * TILE_B)             // 40960 B per stage
#define MMA_SMEM (2 * STAGE_G)           // 81920 B

__global__ void __launch_bounds__(256, 2)
mma_gemm(const __nv_bfloat16* __restrict__ A0, const __nv_bfloat16* __restrict__ A1,
         const __nv_bfloat16* __restrict__ B0, const __nv_bfloat16* __restrict__ B1,
         int mode, const float* __restrict__ bias, float* __restrict__ out) {
    extern __shared__ __align__(16) char smem[];
    const uint32_t smb = (uint32_t)__cvta_generic_to_shared(smem);
    const int tid = threadIdx.x;
    const int wid = tid >> 5, lane = tid & 31;
    const int gid = lane >> 2, tig = lane & 3;
    const int wr = wid >> 2, wc = wid & 3;        // warp grid 2 x 4
    const int m0 = blockIdx.y * 128;
    const int n0 = blockIdx.x * 128;

    const int lr = lane & 7;
    const int aro = lr + ((lane >> 3) & 1) * 8;
    const int aco = (lane >> 4) * 16;
    const int bro = lr + (lane >> 4) * 8;
    const int bco = ((lane >> 3) & 1) * 16;

    const __nv_bfloat16* Asrc[2] = {A0, A1};
    const __nv_bfloat16* Bsrc[2] = {B0, B1};

    float acc[4][4][4];
    #pragma unroll
    for (int i = 0; i < 4; i++)
        #pragma unroll
        for (int j = 0; j < 4; j++)
            #pragma unroll
            for (int r = 0; r < 4; r++) acc[i][j][r] = 0.f;

    auto stageg = [&](int kb_, int bufi) {
        const int kcol = kb_ * 32;
        const uint32_t sb = smb + bufi * STAGE_G;
        #pragma unroll
        for (int t = 0; t < 8; t++) {
            int idx = tid + t * 256;                 // 0..2047
            int a = idx >> 9;                        // 0:A0 1:A1 2:B0 3:B1
            int r = (idx >> 2) & 127, c = idx & 3;
            const __nv_bfloat16* src;
            int sz = 16;
            if (a < 2) {
                src = Asrc[a] + (long)(m0 + r) * C_ + kcol + c * 8;
                if (m0 + r >= M_TOT) sz = 0;
            } else {
                src = Bsrc[a - 2] + (long)(n0 + r) * C_ + kcol + c * 8;
            }
            cpa16(sb + a * TILE_B + r * 80 + c * 16, src, sz);
        }
    };

    stageg(0, 0);
    CP_COMMIT();

    for (int kb = 0; kb < 24; kb++) {
        __syncthreads();
        if (kb + 1 < 24) stageg(kb + 1, (kb + 1) & 1);
        CP_COMMIT();
        CP_WAIT1();
        __syncthreads();

        const uint32_t sb = smb + (kb & 1) * STAGE_G;
        #pragma unroll
        for (int ks = 0; ks < 2; ks++) {
            #pragma unroll
            for (int sa = 0; sa < 2; sa++) {
                uint32_t af[4][4];
                #pragma unroll
                for (int i = 0; i < 4; i++)
                    ldsm4(af[i], sb + sa * TILE_B +
                          (uint32_t)((wr * 64 + i * 16 + aro) * 80 + ks * 32 + aco));
                #pragma unroll
                for (int sb2 = 0; sb2 < 2 - sa; sb2++) {
                    uint32_t bf[4][2], r4[4];
                    ldsm4(r4, sb + (2 + sb2) * TILE_B +
                          (uint32_t)((wc * 32 + bro) * 80 + ks * 32 + bco));
                    bf[0][0] = r4[0]; bf[0][1] = r4[1];
                    bf[1][0] = r4[2]; bf[1][1] = r4[3];
                    ldsm4(r4, sb + (2 + sb2) * TILE_B +
                          (uint32_t)((wc * 32 + 16 + bro) * 80 + ks * 32 + bco));
                    bf[2][0] = r4[0]; bf[2][1] = r4[1];
                    bf[3][0] = r4[2]; bf[3][1] = r4[3];
                    #pragma unroll
                    for (int i = 0; i < 4; i++)
                        #pragma unroll
                        for (int j = 0; j < 4; j++)
                            mma16816(acc[i][j], af[i][0], af[i][1], af[i][2],
                                     af[i][3], bf[j][0], bf[j][1]);
                }
            }
        }
    }

    // ---------------- epilogue ----------------
    #pragma unroll
    for (int i = 0; i < 4; i++) {
        #pragma unroll
        for (int half = 0; half < 2; half++) {
            int gm = m0 + wr * 64 + i * 16 + gid + half * 8;
            if (gm >= M_TOT) continue;
            int btok = gm / N_, nt = gm % N_;
            #pragma unroll
            for (int j = 0; j < 4; j++) {
                float v0 = acc[i][j][half * 2];
                float v1 = acc[i][j][half * 2 + 1];
                int jg = n0 + wc * 32 + j * 8 + tig * 2;
                if (mode == 0) {
                    int qkv_i = jg / C_;
                    int rem = jg % C_;
                    int h = rem >> 6, d0 = rem & 63;
                    if (qkv_i == 0) { v0 *= SCLOG2E; v1 *= SCLOG2E; }
                    __nv_bfloat16* dh = (qkv_i == 0) ? g_qs[0]
                                        : (qkv_i == 1 ? g_ks[0] : g_vs[0]);
                    __nv_bfloat16* dl = (qkv_i == 0) ? g_qs[1]
                                        : (qkv_i == 1 ? g_ks[1] : g_vs[1]);
                    long base = ((long)(btok * H_ + h) * N_ + nt) * 64 + d0;
                    uint32_t hi, lo;
                    split_pack(v0, v1, hi, lo);
                    *(uint32_t*)&dh[base] = hi;
                    *(uint32_t*)&dl[base] = lo;
                } else {
                    long base = OFF_OUT + (long)gm * C_ + jg;
                    *(float2*)&out[base] = make_float2(v0 + bias[jg], v1 + bias[jg + 1]);
                }
            }
        }
    }
}

// ======================================================================
// mma.sync flash attention. Dedicated Q smem region (Q fragments reloaded
// per tile -> fewer live regs), __launch_bounds__(256,2) => 2 CTAs/SM.
// Pre-split bf16 q/k/v (q pre-scaled -> exp2f), ldmatrix (+trans for V),
// cp.async double buffer, hoisted CSA mask, per-warp tile skip.
// Writes ctx directly as bf16 2-splits.
// SMEM: Q0 @0, Q1 @18432; stages @36864 + s*36864 (K0,K1,V0,V1 x 64x144B).
// ======================================================================
#define TILE_A  9216
#define STAGE_A (4 * TILE_A)             // 36864 B per stage
#define QREG_B  (2 * 128 * 144)          // 36864 B (Q hi+lo)
#define ATTN_SMEM3 (QREG_B + 2 * STAGE_A)  // 110592 B

__global__ void __launch_bounds__(256, 2)
attn_mma() {
    extern __shared__ __align__(16) uint32_t asw[];
    const uint32_t smb = (uint32_t)__cvta_generic_to_shared(asw);
    const int tid = threadIdx.x;
    const int wid = tid >> 5, lane = tid & 31;
    const int gid = lane >> 2, tig = lane & 3;
    const int bh = blockIdx.y;
    const int q0g = blockIdx.x * 128;

    const int lr = lane & 7;
    const int aro = lr + ((lane >> 3) & 1) * 8;
    const int aco = (lane >> 4) * 16;
    const int bro = lr + (lane >> 4) * 8;
    const int bco = ((lane >> 3) & 1) * 16;
    const int vro = lr + ((lane >> 3) & 1) * 8;
    const int vco = (lane >> 4) * 16;

    const __nv_bfloat16* Qh = g_qs[0] + (long)bh * N_ * 64;
    const __nv_bfloat16* Ql = g_qs[1] + (long)bh * N_ * 64;
    const __nv_bfloat16* Kh = g_ks[0] + (long)bh * N_ * 64;
    const __nv_bfloat16* Kl = g_ks[1] + (long)bh * N_ * 64;
    const __nv_bfloat16* Vh = g_vs[0] + (long)bh * N_ * 64;
    const __nv_bfloat16* Vl = g_vs[1] + (long)bh * N_ * 64;

    // ---- stage Q splits into dedicated region (persistent) ----
    {
        __nv_bfloat16* Q0 = (__nv_bfloat16*)asw;
        __nv_bfloat16* Q1 = (__nv_bfloat16*)((char*)asw + 18432);
        for (int idx = tid; idx < 128 * 8; idx += 256) {
            int r = idx >> 3, c = idx & 7;
            int qi = q0g + r;
            uint4 vh = make_uint4(0, 0, 0, 0), vl = vh;
            if (qi < N_) {
                vh = *(const uint4*)(Qh + (long)qi * 64 + c * 8);
                vl = *(const uint4*)(Ql + (long)qi * 64 + c * 8);
            }
            *(uint4*)(Q0 + r * 72 + c * 8) = vh;
            *(uint4*)(Q1 + r * 72 + c * 8) = vl;
        }
    }

    float accD[8][4];
    #pragma unroll
    for (int dt = 0; dt < 8; dt++)
        #pragma unroll
        for (int r = 0; r < 4; r++) accD[dt][r] = 0.f;
    float m2[2] = {-INFINITY, -INFINITY};
    float l2[2] = {0.f, 0.f};

    // per-warp row-block data (hoisted out of the kt loop)
    const int rlo = q0g + wid * 16;
    const bool w_dead = (rlo >= N_);
    bool wq_uni = false; int wqb = -2;
    int wblk_lo = 5, wblk_hi = -5;
    if (!w_dead) {
        int rhi = min(rlo + 15, N_ - 1);
        int blo = (max(rlo, 1) - 1) >> 8;
        int bhi = (rhi >= 1) ? ((rhi - 1) >> 8) : -1;
        wblk_lo = blo; wblk_hi = bhi;
        if (rlo >= 1 && blo == bhi) { wq_uni = true; wqb = blo; }
    }
    const int row0g = rlo + gid, row1g = rlo + gid + 8;
    const int qb0 = (row0g >= 1 && row0g < N_) ? ((row0g - 1) >> 8) : -1;
    const int qb1 = (row1g >= 1 && row1g < N_) ? ((row1g - 1) >> 8) : -1;

    auto stagea = [&](int kt_, int bufi) {
        const int k0 = kt_ * 64;
        const uint32_t sb = smb + QREG_B + bufi * STAGE_A;
        const __nv_bfloat16* srcs[4] = {Kh, Kl, Vh, Vl};
        #pragma unroll
        for (int t = 0; t < 8; t++) {
            int idx = tid + t * 256;
            int a = idx >> 9, r = (idx >> 3) & 63, c = idx & 7;
            int kj = k0 + r;
            const __nv_bfloat16* src = srcs[a] + (long)kj * 64 + c * 8;
            cpa16(sb + a * TILE_A + r * 144 + c * 16, src, (kj < N_) ? 16 : 0);
        }
    };

    stagea(0, 0);
    CP_COMMIT();
    __syncthreads();     // Q region ready for all warps

    for (int kt = 0; kt < 17; kt++) {
        const int k0g = kt * 64;
        __syncthreads();
        if (kt + 1 < 17) stagea(kt + 1, (kt + 1) & 1);
        CP_COMMIT();
        CP_WAIT1();
        __syncthreads();

        // tile classification (warp-uniform)
        bool skip = w_dead;
        bool need_mask = false;
        if (!skip) {
            int klo = max(k0g, 1), khi = min(k0g + 63, N_ - 1);
            int kbl = (klo - 1) >> 8, kbh = (khi - 1) >> 8;
            if (wq_uni && k0g >= 1 && kbl == kbh && kbl == wqb) skip = true;
            else need_mask = (k0g + 63 >= N_) ||
                             (kbl <= wblk_hi && kbh >= wblk_lo);
        }
        if (skip) continue;

        const uint32_t sb = smb + QREG_B + (kt & 1) * STAGE_A;

        // ---- S = Q K^T (3 products); Q frags reloaded per ks ----
        float sp[8][4];
        #pragma unroll
        for (int nt = 0; nt < 8; nt++)
            #pragma unroll
            for (int r = 0; r < 4; r++) sp[nt][r] = 0.f;

        #pragma unroll
        for (int ks = 0; ks < 4; ks++) {
            uint32_t qh4[4], ql4[4];
            uint32_t qoff = (uint32_t)((wid * 16 + aro) * 144 + ks * 32 + aco);
            ldsm4(qh4, smb + qoff);
            ldsm4(ql4, smb + 18432 + qoff);
            #pragma unroll
            for (int ntp = 0; ntp < 4; ntp++) {
                uint32_t rowb = (uint32_t)((ntp * 16 + bro) * 144 + ks * 32 + bco);
                uint32_t h4[4], l4[4];
                ldsm4(h4, sb + rowb);
                ldsm4(l4, sb + TILE_A + rowb);
                mma16816(sp[2*ntp], qh4[0], qh4[1], qh4[2], qh4[3], h4[0], h4[1]);
                mma16816(sp[2*ntp], ql4[0], ql4[1], ql4[2], ql4[3], h4[0], h4[1]);
                mma16816(sp[2*ntp], qh4[0], qh4[1], qh4[2], qh4[3], l4[0], l4[1]);
                mma16816(sp[2*ntp+1], qh4[0], qh4[1], qh4[2], qh4[3], h4[2], h4[3]);
                mma16816(sp[2*ntp+1], ql4[0], ql4[1], ql4[2], ql4[3], h4[2], h4[3]);
                mma16816(sp[2*ntp+1], qh4[0], qh4[1], qh4[2], qh4[3], l4[2], l4[3]);
            }
        }

        // ---- CSA mask (only on flagged tiles; scale folded into Q) ----
        if (need_mask) {
            #pragma unroll
            for (int nt = 0; nt < 8; nt++) {
                #pragma unroll
                for (int c = 0; c < 4; c++) {
                    int qb = (c >= 2) ? qb1 : qb0;
                    int key = k0g + nt * 8 + 2 * tig + (c & 1);
                    bool bad = (key >= N_) ||
                               (qb >= 0 && key >= 1 && ((key - 1) >> 8) == qb);
                    if (bad) sp[nt][c] = -INFINITY;
                }
            }
        }

        // ---- online softmax in log2 domain (per half: rows gid, gid+8) ----
        #pragma unroll
        for (int half = 0; half < 2; half++) {
            float mx = -INFINITY;
            #pragma unroll
            for (int nt = 0; nt < 8; nt++)
                mx = fmaxf(mx, fmaxf(sp[nt][half*2], sp[nt][half*2+1]));
            mx = fmaxf(mx, __shfl_xor_sync(0xffffffffu, mx, 1));
            mx = fmaxf(mx, __shfl_xor_sync(0xffffffffu, mx, 2));
            float mnew = fmaxf(m2[half], mx);
            float corr = exp2f(m2[half] - mnew);
            m2[half] = mnew;
            float rs = 0.f;
            #pragma unroll
            for (int nt = 0; nt < 8; nt++) {
                float p0 = exp2f(sp[nt][half*2]   - mnew);
                float p1 = exp2f(sp[nt][half*2+1] - mnew);
                sp[nt][half*2] = p0; sp[nt][half*2+1] = p1;
                rs += p0 + p1;
            }
            rs += __shfl_xor_sync(0xffffffffu, rs, 1);
            rs += __shfl_xor_sync(0xffffffffu, rs, 2);
            l2[half] = l2[half] * corr + rs;
            #pragma unroll
            for (int dt = 0; dt < 8; dt++) {
                accD[dt][half*2]   *= corr;
                accD[dt][half*2+1] *= corr;
            }
        }

        // ---- O += P V (3 products), ldmatrix.trans V fragments ----
        #pragma unroll
        for (int ks = 0; ks < 4; ks++) {
            uint32_t p0[4], p1[4];
            split_pack(sp[2*ks][0],   sp[2*ks][1],   p0[0], p1[0]);
            split_pack(sp[2*ks][2],   sp[2*ks][3],   p0[1], p1[1]);
            split_pack(sp[2*ks+1][0], sp[2*ks+1][1], p0[2], p1[2]);
            split_pack(sp[2*ks+1][2], sp[2*ks+1][3], p0[3], p1[3]);
            #pragma unroll
            for (int dtp = 0; dtp < 4; dtp++) {
                uint32_t rowb = (uint32_t)((ks * 16 + vro) * 144 + dtp * 32 + vco);
                uint32_t h4[4], l4[4];
                ldsm4t(h4, sb + 2 * TILE_A + rowb);
                ldsm4t(l4, sb + 3 * TILE_A + rowb);
                mma16816(accD[2*dtp], p0[0], p0[1], p0[2], p0[3], h4[0], h4[1]);
                mma16816(accD[2*dtp], p1[0], p1[1], p1[2], p1[3], h4[0], h4[1]);
                mma16816(accD[2*dtp], p0[0], p0[1], p0[2], p0[3], l4[0], l4[1]);
                mma16816(accD[2*dtp+1], p0[0], p0[1], p0[2], p0[3], h4[2], h4[3]);
                mma16816(accD[2*dtp+1], p1[0], p1[1], p1[2], p1[3], h4[2], h4[3]);
                mma16816(accD[2*dtp+1], p0[0], p0[1], p0[2], p0[3], l4[2], l4[3]);
            }
        }
    }

    // ---- epilogue: write ctx directly as bf16 2-splits ----
    const int b = bh / H_, h = bh % H_;
    #pragma unroll
    for (int half = 0; half < 2; half++) {
        int row = rlo + gid + half * 8;
        if (row < N_) {
            float inv = 1.f / l2[half];
            #pragma unroll
            for (int dt = 0; dt < 8; dt++) {
                int d = dt * 8 + 2 * tig;
                long base = ((long)b * N_ + row) * C_ + h * 64 + d;
                uint32_t hi, lo;
                split_pack(accD[dt][half*2] * inv, accD[dt][half*2+1] * inv, hi, lo);
                *(uint32_t*)&g_cs[0][base] = hi;
                *(uint32_t*)&g_cs[1][base] = lo;
            }
        }
    }
}

// ======================================================================
// cls per-head softmax row -- GEMM-independent (raw inputs), high precision.
// ======================================================================
__global__ void __launch_bounds__(1024)
cls_head_kernel(const float* __restrict__ x, const float* __restrict__ w) {
    __shared__ double q0s[64];
    __shared__ float uhi[C_], ulo[C_];
    __shared__ double s[N_];
    __shared__ double red[32];
    const int bh = blockIdx.x;
    const int b = bh / H_, h = bh % H_;
    const int tid = threadIdx.x;
    const int wid = tid >> 5, lane = tid & 31;

    const float* xb = x + (long)b * N_ * C_;
    const float* wq = w + (long)(h * 64) * C_;
    const float* wk = w + (long)(C_ + h * 64) * C_;

    for (int d = wid; d < 64; d += 32) {
        double a = 0.0;
        for (int c = lane; c < C_; c += 32)
            a += (double)xb[c] * (double)wq[(long)d * C_ + c];
        #pragma unroll
        for (int o = 16; o >= 1; o >>= 1)
            a += __shfl_xor_sync(0xffffffffu, a, o);
        if (lane == 0) q0s[d] = a;
    }
    __syncthreads();

    for (int c = tid; c < C_; c += 1024) {
        double a = 0.0;
        #pragma unroll 8
        for (int d = 0; d < 64; d++)
            a += q0s[d] * (double)wk[(long)d * C_ + c];
        a *= 0.125;
        float hi = (float)a;
        uhi[c] = hi;
        ulo[c] = (float)(a - (double)hi);
    }
    __syncthreads();

    for (int j = wid; j < N_; j += 32) {
        const float* xr = xb + (long)j * C_;
        float sum = 0.f, comp = 0.f, err = 0.f;
        #pragma unroll 2
        for (int c = lane * 4; c < C_; c += 128) {
            float4 xv = *(const float4*)&xr[c];
            float4 uh = *(const float4*)&uhi[c];
            float4 ul = *(const float4*)&ulo[c];
            #pragma unroll
            for (int e4 = 0; e4 < 4; e4++) {
                float xe = (&xv.x)[e4], he = (&uh.x)[e4], le = (&ul.x)[e4];
                float p = he * xe;
                err = fmaf(he, xe, -p) + err;
                err = fmaf(le, xe, err);
                float y = p - comp;
                float t = sum + y;
                comp = (t - sum) - y;
                sum = t;
            }
        }
        double tot = ((double)sum - (double)comp) + (double)err;
        #pragma unroll
        for (int o = 16; o >= 1; o >>= 1)
            tot += __shfl_xor_sync(0xffffffffu, tot, o);
        if (lane == 0) s[j] = tot;
    }
    __syncthreads();

    double lm = -1e300;
    for (int j = tid; j < N_; j += 1024) lm = fmax(lm, s[j]);
    #pragma unroll
    for (int o = 16; o >= 1; o >>= 1)
        lm = fmax(lm, __shfl_xor_sync(0xffffffffu, lm, o));
    if (lane == 0) red[wid] = lm;
    __syncthreads();
    if (wid == 0) {
        double t = red[lane];
        #pragma unroll
        for (int o = 16; o >= 1; o >>= 1)
            t = fmax(t, __shfl_xor_sync(0xffffffffu, t, o));
        if (lane == 0) red[0] = t;
    }
    __syncthreads();
    const double m = red[0];
    __syncthreads();

    double ls = 0.0;
    for (int j = tid; j < N_; j += 1024) {
        double e = exp(s[j] - m);
        s[j] = e;
        ls += e;
    }
    #pragma unroll
    for (int o = 16; o >= 1; o >>= 1)
        ls += __shfl_xor_sync(0xffffffffu, ls, o);
    if (lane == 0) red[wid] = ls;
    __syncthreads();
    if (wid == 0) {
        double t = red[lane];
        #pragma unroll
        for (int o = 16; o >= 1; o >>= 1)
            t += __shfl_xor_sync(0xffffffffu, t, o);
        if (lane == 0) red[0] = t;
    }
    __syncthreads();
    const double inv = 1.0 / red[0];

    for (int j = tid; j < N_ - 1; j += 1024)
        g_cls_ph[bh][j] = s[j + 1] * inv;
}

// ======================================================================
// head-mean reduce (fp64, h-ascending). One CTA per batch.
// ======================================================================
__global__ void cls_reduce_kernel(float* __restrict__ out) {
    const int b = blockIdx.x, tid = threadIdx.x;
    for (int j = tid; j < N_ - 1; j += 256) {
        double a = 0.0;
        #pragma unroll
        for (int h = 0; h < H_; h++)
            a += g_cls_ph[b * H_ + h][j] * (1.0 / 12.0);
        g_clsd[b * (N_ - 1) + j] = a;
        out[OFF_CLS + (long)b * (N_ - 1) + j] = (float)a;
    }
}

// ======================================================================
// dual bitonic top-k (103 of 1024) on fp64 keys, jax tie-break.
// ======================================================================
__global__ void sort_kernel(float* __restrict__ out) {
    __shared__ double v[1024];
    __shared__ int ix[1024];
    const int b = blockIdx.x, tid = threadIdx.x;

    for (int pass = 0; pass < 2; pass++) {
        __syncthreads();
        for (int i = tid; i < 1024; i += 512) {
            v[i] = g_clsd[b * 1024 + i];
            ix[i] = i;
        }
        __syncthreads();
        const bool desc = (pass == 0);
        for (int k = 2; k <= 1024; k <<= 1) {
            for (int j = k >> 1; j > 0; j >>= 1) {
                for (int i = tid; i < 1024; i += 512) {
                    int p = i ^ j;
                    if (p > i) {
                        double va = v[i], vb = v[p];
                        int ia = ix[i], ib = ix[p];
                        bool ab = desc ? (va > vb || (va == vb && ia < ib))
                                       : (va < vb || (va == vb && ia < ib));
                        bool up = ((i & k) == 0);
                        if (up ? !ab : ab) {
                            v[i] = vb; v[p] = va;
                            ix[i] = ib; ix[p] = ia;
                        }
                    }
                }
                __syncthreads();
            }
        }
        const long offIdx = desc ? OFF_ENH_IDX : OFF_FUSE_IDX;
        const long offBrd = desc ? OFF_ENH_INDEX : OFF_FUSE_INDEX;
        for (int t = tid; t < TOPT; t += 512)
            out[offIdx + (long)b * TOPT + t] = (float)ix[t];
        for (int e = tid; e < TOPT * C_; e += 512) {
            int t = e / C_;
            out[offBrd + ((long)b * TOPT + t) * C_ + (e % C_)] = (float)ix[t];
        }
    }
}

// ======================================================================
// Launch
// ======================================================================
extern "C" void kernel_launch(void* const* d_in, const int* in_sizes, int n_in,
                              void* d_out, int out_size) {
    const float* x     = (const float*)d_in[0];
    const float* w_qkv = (const float*)d_in[1];
    const float* w_out = (const float*)d_in[2];
    const float* b_out = (const float*)d_in[3];
    float* out = (float*)d_out;

    cudaFuncSetAttribute(mma_gemm, cudaFuncAttributeMaxDynamicSharedMemorySize,
                         MMA_SMEM);
    cudaFuncSetAttribute(attn_mma, cudaFuncAttributeMaxDynamicSharedMemorySize,
                         ATTN_SMEM3);

    __nv_bfloat16 *xs0, *xs1, *ws0, *ws1, *wo0, *wo1, *cs0, *cs1;
    cudaGetSymbolAddress((void**)&xs0, g_xs); xs1 = xs0 + (long)M_TOT*C_;
    cudaGetSymbolAddress((void**)&ws0, g_ws); ws1 = ws0 + (long)3*C_*C_;
    cudaGetSymbolAddress((void**)&wo0, g_wo); wo1 = wo0 + (long)C_*C_;
    cudaGetSymbolAddress((void**)&cs0, g_cs); cs1 = cs0 + (long)M_TOT*C_;

    split2<<<(M_TOT*C_ + 255)/256, 256>>>(x, xs0, xs1, M_TOT*C_);
    split2<<<(3*C_*C_ + 255)/256, 256>>>(w_qkv, ws0, ws1, 3*C_*C_);
    split2<<<(C_*C_ + 255)/256, 256>>>(w_out, wo0, wo1, C_*C_);

    // QKV: [4100,2304] = x @ w_qkv^T, writes bf16 q/k/v splits (q pre-scaled)
    mma_gemm<<<dim3(3*C_/128, (M_TOT + 127)/128), 256, MMA_SMEM>>>(
        xs0, xs1, ws0, ws1, 0, b_out, out);

    // attention -> ctx bf16 splits directly
    attn_mma<<<dim3((N_ + 127)/128, B_ * H_), 256, ATTN_SMEM3>>>();

    // OUT: [4100,768] = ctx @ w_out^T + bias
    mma_gemm<<<dim3(C_/128, (M_TOT + 127)/128), 256, MMA_SMEM>>>(
        cs0, cs1, wo0, wo1, 1, b_out, out);

    // cls path: high-precision from raw inputs (GEMM-independent)
    cls_head_kernel<<<B_ * H_, 1024>>>(x, w_qkv);
    cls_reduce_kernel<<<B_, 256>>>(out);
    sort_kernel<<<B_, 512>>>(out);
}

// round 14
// speedup vs baseline: 3.0307x; 1.1680x over previous
#include <cuda_runtime.h>
#include <cuda_bf16.h>
#include <math.h>
#include <cstdint>

// ---------------- Problem constants ----------------
#define B_ 4
#define N_ 1025
#define C_ 768
#define H_ 12
#define D_ 64
#define TOPT 103
#define SCALEF 0.125f            // 64^-0.5
#define SCLOG2E (0.125f * 1.4426950408889634f)   // fold scale * log2(e) into Q

#define M_TOT (B_ * N_)          // 4100

// Output layout (float32, reference tuple flattened & concatenated):
#define OFF_OUT        0L
#define OFF_ENH_INDEX  3148800L
#define OFF_ENH_IDX    3465216L
#define OFF_FUSE_INDEX 3465628L
#define OFF_FUSE_IDX   3782044L
#define OFF_CLS        3782456L

// ---------------- Scratch (no allocation allowed) ----------------
__device__ double g_clsd[B_*(N_-1)];
__device__ double g_cls_ph[B_*H_][N_-1];
__device__ double g_cls_s[B_*H_][N_];     // raw cls scores (fp64-accurate)

// bf16 2-way splits
__device__ __nv_bfloat16 g_xs[2][M_TOT*C_];
__device__ __nv_bfloat16 g_ws[2][3*C_*C_];     // w_qkv [2304,768]
__device__ __nv_bfloat16 g_wo[2][C_*C_];       // w_out [768,768]
__device__ __nv_bfloat16 g_cs[2][M_TOT*C_];    // ctx splits (written by attn)
// q/k/v as bf16 splits, [b,h,n,d]; q pre-scaled by SCALE*log2e
__device__ __nv_bfloat16 g_qs[2][B_*H_*N_*D_];
__device__ __nv_bfloat16 g_ks[2][B_*H_*N_*D_];
__device__ __nv_bfloat16 g_vs[2][B_*H_*N_*D_];

// ================= helpers =================
__device__ __forceinline__ void ldsm4(uint32_t* r, uint32_t addr) {
    asm volatile("ldmatrix.sync.aligned.m8n8.x4.shared.b16 {%0,%1,%2,%3}, [%4];"
        : "=r"(r[0]), "=r"(r[1]), "=r"(r[2]), "=r"(r[3]) : "r"(addr));
}
__device__ __forceinline__ void ldsm4t(uint32_t* r, uint32_t addr) {
    asm volatile("ldmatrix.sync.aligned.m8n8.x4.trans.shared.b16 {%0,%1,%2,%3}, [%4];"
        : "=r"(r[0]), "=r"(r[1]), "=r"(r[2]), "=r"(r[3]) : "r"(addr));
}
__device__ __forceinline__ void mma16816(float c[4], uint32_t a0, uint32_t a1,
                                         uint32_t a2, uint32_t a3,
                                         uint32_t b0, uint32_t b1) {
    asm volatile(
        "mma.sync.aligned.m16n8k16.row.col.f32.bf16.bf16.f32 "
        "{%0,%1,%2,%3}, {%4,%5,%6,%7}, {%8,%9}, {%0,%1,%2,%3};"
        : "+f"(c[0]), "+f"(c[1]), "+f"(c[2]), "+f"(c[3])
        : "r"(a0), "r"(a1), "r"(a2), "r"(a3), "r"(b0), "r"(b1));
}
__device__ __forceinline__ void cpa16(uint32_t dst, const void* src, int sz) {
    asm volatile("cp.async.cg.shared.global [%0], [%1], 16, %2;"
        :: "r"(dst), "l"(src), "r"(sz));
}
#define CP_COMMIT() asm volatile("cp.async.commit_group;" ::: "memory")
#define CP_WAIT1()  asm volatile("cp.async.wait_group 1;" ::: "memory")
// fp32 pair -> bf16x2 (hi split) + bf16x2 (residual split); RN rounding,
// identical results to the scalar __float2bfloat16 version.
__device__ __forceinline__ void split_pack(float x, float y,
                                           uint32_t& hi, uint32_t& lo) {
    asm("cvt.rn.bf16x2.f32 %0, %1, %2;" : "=r"(hi) : "f"(y), "f"(x));
    float fx = __uint_as_float(hi << 16);
    float fy = __uint_as_float(hi & 0xFFFF0000u);
    asm("cvt.rn.bf16x2.f32 %0, %1, %2;" : "=r"(lo) : "f"(y - fy), "f"(x - fx));
}

// ======================================================================
// Split kernel: fp32 -> 2 bf16 splits (residual ~2^-16)
// ======================================================================
__global__ void split2(const float* __restrict__ src,
                       __nv_bfloat16* __restrict__ d0,
                       __nv_bfloat16* __restrict__ d1, int n) {
    int i = blockIdx.x * blockDim.x + threadIdx.x;
    if (i < n) {
        float x = src[i];
        __nv_bfloat16 b0 = __float2bfloat16(x);
        d0[i] = b0;
        d1[i] = __float2bfloat16(x - __bfloat162float(b0));
    }
}

// ======================================================================
// GEMM constants
// ======================================================================
#define TILE_B  (128 * 80)               // 10240 B per split tile (80B rows)
#define STAGE_G (4 * TILE_B)             // 40960 B per stage
#define MMA_SMEM (2 * STAGE_G)           // 81920 B
#define CLS_BLOCKS 192                   // 48 bh x 4 j-chunks
#define QKV_BLOCKS 594                   // 18 x 33

// ---------------- cls score chunk (runs inside fused launch) ----------
// Computes s_j = 0.125*(W_k,h^T (W_q,h x_{b,0})) . x_{b,j} for a j-chunk,
// fp64 phases 1-2 + Kahan-compensated fp32 phase 3 (identical math/order
// to the previous cls_head_kernel), result to g_cls_s.
__device__ void cls_chunk_body(const float* __restrict__ x,
                               const float* __restrict__ w, char* smem) {
    double* q0s = (double*)smem;               // 64 doubles
    float* uhi = (float*)(smem + 512);         // 768 floats
    float* ulo = (float*)(smem + 512 + 3072);  // 768 floats
    const int id = blockIdx.x;
    const int bh = id >> 2, chunk = id & 3;
    const int b = bh / H_, h = bh % H_;
    const int tid = threadIdx.x;
    const int wid = tid >> 5, lane = tid & 31;

    const float* xb = x + (long)b * N_ * C_;
    const float* wq = w + (long)(h * 64) * C_;
    const float* wk = w + (long)(C_ + h * 64) * C_;

    // phase 1: q0[d] fp64 (warp per d)
    for (int d = wid; d < 64; d += 8) {
        double a = 0.0;
        for (int c = lane; c < C_; c += 32)
            a += (double)xb[c] * (double)wq[(long)d * C_ + c];
        #pragma unroll
        for (int o = 16; o >= 1; o >>= 1)
            a += __shfl_xor_sync(0xffffffffu, a, o);
        if (lane == 0) q0s[d] = a;
    }
    __syncthreads();

    // phase 2: u[c] = 0.125 * sum_d q0[d]*wk[d][c] (fp64), hi/lo fp32
    for (int c = tid; c < C_; c += 256) {
        double a = 0.0;
        #pragma unroll 8
        for (int d = 0; d < 64; d++)
            a += q0s[d] * (double)wk[(long)d * C_ + c];
        a *= 0.125;
        float hi = (float)a;
        uhi[c] = hi;
        ulo[c] = (float)(a - (double)hi);
    }
    __syncthreads();

    // phase 3: s[j] for this chunk, warp-per-j compensated fp32
    const int jlo = chunk * 257;
    const int jhi = min(jlo + 257, N_);
    for (int j = jlo + wid; j < jhi; j += 8) {
        const float* xr = xb + (long)j * C_;
        float sum = 0.f, comp = 0.f, err = 0.f;
        #pragma unroll 2
        for (int c = lane * 4; c < C_; c += 128) {
            float4 xv = *(const float4*)&xr[c];
            float4 uh = *(const float4*)&uhi[c];
            float4 ul = *(const float4*)&ulo[c];
            #pragma unroll
            for (int e4 = 0; e4 < 4; e4++) {
                float xe = (&xv.x)[e4], he = (&uh.x)[e4], le = (&ul.x)[e4];
                float p = he * xe;
                err = fmaf(he, xe, -p) + err;
                err = fmaf(le, xe, err);
                float y = p - comp;
                float t = sum + y;
                comp = (t - sum) - y;
                sum = t;
            }
        }
        double tot = ((double)sum - (double)comp) + (double)err;
        #pragma unroll
        for (int o = 16; o >= 1; o >>= 1)
            tot += __shfl_xor_sync(0xffffffffu, tot, o);
        if (lane == 0) g_cls_s[bh][j] = tot;
    }
}

// ======================================================================
// Fused: blocks [0,192) = cls score chunks; blocks [192,786) = QKV GEMM
// (2-split/3-product mma.sync, ldmatrix, cp.async double buffer; writes
// q/k/v bf16 splits, q pre-scaled by SCALE*log2e).
// ======================================================================
__global__ void __launch_bounds__(256, 2)
fused_qkv_cls(const __nv_bfloat16* __restrict__ A0,
              const __nv_bfloat16* __restrict__ A1,
              const __nv_bfloat16* __restrict__ B0,
              const __nv_bfloat16* __restrict__ B1,
              const float* __restrict__ x, const float* __restrict__ w) {
    extern __shared__ __align__(16) char smem[];
    if (blockIdx.x < CLS_BLOCKS) {
        cls_chunk_body(x, w, smem);
        return;
    }
    const uint32_t smb = (uint32_t)__cvta_generic_to_shared(smem);
    const int bidx = blockIdx.x - CLS_BLOCKS;
    const int m0 = (bidx / 18) * 128;
    const int n0 = (bidx % 18) * 128;
    const int tid = threadIdx.x;
    const int wid = tid >> 5, lane = tid & 31;
    const int gid = lane >> 2, tig = lane & 3;
    const int wr = wid >> 2, wc = wid & 3;

    const int lr = lane & 7;
    const int aro = lr + ((lane >> 3) & 1) * 8;
    const int aco = (lane >> 4) * 16;
    const int bro = lr + (lane >> 4) * 8;
    const int bco = ((lane >> 3) & 1) * 16;

    const __nv_bfloat16* Asrc[2] = {A0, A1};
    const __nv_bfloat16* Bsrc[2] = {B0, B1};

    float acc[4][4][4];
    #pragma unroll
    for (int i = 0; i < 4; i++)
        #pragma unroll
        for (int j = 0; j < 4; j++)
            #pragma unroll
            for (int r = 0; r < 4; r++) acc[i][j][r] = 0.f;

    auto stageg = [&](int kb_, int bufi) {
        const int kcol = kb_ * 32;
        const uint32_t sb = smb + bufi * STAGE_G;
        #pragma unroll
        for (int t = 0; t < 8; t++) {
            int idx = tid + t * 256;
            int a = idx >> 9;
            int r = (idx >> 2) & 127, c = idx & 3;
            const __nv_bfloat16* src;
            int sz = 16;
            if (a < 2) {
                src = Asrc[a] + (long)(m0 + r) * C_ + kcol + c * 8;
                if (m0 + r >= M_TOT) sz = 0;
            } else {
                src = Bsrc[a - 2] + (long)(n0 + r) * C_ + kcol + c * 8;
            }
            cpa16(sb + a * TILE_B + r * 80 + c * 16, src, sz);
        }
    };

    stageg(0, 0);
    CP_COMMIT();

    for (int kb = 0; kb < 24; kb++) {
        __syncthreads();
        if (kb + 1 < 24) stageg(kb + 1, (kb + 1) & 1);
        CP_COMMIT();
        CP_WAIT1();
        __syncthreads();

        const uint32_t sb = smb + (kb & 1) * STAGE_G;
        #pragma unroll
        for (int ks = 0; ks < 2; ks++) {
            #pragma unroll
            for (int sa = 0; sa < 2; sa++) {
                uint32_t af[4][4];
                #pragma unroll
                for (int i = 0; i < 4; i++)
                    ldsm4(af[i], sb + sa * TILE_B +
                          (uint32_t)((wr * 64 + i * 16 + aro) * 80 + ks * 32 + aco));
                #pragma unroll
                for (int sb2 = 0; sb2 < 2 - sa; sb2++) {
                    uint32_t bf[4][2], r4[4];
                    ldsm4(r4, sb + (2 + sb2) * TILE_B +
                          (uint32_t)((wc * 32 + bro) * 80 + ks * 32 + bco));
                    bf[0][0] = r4[0]; bf[0][1] = r4[1];
                    bf[1][0] = r4[2]; bf[1][1] = r4[3];
                    ldsm4(r4, sb + (2 + sb2) * TILE_B +
                          (uint32_t)((wc * 32 + 16 + bro) * 80 + ks * 32 + bco));
                    bf[2][0] = r4[0]; bf[2][1] = r4[1];
                    bf[3][0] = r4[2]; bf[3][1] = r4[3];
                    #pragma unroll
                    for (int i = 0; i < 4; i++)
                        #pragma unroll
                        for (int j = 0; j < 4; j++)
                            mma16816(acc[i][j], af[i][0], af[i][1], af[i][2],
                                     af[i][3], bf[j][0], bf[j][1]);
                }
            }
        }
    }

    // epilogue: scatter q/k/v bf16 splits (q pre-scaled)
    #pragma unroll
    for (int i = 0; i < 4; i++) {
        #pragma unroll
        for (int half = 0; half < 2; half++) {
            int gm = m0 + wr * 64 + i * 16 + gid + half * 8;
            if (gm >= M_TOT) continue;
            int btok = gm / N_, nt = gm % N_;
            #pragma unroll
            for (int j = 0; j < 4; j++) {
                float v0 = acc[i][j][half * 2];
                float v1 = acc[i][j][half * 2 + 1];
                int jg = n0 + wc * 32 + j * 8 + tig * 2;
                int qkv_i = jg / C_;
                int rem = jg % C_;
                int h = rem >> 6, d0 = rem & 63;
                if (qkv_i == 0) { v0 *= SCLOG2E; v1 *= SCLOG2E; }
                __nv_bfloat16* dh = (qkv_i == 0) ? g_qs[0]
                                    : (qkv_i == 1 ? g_ks[0] : g_vs[0]);
                __nv_bfloat16* dl = (qkv_i == 0) ? g_qs[1]
                                    : (qkv_i == 1 ? g_ks[1] : g_vs[1]);
                long base = ((long)(btok * H_ + h) * N_ + nt) * 64 + d0;
                uint32_t hi, lo;
                split_pack(v0, v1, hi, lo);
                *(uint32_t*)&dh[base] = hi;
                *(uint32_t*)&dl[base] = lo;
            }
        }
    }
}

// ======================================================================
// out projection GEMM (mode-1 path of the old mma_gemm)
// ======================================================================
__global__ void __launch_bounds__(256, 2)
out_gemm(const __nv_bfloat16* __restrict__ A0, const __nv_bfloat16* __restrict__ A1,
         const __nv_bfloat16* __restrict__ B0, const __nv_bfloat16* __restrict__ B1,
         const float* __restrict__ bias, float* __restrict__ out) {
    extern __shared__ __align__(16) char smem[];
    const uint32_t smb = (uint32_t)__cvta_generic_to_shared(smem);
    const int tid = threadIdx.x;
    const int wid = tid >> 5, lane = tid & 31;
    const int gid = lane >> 2, tig = lane & 3;
    const int wr = wid >> 2, wc = wid & 3;
    const int m0 = blockIdx.y * 128;
    const int n0 = blockIdx.x * 128;

    const int lr = lane & 7;
    const int aro = lr + ((lane >> 3) & 1) * 8;
    const int aco = (lane >> 4) * 16;
    const int bro = lr + (lane >> 4) * 8;
    const int bco = ((lane >> 3) & 1) * 16;

    const __nv_bfloat16* Asrc[2] = {A0, A1};
    const __nv_bfloat16* Bsrc[2] = {B0, B1};

    float acc[4][4][4];
    #pragma unroll
    for (int i = 0; i < 4; i++)
        #pragma unroll
        for (int j = 0; j < 4; j++)
            #pragma unroll
            for (int r = 0; r < 4; r++) acc[i][j][r] = 0.f;

    auto stageg = [&](int kb_, int bufi) {
        const int kcol = kb_ * 32;
        const uint32_t sb = smb + bufi * STAGE_G;
        #pragma unroll
        for (int t = 0; t < 8; t++) {
            int idx = tid + t * 256;
            int a = idx >> 9;
            int r = (idx >> 2) & 127, c = idx & 3;
            const __nv_bfloat16* src;
            int sz = 16;
            if (a < 2) {
                src = Asrc[a] + (long)(m0 + r) * C_ + kcol + c * 8;
                if (m0 + r >= M_TOT) sz = 0;
            } else {
                src = Bsrc[a - 2] + (long)(n0 + r) * C_ + kcol + c * 8;
            }
            cpa16(sb + a * TILE_B + r * 80 + c * 16, src, sz);
        }
    };

    stageg(0, 0);
    CP_COMMIT();

    for (int kb = 0; kb < 24; kb++) {
        __syncthreads();
        if (kb + 1 < 24) stageg(kb + 1, (kb + 1) & 1);
        CP_COMMIT();
        CP_WAIT1();
        __syncthreads();

        const uint32_t sb = smb + (kb & 1) * STAGE_G;
        #pragma unroll
        for (int ks = 0; ks < 2; ks++) {
            #pragma unroll
            for (int sa = 0; sa < 2; sa++) {
                uint32_t af[4][4];
                #pragma unroll
                for (int i = 0; i < 4; i++)
                    ldsm4(af[i], sb + sa * TILE_B +
                          (uint32_t)((wr * 64 + i * 16 + aro) * 80 + ks * 32 + aco));
                #pragma unroll
                for (int sb2 = 0; sb2 < 2 - sa; sb2++) {
                    uint32_t bf[4][2], r4[4];
                    ldsm4(r4, sb + (2 + sb2) * TILE_B +
                          (uint32_t)((wc * 32 + bro) * 80 + ks * 32 + bco));
                    bf[0][0] = r4[0]; bf[0][1] = r4[1];
                    bf[1][0] = r4[2]; bf[1][1] = r4[3];
                    ldsm4(r4, sb + (2 + sb2) * TILE_B +
                          (uint32_t)((wc * 32 + 16 + bro) * 80 + ks * 32 + bco));
                    bf[2][0] = r4[0]; bf[2][1] = r4[1];
                    bf[3][0] = r4[2]; bf[3][1] = r4[3];
                    #pragma unroll
                    for (int i = 0; i < 4; i++)
                        #pragma unroll
                        for (int j = 0; j < 4; j++)
                            mma16816(acc[i][j], af[i][0], af[i][1], af[i][2],
                                     af[i][3], bf[j][0], bf[j][1]);
                }
            }
        }
    }

    #pragma unroll
    for (int i = 0; i < 4; i++) {
        #pragma unroll
        for (int half = 0; half < 2; half++) {
            int gm = m0 + wr * 64 + i * 16 + gid + half * 8;
            if (gm >= M_TOT) continue;
            #pragma unroll
            for (int j = 0; j < 4; j++) {
                int jg = n0 + wc * 32 + j * 8 + tig * 2;
                long base = OFF_OUT + (long)gm * C_ + jg;
                *(float2*)&out[base] = make_float2(
                    acc[i][j][half*2]   + bias[jg],
                    acc[i][j][half*2+1] + bias[jg + 1]);
            }
        }
    }
}

// ======================================================================
// mma.sync flash attention (unchanged structure from R13; new split_pack).
// ======================================================================
#define TILE_A  9216
#define STAGE_A (4 * TILE_A)             // 36864 B per stage
#define QREG_B  (2 * 128 * 144)          // 36864 B (Q hi+lo)
#define ATTN_SMEM3 (QREG_B + 2 * STAGE_A)  // 110592 B

__global__ void __launch_bounds__(256, 2)
attn_mma() {
    extern __shared__ __align__(16) uint32_t asw[];
    const uint32_t smb = (uint32_t)__cvta_generic_to_shared(asw);
    const int tid = threadIdx.x;
    const int wid = tid >> 5, lane = tid & 31;
    const int gid = lane >> 2, tig = lane & 3;
    const int bh = blockIdx.y;
    const int q0g = blockIdx.x * 128;

    const int lr = lane & 7;
    const int aro = lr + ((lane >> 3) & 1) * 8;
    const int aco = (lane >> 4) * 16;
    const int bro = lr + (lane >> 4) * 8;
    const int bco = ((lane >> 3) & 1) * 16;
    const int vro = lr + ((lane >> 3) & 1) * 8;
    const int vco = (lane >> 4) * 16;

    const __nv_bfloat16* Qh = g_qs[0] + (long)bh * N_ * 64;
    const __nv_bfloat16* Ql = g_qs[1] + (long)bh * N_ * 64;
    const __nv_bfloat16* Kh = g_ks[0] + (long)bh * N_ * 64;
    const __nv_bfloat16* Kl = g_ks[1] + (long)bh * N_ * 64;
    const __nv_bfloat16* Vh = g_vs[0] + (long)bh * N_ * 64;
    const __nv_bfloat16* Vl = g_vs[1] + (long)bh * N_ * 64;

    {
        __nv_bfloat16* Q0 = (__nv_bfloat16*)asw;
        __nv_bfloat16* Q1 = (__nv_bfloat16*)((char*)asw + 18432);
        for (int idx = tid; idx < 128 * 8; idx += 256) {
            int r = idx >> 3, c = idx & 7;
            int qi = q0g + r;
            uint4 vh = make_uint4(0, 0, 0, 0), vl = vh;
            if (qi < N_) {
                vh = *(const uint4*)(Qh + (long)qi * 64 + c * 8);
                vl = *(const uint4*)(Ql + (long)qi * 64 + c * 8);
            }
            *(uint4*)(Q0 + r * 72 + c * 8) = vh;
            *(uint4*)(Q1 + r * 72 + c * 8) = vl;
        }
    }

    float accD[8][4];
    #pragma unroll
    for (int dt = 0; dt < 8; dt++)
        #pragma unroll
        for (int r = 0; r < 4; r++) accD[dt][r] = 0.f;
    float m2[2] = {-INFINITY, -INFINITY};
    float l2[2] = {0.f, 0.f};

    const int rlo = q0g + wid * 16;
    const bool w_dead = (rlo >= N_);
    bool wq_uni = false; int wqb = -2;
    int wblk_lo = 5, wblk_hi = -5;
    if (!w_dead) {
        int rhi = min(rlo + 15, N_ - 1);
        int blo = (max(rlo, 1) - 1) >> 8;
        int bhi = (rhi >= 1) ? ((rhi - 1) >> 8) : -1;
        wblk_lo = blo; wblk_hi = bhi;
        if (rlo >= 1 && blo == bhi) { wq_uni = true; wqb = blo; }
    }
    const int row0g = rlo + gid, row1g = rlo + gid + 8;
    const int qb0 = (row0g >= 1 && row0g < N_) ? ((row0g - 1) >> 8) : -1;
    const int qb1 = (row1g >= 1 && row1g < N_) ? ((row1g - 1) >> 8) : -1;

    auto stagea = [&](int kt_, int bufi) {
        const int k0 = kt_ * 64;
        const uint32_t sb = smb + QREG_B + bufi * STAGE_A;
        const __nv_bfloat16* srcs[4] = {Kh, Kl, Vh, Vl};
        #pragma unroll
        for (int t = 0; t < 8; t++) {
            int idx = tid + t * 256;
            int a = idx >> 9, r = (idx >> 3) & 63, c = idx & 7;
            int kj = k0 + r;
            const __nv_bfloat16* src = srcs[a] + (long)kj * 64 + c * 8;
            cpa16(sb + a * TILE_A + r * 144 + c * 16, src, (kj < N_) ? 16 : 0);
        }
    };

    stagea(0, 0);
    CP_COMMIT();
    __syncthreads();

    for (int kt = 0; kt < 17; kt++) {
        const int k0g = kt * 64;
        __syncthreads();
        if (kt + 1 < 17) stagea(kt + 1, (kt + 1) & 1);
        CP_COMMIT();
        CP_WAIT1();
        __syncthreads();

        bool skip = w_dead;
        bool need_mask = false;
        if (!skip) {
            int klo = max(k0g, 1), khi = min(k0g + 63, N_ - 1);
            int kbl = (klo - 1) >> 8, kbh = (khi - 1) >> 8;
            if (wq_uni && k0g >= 1 && kbl == kbh && kbl == wqb) skip = true;
            else need_mask = (k0g + 63 >= N_) ||
                             (kbl <= wblk_hi && kbh >= wblk_lo);
        }
        if (skip) continue;

        const uint32_t sb = smb + QREG_B + (kt & 1) * STAGE_A;

        float sp[8][4];
        #pragma unroll
        for (int nt = 0; nt < 8; nt++)
            #pragma unroll
            for (int r = 0; r < 4; r++) sp[nt][r] = 0.f;

        #pragma unroll
        for (int ks = 0; ks < 4; ks++) {
            uint32_t qh4[4], ql4[4];
            uint32_t qoff = (uint32_t)((wid * 16 + aro) * 144 + ks * 32 + aco);
            ldsm4(qh4, smb + qoff);
            ldsm4(ql4, smb + 18432 + qoff);
            #pragma unroll
            for (int ntp = 0; ntp < 4; ntp++) {
                uint32_t rowb = (uint32_t)((ntp * 16 + bro) * 144 + ks * 32 + bco);
                uint32_t h4[4], l4[4];
                ldsm4(h4, sb + rowb);
                ldsm4(l4, sb + TILE_A + rowb);
                mma16816(sp[2*ntp], qh4[0], qh4[1], qh4[2], qh4[3], h4[0], h4[1]);
                mma16816(sp[2*ntp], ql4[0], ql4[1], ql4[2], ql4[3], h4[0], h4[1]);
                mma16816(sp[2*ntp], qh4[0], qh4[1], qh4[2], qh4[3], l4[0], l4[1]);
                mma16816(sp[2*ntp+1], qh4[0], qh4[1], qh4[2], qh4[3], h4[2], h4[3]);
                mma16816(sp[2*ntp+1], ql4[0], ql4[1], ql4[2], ql4[3], h4[2], h4[3]);
                mma16816(sp[2*ntp+1], qh4[0], qh4[1], qh4[2], qh4[3], l4[2], l4[3]);
            }
        }

        if (need_mask) {
            #pragma unroll
            for (int nt = 0; nt < 8; nt++) {
                #pragma unroll
                for (int c = 0; c < 4; c++) {
                    int qb = (c >= 2) ? qb1 : qb0;
                    int key = k0g + nt * 8 + 2 * tig + (c & 1);
                    bool bad = (key >= N_) ||
                               (qb >= 0 && key >= 1 && ((key - 1) >> 8) == qb);
                    if (bad) sp[nt][c] = -INFINITY;
                }
            }
        }

        #pragma unroll
        for (int half = 0; half < 2; half++) {
            float mx = -INFINITY;
            #pragma unroll
            for (int nt = 0; nt < 8; nt++)
                mx = fmaxf(mx, fmaxf(sp[nt][half*2], sp[nt][half*2+1]));
            mx = fmaxf(mx, __shfl_xor_sync(0xffffffffu, mx, 1));
            mx = fmaxf(mx, __shfl_xor_sync(0xffffffffu, mx, 2));
            float mnew = fmaxf(m2[half], mx);
            float corr = exp2f(m2[half] - mnew);
            m2[half] = mnew;
            float rs = 0.f;
            #pragma unroll
            for (int nt = 0; nt < 8; nt++) {
                float p0 = exp2f(sp[nt][half*2]   - mnew);
                float p1 = exp2f(sp[nt][half*2+1] - mnew);
                sp[nt][half*2] = p0; sp[nt][half*2+1] = p1;
                rs += p0 + p1;
            }
            rs += __shfl_xor_sync(0xffffffffu, rs, 1);
            rs += __shfl_xor_sync(0xffffffffu, rs, 2);
            l2[half] = l2[half] * corr + rs;
            #pragma unroll
            for (int dt = 0; dt < 8; dt++) {
                accD[dt][half*2]   *= corr;
                accD[dt][half*2+1] *= corr;
            }
        }

        #pragma unroll
        for (int ks = 0; ks < 4; ks++) {
            uint32_t p0[4], p1[4];
            split_pack(sp[2*ks][0],   sp[2*ks][1],   p0[0], p1[0]);
            split_pack(sp[2*ks][2],   sp[2*ks][3],   p0[1], p1[1]);
            split_pack(sp[2*ks+1][0], sp[2*ks+1][1], p0[2], p1[2]);
            split_pack(sp[2*ks+1][2], sp[2*ks+1][3], p0[3], p1[3]);
            #pragma unroll
            for (int dtp = 0; dtp < 4; dtp++) {
                uint32_t rowb = (uint32_t)((ks * 16 + vro) * 144 + dtp * 32 + vco);
                uint32_t h4[4], l4[4];
                ldsm4t(h4, sb + 2 * TILE_A + rowb);
                ldsm4t(l4, sb + 3 * TILE_A + rowb);
                mma16816(accD[2*dtp], p0[0], p0[1], p0[2], p0[3], h4[0], h4[1]);
                mma16816(accD[2*dtp], p1[0], p1[1], p1[2], p1[3], h4[0], h4[1]);
                mma16816(accD[2*dtp], p0[0], p0[1], p0[2], p0[3], l4[0], l4[1]);
                mma16816(accD[2*dtp+1], p0[0], p0[1], p0[2], p0[3], h4[2], h4[3]);
                mma16816(accD[2*dtp+1], p1[0], p1[1], p1[2], p1[3], h4[2], h4[3]);
                mma16816(accD[2*dtp+1], p0[0], p0[1], p0[2], p0[3], l4[2], l4[3]);
            }
        }
    }

    const int b = bh / H_, h = bh % H_;
    #pragma unroll
    for (int half = 0; half < 2; half++) {
        int row = rlo + gid + half * 8;
        if (row < N_) {
            float inv = 1.f / l2[half];
            #pragma unroll
            for (int dt = 0; dt < 8; dt++) {
                int d = dt * 8 + 2 * tig;
                long base = ((long)b * N_ + row) * C_ + h * 64 + d;
                uint32_t hi, lo;
                split_pack(accD[dt][half*2] * inv, accD[dt][half*2+1] * inv, hi, lo);
                *(uint32_t*)&g_cs[0][base] = hi;
                *(uint32_t*)&g_cs[1][base] = lo;
            }
        }
    }
}

// ======================================================================
// cls softmax over precomputed scores (fp64). One CTA per (b,h).
// ======================================================================
__global__ void __launch_bounds__(1024)
cls_soft_kernel() {
    __shared__ double s[N_];
    __shared__ double red[32];
    const int bh = blockIdx.x;
    const int tid = threadIdx.x;
    const int wid = tid >> 5, lane = tid & 31;

    for (int j = tid; j < N_; j += 1024) s[j] = g_cls_s[bh][j];
    __syncthreads();

    double lm = -1e300;
    for (int j = tid; j < N_; j += 1024) lm = fmax(lm, s[j]);
    #pragma unroll
    for (int o = 16; o >= 1; o >>= 1)
        lm = fmax(lm, __shfl_xor_sync(0xffffffffu, lm, o));
    if (lane == 0) red[wid] = lm;
    __syncthreads();
    if (wid == 0) {
        double t = red[lane];
        #pragma unroll
        for (int o = 16; o >= 1; o >>= 1)
            t = fmax(t, __shfl_xor_sync(0xffffffffu, t, o));
        if (lane == 0) red[0] = t;
    }
    __syncthreads();
    const double m = red[0];
    __syncthreads();

    double ls = 0.0;
    for (int j = tid; j < N_; j += 1024) {
        double e = exp(s[j] - m);
        s[j] = e;
        ls += e;
    }
    #pragma unroll
    for (int o = 16; o >= 1; o >>= 1)
        ls += __shfl_xor_sync(0xffffffffu, ls, o);
    if (lane == 0) red[wid] = ls;
    __syncthreads();
    if (wid == 0) {
        double t = red[lane];
        #pragma unroll
        for (int o = 16; o >= 1; o >>= 1)
            t += __shfl_xor_sync(0xffffffffu, t, o);
        if (lane == 0) red[0] = t;
    }
    __syncthreads();
    const double inv = 1.0 / red[0];

    for (int j = tid; j < N_ - 1; j += 1024)
        g_cls_ph[bh][j] = s[j + 1] * inv;
}

// ======================================================================
// head-mean reduce (fp64, h-ascending). One CTA per batch.
// ======================================================================
__global__ void cls_reduce_kernel(float* __restrict__ out) {
    const int b = blockIdx.x, tid = threadIdx.x;
    for (int j = tid; j < N_ - 1; j += 256) {
        double a = 0.0;
        #pragma unroll
        for (int h = 0; h < H_; h++)
            a += g_cls_ph[b * H_ + h][j] * (1.0 / 12.0);
        g_clsd[b * (N_ - 1) + j] = a;
        out[OFF_CLS + (long)b * (N_ - 1) + j] = (float)a;
    }
}

// ======================================================================
// dual bitonic top-k (103 of 1024) on fp64 keys, jax tie-break.
// ======================================================================
__global__ void sort_kernel(float* __restrict__ out) {
    __shared__ double v[1024];
    __shared__ int ix[1024];
    const int b = blockIdx.x, tid = threadIdx.x;

    for (int pass = 0; pass < 2; pass++) {
        __syncthreads();
        for (int i = tid; i < 1024; i += 512) {
            v[i] = g_clsd[b * 1024 + i];
            ix[i] = i;
        }
        __syncthreads();
        const bool desc = (pass == 0);
        for (int k = 2; k <= 1024; k <<= 1) {
            for (int j = k >> 1; j > 0; j >>= 1) {
                for (int i = tid; i < 1024; i += 512) {
                    int p = i ^ j;
                    if (p > i) {
                        double va = v[i], vb = v[p];
                        int ia = ix[i], ib = ix[p];
                        bool ab = desc ? (va > vb || (va == vb && ia < ib))
                                       : (va < vb || (va == vb && ia < ib));
                        bool up = ((i & k) == 0);
                        if (up ? !ab : ab) {
                            v[i] = vb; v[p] = va;
                            ix[i] = ib; ix[p] = ia;
                        }
                    }
                }
                __syncthreads();
            }
        }
        const long offIdx = desc ? OFF_ENH_IDX : OFF_FUSE_IDX;
        const long offBrd = desc ? OFF_ENH_INDEX : OFF_FUSE_INDEX;
        for (int t = tid; t < TOPT; t += 512)
            out[offIdx + (long)b * TOPT + t] = (float)ix[t];
        for (int e = tid; e < TOPT * C_; e += 512) {
            int t = e / C_;
            out[offBrd + ((long)b * TOPT + t) * C_ + (e % C_)] = (float)ix[t];
        }
    }
}

// ======================================================================
// Launch
// ======================================================================
extern "C" void kernel_launch(void* const* d_in, const int* in_sizes, int n_in,
                              void* d_out, int out_size) {
    const float* x     = (const float*)d_in[0];
    const float* w_qkv = (const float*)d_in[1];
    const float* w_out = (const float*)d_in[2];
    const float* b_out = (const float*)d_in[3];
    float* out = (float*)d_out;

    cudaFuncSetAttribute(fused_qkv_cls, cudaFuncAttributeMaxDynamicSharedMemorySize,
                         MMA_SMEM);
    cudaFuncSetAttribute(out_gemm, cudaFuncAttributeMaxDynamicSharedMemorySize,
                         MMA_SMEM);
    cudaFuncSetAttribute(attn_mma, cudaFuncAttributeMaxDynamicSharedMemorySize,
                         ATTN_SMEM3);

    __nv_bfloat16 *xs0, *xs1, *ws0, *ws1, *wo0, *wo1, *cs0, *cs1;
    cudaGetSymbolAddress((void**)&xs0, g_xs); xs1 = xs0 + (long)M_TOT*C_;
    cudaGetSymbolAddress((void**)&ws0, g_ws); ws1 = ws0 + (long)3*C_*C_;
    cudaGetSymbolAddress((void**)&wo0, g_wo); wo1 = wo0 + (long)C_*C_;
    cudaGetSymbolAddress((void**)&cs0, g_cs); cs1 = cs0 + (long)M_TOT*C_;

    split2<<<(M_TOT*C_ + 255)/256, 256>>>(x, xs0, xs1, M_TOT*C_);
    split2<<<(3*C_*C_ + 255)/256, 256>>>(w_qkv, ws0, ws1, 3*C_*C_);
    split2<<<(C_*C_ + 255)/256, 256>>>(w_out, wo0, wo1, C_*C_);

    // fused: cls score chunks (blocks 0..191) + QKV GEMM (192..785)
    fused_qkv_cls<<<CLS_BLOCKS + QKV_BLOCKS, 256, MMA_SMEM>>>(
        xs0, xs1, ws0, ws1, x, w_qkv);

    // attention -> ctx bf16 splits directly
    attn_mma<<<dim3((N_ + 127)/128, B_ * H_), 256, ATTN_SMEM3>>>();

    // OUT: [4100,768] = ctx @ w_out^T + bias
    out_gemm<<<dim3(C_/128, (M_TOT + 127)/128), 256, MMA_SMEM>>>(
        cs0, cs1, wo0, wo1, b_out, out);

    // cls tail: fp64 softmax over precomputed scores, mean, top-k
    cls_soft_kernel<<<B_ * H_, 1024>>>();
    cls_reduce_kernel<<<B_, 256>>>(out);
    sort_kernel<<<B_, 512>>>(out);
}